// round 11
// baseline (speedup 1.0000x reference)
#include <cuda_runtime.h>
#include <math.h>
#include <stdint.h>

// ---------------- constants ----------------
#define NB   8
#define NRr  300
#define DD_  256
#define HH   8
#define HDIM 32
#define SS   49
#define FFN  2048
#define NCL  80
#define ROWS (NB*NRr)    // 2400

// ---------------- scratch ----------------
__device__ float g_qk   [ROWS*DD_];       // rounded(pf+query)
__device__ float g_pfr  [ROWS*DD_];       // rounded(pf)
__device__ float g_qkp  [ROWS*512];       // merged q|k projections
__device__ float g_vp   [ROWS*DD_];
__device__ float g_mask [NB*NRr*NRr];
__device__ float g_ctx  [ROWS*DD_];       // rounded
__device__ float g_tgt2 [ROWS*DD_];
__device__ float g_pf1  [ROWS*DD_];
__device__ float g_pf1r [ROWS*DD_];
__device__ float g_params[78643200];      // 2400*32768
__device__ float g_f2   [30105600];       // 2400*12544 (rounded)
__device__ float g_x    [ROWS*DD_];
__device__ float g_pf3  [ROWS*DD_];
__device__ float g_pf3r [ROWS*DD_];
__device__ float g_ffn  [ROWS*FFN];       // rounded via epilogue flag
__device__ float g_t2   [ROWS*DD_];
__device__ float g_fc   [ROWS*DD_];       // rounded
__device__ float g_clsy [ROWS*DD_];
__device__ float g_clsf [ROWS*DD_];       // rounded
__device__ float g_part [8*ROWS*256];     // split-K partials
// rounded weights
__device__ float g_wqkv_r  [768*256];
__device__ float g_wattn_r [256*256];
__device__ float g_wdyn_r  [32768*256];
__device__ float g_wdynout_r[256*12544];
__device__ float g_wff1_r  [2048*256];
__device__ float g_wff2_r  [256*2048];
__device__ float g_wcls_r  [256*256];
__device__ float g_wlog_r  [80*256];

// ---------------- helpers ----------------
__device__ __forceinline__ float blockReduceSum256(float v) {
    __shared__ float red[8];
    int lane = threadIdx.x & 31, w = threadIdx.x >> 5;
    #pragma unroll
    for (int o = 16; o; o >>= 1) v += __shfl_xor_sync(0xffffffffu, v, o);
    __syncthreads();
    if (lane == 0) red[w] = v;
    __syncthreads();
    float s = 0.f;
    #pragma unroll
    for (int i = 0; i < 8; i++) s += red[i];
    return s;
}

__device__ __forceinline__ float tfr(float x) {
    uint32_t u;
    asm("cvt.rna.tf32.f32 %0, %1;" : "=r"(u) : "f"(x));
    return __uint_as_float(u);
}

__device__ __forceinline__ void mma_tf32(float* c,
        uint32_t a0, uint32_t a1, uint32_t a2, uint32_t a3,
        uint32_t b0, uint32_t b1) {
    asm volatile(
        "mma.sync.aligned.m16n8k8.row.col.f32.tf32.tf32.f32 "
        "{%0,%1,%2,%3}, {%4,%5,%6,%7}, {%8,%9}, {%0,%1,%2,%3};"
        : "+f"(c[0]), "+f"(c[1]), "+f"(c[2]), "+f"(c[3])
        : "r"(a0), "r"(a1), "r"(a2), "r"(a3), "r"(b0), "r"(b1));
}

// ---------------- weight rounding (one streaming pass) ----------------
#define S_DYN    2097152
#define S_DYNOUT  802816
#define S_FF1     131072
#define S_FF2     131072
#define S_QKV      49152
#define S_ATTN     16384
#define S_CLS      16384
#define S_LOG       5120
#define S_TOT4   3249152

__global__ void round_weights(const float4* __restrict__ s_dyn,    float4* d_dyn,
                              const float4* __restrict__ s_dynout, float4* d_dynout,
                              const float4* __restrict__ s_ff1,    float4* d_ff1,
                              const float4* __restrict__ s_ff2,    float4* d_ff2,
                              const float4* __restrict__ s_qkv,    float4* d_qkv,
                              const float4* __restrict__ s_attn,   float4* d_attn,
                              const float4* __restrict__ s_cls,    float4* d_cls,
                              const float4* __restrict__ s_log,    float4* d_log) {
    for (long i = blockIdx.x*(long)blockDim.x + threadIdx.x; i < S_TOT4;
         i += (long)gridDim.x*blockDim.x) {
        long j = i;
        const float4* s; float4* d;
        if (j < S_DYN)                       { s = s_dyn;    d = d_dyn; }
        else if ((j -= S_DYN)    < S_DYNOUT) { s = s_dynout; d = d_dynout; }
        else if ((j -= S_DYNOUT) < S_FF1)    { s = s_ff1;    d = d_ff1; }
        else if ((j -= S_FF1)    < S_FF2)    { s = s_ff2;    d = d_ff2; }
        else if ((j -= S_FF2)    < S_QKV)    { s = s_qkv;    d = d_qkv; }
        else if ((j -= S_QKV)    < S_ATTN)   { s = s_attn;   d = d_attn; }
        else if ((j -= S_ATTN)   < S_CLS)    { s = s_cls;    d = d_cls; }
        else { j -= S_CLS;                     s = s_log;    d = d_log; }
        float4 v = s[j];
        v.x = tfr(v.x); v.y = tfr(v.y); v.z = tfr(v.z); v.w = tfr(v.w);
        d[j] = v;
    }
}

// ---------------- TF32 GEMM: R10 structure, LDS.128 feed + 2-mma k-packing ----------------
// C[M,N] = A[M,K] @ B[N,K]^T + bias.  BM=128 BN=128 BK=32, 256 threads,
// 8 warps (4x2 of 32x64), 2-stage cp.async (73728 B smem).
// A and B MUST be TF32-pre-rounded. flags: 1=relu, 2=round output.
// Split-K: gridDim.z > 1 -> raw partials to P[z][M][256] (requires N==256).
#define GTILE 4608   // 128*36 floats per buffer

__device__ __forceinline__ void gemm_load_tile(
        const float* __restrict__ A, const float* __restrict__ B,
        int M, int N, int K, int row0, int col0,
        uint32_t sbase, int tid, int buf, int k0) {
    int r  = tid >> 3;
    int c4 = (tid & 7) * 4;
    #pragma unroll
    for (int p = 0; p < 4; p++) {
        int rr = r + p * 32;
        int gr = row0 + rr;
        const float* src = A + (size_t)(gr < M ? gr : (M - 1)) * K + k0 + c4;
        uint32_t dst = sbase + (uint32_t)((buf * GTILE + rr * 36 + c4) * 4);
        int sz = (gr < M) ? 16 : 0;
        asm volatile("cp.async.cg.shared.global [%0], [%1], 16, %2;\n"
                     :: "r"(dst), "l"(src), "r"(sz));
    }
    #pragma unroll
    for (int p = 0; p < 4; p++) {
        int rr = r + p * 32;
        int gn = col0 + rr;
        const float* src = B + (size_t)(gn < N ? gn : (N - 1)) * K + k0 + c4;
        uint32_t dst = sbase + (uint32_t)(((2 * GTILE) + buf * GTILE + rr * 36 + c4) * 4);
        int sz = (gn < N) ? 16 : 0;
        asm volatile("cp.async.cg.shared.global [%0], [%1], 16, %2;\n"
                     :: "r"(dst), "l"(src), "r"(sz));
    }
}

__global__ __launch_bounds__(256)
void tf32_gemm(const float* __restrict__ A, const float* __restrict__ B,
               const float* __restrict__ bias, float* __restrict__ C,
               float* __restrict__ P,
               int M, int N, int K, int flags) {
    extern __shared__ float sm[];
    const int tid  = threadIdx.x;
    const int warp = tid >> 5, lane = tid & 31;
    const int wm = warp >> 1, wn = warp & 1;
    const int row0 = blockIdx.y * 128;
    const int col0 = blockIdx.x * 128;
    const int Kper  = K / gridDim.z;
    const int kbase = blockIdx.z * Kper;
    uint32_t sbase = (uint32_t)__cvta_generic_to_shared(sm);

    float acc[2][8][4];
    #pragma unroll
    for (int i = 0; i < 2; i++)
        #pragma unroll
        for (int j = 0; j < 8; j++)
            #pragma unroll
            for (int k = 0; k < 4; k++) acc[i][j][k] = 0.f;

    const int T = Kper >> 5;
    gemm_load_tile(A, B, M, N, K, row0, col0, sbase, tid, 0, kbase);
    asm volatile("cp.async.commit_group;");

    const int t4k  = (lane & 3) * 4;   // float4 k-pack: 2 mmas share one LDS.128
    const int arow = wm * 32 + (lane >> 2);
    const int brow = wn * 64 + (lane >> 2);

    for (int t = 0; t < T; t++) {
        if (t + 1 < T) {
            gemm_load_tile(A, B, M, N, K, row0, col0, sbase, tid, (t + 1) & 1, kbase + (t + 1) * 32);
            asm volatile("cp.async.commit_group;");
            asm volatile("cp.async.wait_group 1;");
        } else {
            asm volatile("cp.async.wait_group 0;");
        }
        __syncthreads();

        const float* as = sm + (t & 1) * GTILE;
        const float* bs = sm + 2 * GTILE + (t & 1) * GTILE;
        #pragma unroll
        for (int kk2 = 0; kk2 < 2; kk2++) {
            const int kb = kk2 * 16 + t4k;
            // A fragments: per mi, rows (arow+mi*16) and (+8), 4 logical ks each
            float4 va0[2], va1[2];
            #pragma unroll
            for (int mi = 0; mi < 2; mi++) {
                va0[mi] = *(const float4*)(as + (arow + mi * 16) * 36 + kb);
                va1[mi] = *(const float4*)(as + (arow + mi * 16 + 8) * 36 + kb);
            }
            #pragma unroll
            for (int ni = 0; ni < 8; ni++) {
                float4 vb = *(const float4*)(bs + (brow + ni * 8) * 36 + kb);
                uint32_t b0 = __float_as_uint(vb.x);
                uint32_t b1 = __float_as_uint(vb.y);
                uint32_t b2 = __float_as_uint(vb.z);
                uint32_t b3 = __float_as_uint(vb.w);
                #pragma unroll
                for (int mi = 0; mi < 2; mi++) {
                    // mma0: logical ks (4t, 4t+1)
                    mma_tf32(acc[mi][ni],
                             __float_as_uint(va0[mi].x), __float_as_uint(va1[mi].x),
                             __float_as_uint(va0[mi].y), __float_as_uint(va1[mi].y),
                             b0, b1);
                    // mma1: logical ks (4t+2, 4t+3)
                    mma_tf32(acc[mi][ni],
                             __float_as_uint(va0[mi].z), __float_as_uint(va1[mi].z),
                             __float_as_uint(va0[mi].w), __float_as_uint(va1[mi].w),
                             b2, b3);
                }
            }
        }
        __syncthreads();
    }

    // epilogue
    if (gridDim.z == 1) {
        #pragma unroll
        for (int mi = 0; mi < 2; mi++) {
            int gr0 = row0 + wm * 32 + mi * 16 + (lane >> 2);
            #pragma unroll
            for (int ni = 0; ni < 8; ni++) {
                int gc = col0 + wn * 64 + ni * 8 + 2 * (lane & 3);
                if (gc >= N) continue;
                float bb0 = 0.f, bb1 = 0.f;
                if (bias) { bb0 = bias[gc]; bb1 = bias[gc + 1]; }
                #pragma unroll
                for (int half = 0; half < 2; half++) {
                    int gr = gr0 + half * 8;
                    if (gr >= M) continue;
                    float v0 = acc[mi][ni][half * 2]     + bb0;
                    float v1 = acc[mi][ni][half * 2 + 1] + bb1;
                    if (flags & 1) { v0 = fmaxf(v0, 0.f); v1 = fmaxf(v1, 0.f); }
                    if (flags & 2) { v0 = tfr(v0); v1 = tfr(v1); }
                    *(float2*)(C + (size_t)gr * N + gc) = make_float2(v0, v1);
                }
            }
        }
    } else {
        float* Pz = P + (size_t)blockIdx.z * M * 256;
        #pragma unroll
        for (int mi = 0; mi < 2; mi++) {
            int gr0 = row0 + wm * 32 + mi * 16 + (lane >> 2);
            #pragma unroll
            for (int ni = 0; ni < 8; ni++) {
                int gc = col0 + wn * 64 + ni * 8 + 2 * (lane & 3);
                if (gc >= N) continue;
                if (gr0 < M)
                    *(float2*)(Pz + (size_t)gr0 * 256 + gc) =
                        make_float2(acc[mi][ni][0], acc[mi][ni][1]);
                if (gr0 + 8 < M)
                    *(float2*)(Pz + (size_t)(gr0 + 8) * 256 + gc) =
                        make_float2(acc[mi][ni][2], acc[mi][ni][3]);
            }
        }
    }
}

// ---------------- split-K reduce: out[r][c] = sum_z P[z][r][c] + bias[c] ----------------
__global__ void reduce_splitk(const float* __restrict__ P, const float* __restrict__ bias,
                              float* __restrict__ out, int Z) {
    int r = blockIdx.x, c = threadIdx.x;    // 256 threads
    float s = 0.f;
    for (int z = 0; z < Z; z++) s += P[((size_t)z * ROWS + r) * 256 + c];
    out[(size_t)r * 256 + c] = s + bias[c];
}

// ---------------- IoU-relation attention mask ----------------
__global__ void mask_kernel(const float* __restrict__ bboxes,
                            const float* __restrict__ cur,
                            float* __restrict__ maskf) {
    int q = blockIdx.x, b = blockIdx.y, k = threadIdx.x;
    if (k >= NRr) return;
    float4 bq = *(const float4*)(bboxes + (size_t)(b*NRr + q)*4);
    float4 bk = *(const float4*)(bboxes + (size_t)(b*NRr + k)*4);
    float aq = (bq.z-bq.x)*(bq.w-bq.y);
    float ak = (bk.z-bk.x)*(bk.w-bk.y);
    float lx = fmaxf(bq.x, bk.x), ly = fmaxf(bq.y, bk.y);
    float rx = fminf(bq.z, bk.z), ry = fminf(bq.w, bk.w);
    float w  = fmaxf(rx-lx, 0.f), h = fmaxf(ry-ly, 0.f);
    float inter = w*h;
    float uni = fmaxf(aq + ak - inter, 1e-9f);
    float iou = inter/uni;
    float o   = (iou < 0.5f) ? 1.f : 0.f;
    float cq = cur[b*NRr + q], ck = cur[b*NRr + k];
    float val = o*cq*ck + ((q == k) ? (1.f - cq) : 0.f);
    maskf[((size_t)(b*NRr + q))*NRr + k] = (val > 0.f) ? 1.f : 0.f;
}

// ---------------- qk = round(pf+query); pfr = round(pf) ----------------
__global__ void add_round_kernel(const float* __restrict__ a, const float* __restrict__ b,
                                 float* __restrict__ qk, float* __restrict__ pfr, int n) {
    int i = blockIdx.x*blockDim.x + threadIdx.x;
    if (i < n) {
        float av = a[i];
        qk[i]  = tfr(av + b[i]);
        pfr[i] = tfr(av);
    }
}

// ---------------- masked multi-head attention (merged q|k input) ----------------
#define QCH 100
__global__ void attn_kernel(const float* __restrict__ qkp, const float* __restrict__ vp,
                            const float* __restrict__ maskf, float* __restrict__ ctx) {
    const int bh = blockIdx.x / 3;
    const int ch = blockIdx.x % 3;
    const int b = bh >> 3;
    const int h = bh & 7;
    __shared__ float Ks[150*32];
    __shared__ float Vs[150*32];
    const int tid = threadIdx.x;          // 128
    const int q = ch * QCH + tid;
    const bool act = (tid < QCH) && (q < NRr);
    float qv[32], acc[32];
    float m = -1e30f, ssum = 0.f;
    if (act) {
        const float* qr = qkp + ((size_t)(b*NRr + q))*512 + h*HDIM;
        #pragma unroll
        for (int d = 0; d < 32; d++) { qv[d] = qr[d]; acc[d] = 0.f; }
    }
    const float* mrow = maskf + ((size_t)(b*NRr) + (act ? q : 0))*NRr;
    const float scale = 0.17677669529663687f;  // 1/sqrt(32)

    for (int c0 = 0; c0 < NRr; c0 += 150) {
        __syncthreads();
        for (int i = tid; i < 150*32; i += 128) {
            int k = i >> 5, d = i & 31;
            Ks[i] = qkp[((size_t)(b*NRr + c0 + k))*512 + 256 + h*HDIM + d];
            Vs[i] = vp[((size_t)(b*NRr + c0 + k))*DD_ + h*HDIM + d];
        }
        __syncthreads();
        if (act) {
            for (int k = 0; k < 150; k++) {
                const float* kr = Ks + k*32;
                float x0 = 0.f, x1 = 0.f, x2 = 0.f, x3 = 0.f;
                #pragma unroll
                for (int d = 0; d < 32; d += 4) {
                    x0 += qv[d]*kr[d];   x1 += qv[d+1]*kr[d+1];
                    x2 += qv[d+2]*kr[d+2]; x3 += qv[d+3]*kr[d+3];
                }
                float x = ((x0+x1)+(x2+x3))*scale;
                if (mrow[c0+k] > 0.f) x = -1e9f;
                float nm = fmaxf(m, x);
                float sc = __expf(m - nm);
                float e  = __expf(x - nm);
                ssum = ssum*sc + e;
                const float* vr = Vs + k*32;
                #pragma unroll
                for (int d = 0; d < 32; d++) acc[d] = acc[d]*sc + e*vr[d];
                m = nm;
            }
        }
    }
    if (act) {
        float inv = 1.f/ssum;
        float* cr = ctx + ((size_t)(b*NRr + q))*DD_ + h*HDIM;
        #pragma unroll
        for (int d = 0; d < 32; d++) cr[d] = tfr(acc[d]*inv);
    }
}

// ---------------- ln(residual) * mask -> exact (optional) + rounded ----------------
__global__ void ln_res_mask_kernel(const float* __restrict__ a, const float* __restrict__ bq,
                                   const float* __restrict__ cur,
                                   float* __restrict__ out, float* __restrict__ out_r) {
    int r = blockIdx.x, t = threadIdx.x;
    float x = a[(size_t)r*DD_ + t] + bq[(size_t)r*DD_ + t];
    float mean = blockReduceSum256(x) * (1.f/256.f);
    float d = x - mean;
    float var = blockReduceSum256(d*d) * (1.f/256.f);
    float y = d * rsqrtf(var + 1e-5f) * cur[r];
    if (out) out[(size_t)r*DD_ + t] = y;
    out_r[(size_t)r*DD_ + t] = tfr(y);
}

// ---------------- relu(ln(x)) -> + pf1 -> ln (exact + rounded) ----------------
__global__ void post_dyn_kernel(const float* __restrict__ x, const float* __restrict__ pf1,
                                float* __restrict__ out, float* __restrict__ out_r) {
    int r = blockIdx.x, t = threadIdx.x;
    float v = x[(size_t)r*DD_ + t];
    float m1 = blockReduceSum256(v) * (1.f/256.f);
    float d1 = v - m1;
    float v1 = blockReduceSum256(d1*d1) * (1.f/256.f);
    float rl = fmaxf(d1 * rsqrtf(v1 + 1e-5f), 0.f);
    float y = pf1[(size_t)r*DD_ + t] + rl;
    float m2 = blockReduceSum256(y) * (1.f/256.f);
    float d2 = y - m2;
    float v2 = blockReduceSum256(d2*d2) * (1.f/256.f);
    float z = d2 * rsqrtf(v2 + 1e-5f);
    out[(size_t)r*DD_ + t] = z;
    out_r[(size_t)r*DD_ + t] = tfr(z);
}

// ---------------- relu(ln(x)) rounded ----------------
__global__ void ln_relu_kernel(const float* __restrict__ x, float* __restrict__ out) {
    int r = blockIdx.x, t = threadIdx.x;
    float v = x[(size_t)r*DD_ + t];
    float m = blockReduceSum256(v) * (1.f/256.f);
    float d = v - m;
    float var = blockReduceSum256(d*d) * (1.f/256.f);
    out[(size_t)r*DD_ + t] = tfr(fmaxf(d * rsqrtf(var + 1e-5f), 0.f));
}

// ---------------- DynamicConv (register-tiled) ----------------
#define SPAD 52
#define DYN_SMEM 210944

__global__ __launch_bounds__(256)
void dynconv_kernel(const float* __restrict__ roi, const float* __restrict__ params,
                    float* __restrict__ out) {
    int n = blockIdx.x;
    extern __shared__ float sm[];
    float* featsT = sm;                 // [d][s] 256 x 52
    float* p1     = sm + 13312;         // [d][e] 256 x 64
    float* p2     = p1 + 16384;         // [e][d] 64 x 256
    float* f1     = p2 + 16384;         // [s][e] 52 x 64
    float* f1T    = f1 + 3328;          // [e][s] 64 x 52
    int tid = threadIdx.x;

    for (int i = tid; i < 256*3; i += 256) {
        int d = i / 3, s = 49 + (i % 3);
        featsT[d*SPAD + s] = 0.f;
    }
    for (int i = tid; i < SS*DD_; i += 256) {
        int s = i >> 8, d = i & 255;
        featsT[d*SPAD + s] = roi[((size_t)s*ROWS + n)*DD_ + d];
    }
    const float4* pr = (const float4*)(params + (size_t)n * 32768);
    float4* p14 = (float4*)p1;
    float4* p24 = (float4*)p2;
    for (int i = tid; i < 4096; i += 256) p14[i] = pr[i];
    for (int i = tid; i < 4096; i += 256) p24[i] = pr[4096 + i];
    __syncthreads();

    {
        int te = tid & 15, tsg = tid >> 4;
        if (tsg < 13) {
            int e0 = te * 4, s0 = tsg * 4;
            float acc[4][4];
            #pragma unroll
            for (int i = 0; i < 4; i++)
                #pragma unroll
                for (int j = 0; j < 4; j++) acc[i][j] = 0.f;
            for (int d = 0; d < 256; d++) {
                float4 fv = *(const float4*)(featsT + d*SPAD + s0);
                float4 pv = *(const float4*)(p1 + d*64 + e0);
                acc[0][0] += fv.x*pv.x; acc[0][1] += fv.x*pv.y; acc[0][2] += fv.x*pv.z; acc[0][3] += fv.x*pv.w;
                acc[1][0] += fv.y*pv.x; acc[1][1] += fv.y*pv.y; acc[1][2] += fv.y*pv.z; acc[1][3] += fv.y*pv.w;
                acc[2][0] += fv.z*pv.x; acc[2][1] += fv.z*pv.y; acc[2][2] += fv.z*pv.z; acc[2][3] += fv.z*pv.w;
                acc[3][0] += fv.w*pv.x; acc[3][1] += fv.w*pv.y; acc[3][2] += fv.w*pv.z; acc[3][3] += fv.w*pv.w;
            }
            #pragma unroll
            for (int i = 0; i < 4; i++)
                #pragma unroll
                for (int j = 0; j < 4; j++)
                    f1[(s0+i)*64 + e0 + j] = acc[i][j];
        }
    }
    __syncthreads();

    int warp = tid >> 5, lane = tid & 31;
    for (int s = warp; s < SS; s += 8) {
        float x0 = f1[s*64 + lane], x1 = f1[s*64 + 32 + lane];
        float sum = x0 + x1;
        #pragma unroll
        for (int o = 16; o; o >>= 1) sum += __shfl_xor_sync(0xffffffffu, sum, o);
        float m = sum * (1.f/64.f);
        float d0 = x0 - m, d1 = x1 - m;
        float vs = d0*d0 + d1*d1;
        #pragma unroll
        for (int o = 16; o; o >>= 1) vs += __shfl_xor_sync(0xffffffffu, vs, o);
        float inv = rsqrtf(vs*(1.f/64.f) + 1e-5f);
        f1T[lane*SPAD + s]        = fmaxf(d0*inv, 0.f);
        f1T[(32+lane)*SPAD + s]   = fmaxf(d1*inv, 0.f);
    }
    __syncthreads();

    float* f2 = featsT;
    {
        int td = tid & 63, tsg2 = tid >> 6;
        int d0 = td * 4;
        for (int sg = tsg2; sg < 13; sg += 4) {
            int s0 = sg * 4;
            float acc[4][4];
            #pragma unroll
            for (int i = 0; i < 4; i++)
                #pragma unroll
                for (int j = 0; j < 4; j++) acc[i][j] = 0.f;
            for (int e = 0; e < 64; e++) {
                float4 fv = *(const float4*)(f1T + e*SPAD + s0);
                float4 pv = *(const float4*)(p2 + e*256 + d0);
                acc[0][0] += fv.x*pv.x; acc[0][1] += fv.x*pv.y; acc[0][2] += fv.x*pv.z; acc[0][3] += fv.x*pv.w;
                acc[1][0] += fv.y*pv.x; acc[1][1] += fv.y*pv.y; acc[1][2] += fv.y*pv.z; acc[1][3] += fv.y*pv.w;
                acc[2][0] += fv.z*pv.x; acc[2][1] += fv.z*pv.y; acc[2][2] += fv.z*pv.z; acc[2][3] += fv.z*pv.w;
                acc[3][0] += fv.w*pv.x; acc[3][1] += fv.w*pv.y; acc[3][2] += fv.w*pv.z; acc[3][3] += fv.w*pv.w;
            }
            #pragma unroll
            for (int i = 0; i < 4; i++)
                #pragma unroll
                for (int j = 0; j < 4; j++)
                    f2[(s0+i)*256 + d0 + j] = acc[i][j];
        }
    }
    __syncthreads();

    for (int s = warp; s < SS; s += 8) {
        float x[8]; float sum = 0.f;
        #pragma unroll
        for (int j = 0; j < 8; j++) { x[j] = f2[s*256 + j*32 + lane]; sum += x[j]; }
        #pragma unroll
        for (int o = 16; o; o >>= 1) sum += __shfl_xor_sync(0xffffffffu, sum, o);
        float m = sum * (1.f/256.f);
        float vs = 0.f;
        #pragma unroll
        for (int j = 0; j < 8; j++) { float dd = x[j]-m; vs += dd*dd; }
        #pragma unroll
        for (int o = 16; o; o >>= 1) vs += __shfl_xor_sync(0xffffffffu, vs, o);
        float inv = rsqrtf(vs*(1.f/256.f) + 1e-5f);
        #pragma unroll
        for (int j = 0; j < 8; j++)
            out[(size_t)n*12544 + s*256 + j*32 + lane] = tfr(fmaxf((x[j]-m)*inv, 0.f));
    }
}

// ---------------- host ----------------
extern "C" void kernel_launch(void* const* d_in, const int* in_sizes, int n_in,
                              void* d_out, int out_size) {
    const float* bboxes     = (const float*)d_in[0];
    const float* pf         = (const float*)d_in[1];
    const float* roi        = (const float*)d_in[2];
    const float* query      = (const float*)d_in[3];
    const float* cur        = (const float*)d_in[4];
    const float* w_qkv      = (const float*)d_in[5];
    const float* b_qkv      = (const float*)d_in[6];
    const float* w_attn_out = (const float*)d_in[7];
    const float* b_attn_out = (const float*)d_in[8];
    const float* w_dyn      = (const float*)d_in[9];
    const float* b_dyn      = (const float*)d_in[10];
    const float* w_dyn_out  = (const float*)d_in[11];
    const float* b_dyn_out  = (const float*)d_in[12];
    const float* w_ff1      = (const float*)d_in[13];
    const float* b_ff1      = (const float*)d_in[14];
    const float* w_ff2      = (const float*)d_in[15];
    const float* b_ff2      = (const float*)d_in[16];
    const float* w_cls      = (const float*)d_in[17];
    const float* w_logits   = (const float*)d_in[18];
    const float* b_logits   = (const float*)d_in[19];
    float* out = (float*)d_out;

    float *qk,*pfr,*qkp,*vp,*maskb,*ctx,*tgt2,*pf1,*pf1r,*params,*f2,*x,*pf3,*pf3r,*ffn,*t2,*fc,*clsy,*clsf,*part;
    float *wqkv,*wattn,*wdyn,*wdynout,*wff1,*wff2,*wcls,*wlog;
    cudaGetSymbolAddress((void**)&qk,     g_qk);
    cudaGetSymbolAddress((void**)&pfr,    g_pfr);
    cudaGetSymbolAddress((void**)&qkp,    g_qkp);
    cudaGetSymbolAddress((void**)&vp,     g_vp);
    cudaGetSymbolAddress((void**)&maskb,  g_mask);
    cudaGetSymbolAddress((void**)&ctx,    g_ctx);
    cudaGetSymbolAddress((void**)&tgt2,   g_tgt2);
    cudaGetSymbolAddress((void**)&pf1,    g_pf1);
    cudaGetSymbolAddress((void**)&pf1r,   g_pf1r);
    cudaGetSymbolAddress((void**)&params, g_params);
    cudaGetSymbolAddress((void**)&f2,     g_f2);
    cudaGetSymbolAddress((void**)&x,      g_x);
    cudaGetSymbolAddress((void**)&pf3,    g_pf3);
    cudaGetSymbolAddress((void**)&pf3r,   g_pf3r);
    cudaGetSymbolAddress((void**)&ffn,    g_ffn);
    cudaGetSymbolAddress((void**)&t2,     g_t2);
    cudaGetSymbolAddress((void**)&fc,     g_fc);
    cudaGetSymbolAddress((void**)&clsy,   g_clsy);
    cudaGetSymbolAddress((void**)&clsf,   g_clsf);
    cudaGetSymbolAddress((void**)&part,   g_part);
    cudaGetSymbolAddress((void**)&wqkv,   g_wqkv_r);
    cudaGetSymbolAddress((void**)&wattn,  g_wattn_r);
    cudaGetSymbolAddress((void**)&wdyn,   g_wdyn_r);
    cudaGetSymbolAddress((void**)&wdynout,g_wdynout_r);
    cudaGetSymbolAddress((void**)&wff1,   g_wff1_r);
    cudaGetSymbolAddress((void**)&wff2,   g_wff2_r);
    cudaGetSymbolAddress((void**)&wcls,   g_wcls_r);
    cudaGetSymbolAddress((void**)&wlog,   g_wlog_r);

    const int GEMM_SMEM = 4 * GTILE * 4;   // 73728 B (2 stages, proven)
    cudaFuncSetAttribute(tf32_gemm, cudaFuncAttributeMaxDynamicSharedMemorySize, GEMM_SMEM);
    cudaFuncSetAttribute(dynconv_kernel, cudaFuncAttributeMaxDynamicSharedMemorySize, DYN_SMEM);

    auto grd = [](int M, int N) { return dim3((unsigned)((N+127)/128), (unsigned)((M+127)/128), 1); };

    // prep: mask, rounded activations, rounded weights
    mask_kernel<<<dim3(NRr, NB), 320>>>(bboxes, cur, maskb);
    add_round_kernel<<<(ROWS*DD_+255)/256, 256>>>(pf, query, qk, pfr, ROWS*DD_);
    round_weights<<<1280, 256>>>((const float4*)w_dyn,     (float4*)wdyn,
                                 (const float4*)w_dyn_out, (float4*)wdynout,
                                 (const float4*)w_ff1,     (float4*)wff1,
                                 (const float4*)w_ff2,     (float4*)wff2,
                                 (const float4*)w_qkv,     (float4*)wqkv,
                                 (const float4*)w_attn_out,(float4*)wattn,
                                 (const float4*)w_cls,     (float4*)wcls,
                                 (const float4*)w_logits,  (float4*)wlog);

    // merged q|k projection (N=512) + v
    tf32_gemm<<<grd(ROWS,512), 256, GEMM_SMEM>>>(qk,  wqkv,           b_qkv,     qkp, nullptr, ROWS, 512, 256, 0);
    tf32_gemm<<<grd(ROWS,256), 256, GEMM_SMEM>>>(pfr, wqkv + 512*256, b_qkv+512, vp,  nullptr, ROWS, 256, 256, 0);
    // masked MHSA (ctx rounded in epilogue)
    attn_kernel<<<NB*HH*3, 128>>>(qkp, vp, maskb, ctx);
    // out proj + norm1*mask
    tf32_gemm<<<grd(ROWS,256), 256, GEMM_SMEM>>>(ctx, wattn, b_attn_out, tgt2, nullptr, ROWS, 256, 256, 0);
    ln_res_mask_kernel<<<ROWS, 256>>>(pf, tgt2, cur, pf1, pf1r);
    // DynamicConv params GEMM (dominant, chip-full)
    tf32_gemm<<<grd(ROWS,32768), 256, GEMM_SMEM>>>(pf1r, wdyn, b_dyn, params, nullptr, ROWS, 32768, 256, 0);
    // per-instance dynamic conv (rounded output)
    dynconv_kernel<<<ROWS, 256, DYN_SMEM>>>(roi, params, f2);
    // dyn out proj — split-K(8) + reduce; norm2
    tf32_gemm<<<dim3(2,19,8), 256, GEMM_SMEM>>>(f2, wdynout, nullptr, nullptr, part, ROWS, 256, 12544, 0);
    reduce_splitk<<<ROWS, 256>>>(part, b_dyn_out, x, 8);
    post_dyn_kernel<<<ROWS, 256>>>(x, pf1, pf3, pf3r);
    // FFN: ff1 (relu+round) + ff2 split-K(8); norm3
    tf32_gemm<<<grd(ROWS,2048), 256, GEMM_SMEM>>>(pf3r, wff1, b_ff1, ffn, nullptr, ROWS, 2048, 256, 3);
    tf32_gemm<<<dim3(2,19,8), 256, GEMM_SMEM>>>(ffn, wff2, nullptr, nullptr, part, ROWS, 256, 2048, 0);
    reduce_splitk<<<ROWS, 256>>>(part, b_ff2, t2, 8);
    ln_res_mask_kernel<<<ROWS, 256>>>(pf3, t2, cur, nullptr, fc);
    // cls tower + logits
    tf32_gemm<<<grd(ROWS,256), 256, GEMM_SMEM>>>(fc, wcls, nullptr, clsy, nullptr, ROWS, 256, 256, 0);
    ln_relu_kernel<<<ROWS, 256>>>(clsy, clsf);
    tf32_gemm<<<grd(ROWS,80), 256, GEMM_SMEM>>>(clsf, wlog, b_logits, out, nullptr, ROWS, 80, 256, 0);
}

// round 12
// speedup vs baseline: 1.1131x; 1.1131x over previous
#include <cuda_runtime.h>
#include <math.h>
#include <stdint.h>

// ---------------- constants ----------------
#define NB   8
#define NRr  300
#define DD_  256
#define HH   8
#define HDIM 32
#define SS   49
#define FFN  2048
#define NCL  80
#define ROWS (NB*NRr)    // 2400

// ---------------- scratch ----------------
__device__ float g_qk   [ROWS*DD_];       // rounded(pf+query)
__device__ float g_pfr  [ROWS*DD_];       // rounded(pf)
__device__ float g_qp   [ROWS*DD_];
__device__ float g_kp   [ROWS*DD_];
__device__ float g_vp   [ROWS*DD_];
__device__ float g_mask [NB*NRr*NRr];
__device__ float g_ctx  [ROWS*DD_];       // rounded
__device__ float g_tgt2 [ROWS*DD_];
__device__ float g_pf1  [ROWS*DD_];
__device__ float g_pf1r [ROWS*DD_];
__device__ float g_params[78643200];      // 2400*32768
__device__ float g_f2   [30105600];       // 2400*12544 (rounded)
__device__ float g_x    [ROWS*DD_];
__device__ float g_pf3  [ROWS*DD_];
__device__ float g_pf3r [ROWS*DD_];
__device__ float g_ffn  [ROWS*FFN];       // rounded via epilogue flag
__device__ float g_t2   [ROWS*DD_];
__device__ float g_fc   [ROWS*DD_];       // rounded
__device__ float g_clsy [ROWS*DD_];
__device__ float g_clsf [ROWS*DD_];       // rounded
__device__ float g_part [8*ROWS*256];     // split-K partials
// rounded weights
__device__ float g_wqkv_r  [768*256];
__device__ float g_wattn_r [256*256];
__device__ float g_wdyn_r  [32768*256];
__device__ float g_wdynout_r[256*12544];
__device__ float g_wff1_r  [2048*256];
__device__ float g_wff2_r  [256*2048];
__device__ float g_wcls_r  [256*256];
__device__ float g_wlog_r  [80*256];

// ---------------- helpers ----------------
__device__ __forceinline__ float blockReduceSum256(float v) {
    __shared__ float red[8];
    int lane = threadIdx.x & 31, w = threadIdx.x >> 5;
    #pragma unroll
    for (int o = 16; o; o >>= 1) v += __shfl_xor_sync(0xffffffffu, v, o);
    __syncthreads();
    if (lane == 0) red[w] = v;
    __syncthreads();
    float s = 0.f;
    #pragma unroll
    for (int i = 0; i < 8; i++) s += red[i];
    return s;
}

__device__ __forceinline__ float tfr(float x) {
    uint32_t u;
    asm("cvt.rna.tf32.f32 %0, %1;" : "=r"(u) : "f"(x));
    return __uint_as_float(u);
}

__device__ __forceinline__ void mma_tf32(float* c,
        uint32_t a0, uint32_t a1, uint32_t a2, uint32_t a3,
        uint32_t b0, uint32_t b1) {
    asm volatile(
        "mma.sync.aligned.m16n8k8.row.col.f32.tf32.tf32.f32 "
        "{%0,%1,%2,%3}, {%4,%5,%6,%7}, {%8,%9}, {%0,%1,%2,%3};"
        : "+f"(c[0]), "+f"(c[1]), "+f"(c[2]), "+f"(c[3])
        : "r"(a0), "r"(a1), "r"(a2), "r"(a3), "r"(b0), "r"(b1));
}

// ---------------- weight rounding (one streaming pass) ----------------
#define S_DYN    2097152
#define S_DYNOUT  802816
#define S_FF1     131072
#define S_FF2     131072
#define S_QKV      49152
#define S_ATTN     16384
#define S_CLS      16384
#define S_LOG       5120
#define S_TOT4   3249152

__global__ void round_weights(const float4* __restrict__ s_dyn,    float4* d_dyn,
                              const float4* __restrict__ s_dynout, float4* d_dynout,
                              const float4* __restrict__ s_ff1,    float4* d_ff1,
                              const float4* __restrict__ s_ff2,    float4* d_ff2,
                              const float4* __restrict__ s_qkv,    float4* d_qkv,
                              const float4* __restrict__ s_attn,   float4* d_attn,
                              const float4* __restrict__ s_cls,    float4* d_cls,
                              const float4* __restrict__ s_log,    float4* d_log) {
    for (long i = blockIdx.x*(long)blockDim.x + threadIdx.x; i < S_TOT4;
         i += (long)gridDim.x*blockDim.x) {
        long j = i;
        const float4* s; float4* d;
        if (j < S_DYN)                       { s = s_dyn;    d = d_dyn; }
        else if ((j -= S_DYN)    < S_DYNOUT) { s = s_dynout; d = d_dynout; }
        else if ((j -= S_DYNOUT) < S_FF1)    { s = s_ff1;    d = d_ff1; }
        else if ((j -= S_FF1)    < S_FF2)    { s = s_ff2;    d = d_ff2; }
        else if ((j -= S_FF2)    < S_QKV)    { s = s_qkv;    d = d_qkv; }
        else if ((j -= S_QKV)    < S_ATTN)   { s = s_attn;   d = d_attn; }
        else if ((j -= S_ATTN)   < S_CLS)    { s = s_cls;    d = d_cls; }
        else { j -= S_CLS;                     s = s_log;    d = d_log; }
        float4 v = s[j];
        v.x = tfr(v.x); v.y = tfr(v.y); v.z = tfr(v.z); v.w = tfr(v.w);
        d[j] = v;
    }
}

// ---------------- TF32 GEMM: R10 champion + forced 2 CTAs/SM ----------------
// C[M,N] = A[M,K] @ B[N,K]^T + bias.  BM=128 BN=128 BK=32, 256 threads,
// 8 warps (4x2 of 32x64), 2-stage cp.async (73728 B smem).
// A and B MUST be TF32-pre-rounded. flags: 1=relu, 2=round output.
// Split-K: gridDim.z > 1 -> raw partials to P[z][M][256] (requires N==256).
#define GTILE 4608   // 128*36 floats per buffer

__device__ __forceinline__ void gemm_load_tile(
        const float* __restrict__ A, const float* __restrict__ B,
        int M, int N, int K, int row0, int col0,
        uint32_t sbase, int tid, int buf, int k0) {
    int r  = tid >> 3;
    int c4 = (tid & 7) * 4;
    #pragma unroll
    for (int p = 0; p < 4; p++) {
        int rr = r + p * 32;
        int gr = row0 + rr;
        const float* src = A + (size_t)(gr < M ? gr : (M - 1)) * K + k0 + c4;
        uint32_t dst = sbase + (uint32_t)((buf * GTILE + rr * 36 + c4) * 4);
        int sz = (gr < M) ? 16 : 0;
        asm volatile("cp.async.cg.shared.global [%0], [%1], 16, %2;\n"
                     :: "r"(dst), "l"(src), "r"(sz));
    }
    #pragma unroll
    for (int p = 0; p < 4; p++) {
        int rr = r + p * 32;
        int gn = col0 + rr;
        const float* src = B + (size_t)(gn < N ? gn : (N - 1)) * K + k0 + c4;
        uint32_t dst = sbase + (uint32_t)(((2 * GTILE) + buf * GTILE + rr * 36 + c4) * 4);
        int sz = (gn < N) ? 16 : 0;
        asm volatile("cp.async.cg.shared.global [%0], [%1], 16, %2;\n"
                     :: "r"(dst), "l"(src), "r"(sz));
    }
}

__global__ __launch_bounds__(256, 2)
void tf32_gemm(const float* __restrict__ A, const float* __restrict__ B,
               const float* __restrict__ bias, float* __restrict__ C,
               float* __restrict__ P,
               int M, int N, int K, int flags) {
    extern __shared__ float sm[];
    const int tid  = threadIdx.x;
    const int warp = tid >> 5, lane = tid & 31;
    const int wm = warp >> 1, wn = warp & 1;
    const int row0 = blockIdx.y * 128;
    const int col0 = blockIdx.x * 128;
    const int Kper  = K / gridDim.z;
    const int kbase = blockIdx.z * Kper;
    uint32_t sbase = (uint32_t)__cvta_generic_to_shared(sm);

    float acc[2][8][4];
    #pragma unroll
    for (int i = 0; i < 2; i++)
        #pragma unroll
        for (int j = 0; j < 8; j++)
            #pragma unroll
            for (int k = 0; k < 4; k++) acc[i][j][k] = 0.f;

    const int T = Kper >> 5;
    gemm_load_tile(A, B, M, N, K, row0, col0, sbase, tid, 0, kbase);
    asm volatile("cp.async.commit_group;");

    const int t2k  = (lane & 3) * 2;   // k-slot remap: hw (t,t+4) <- logical (2t,2t+1)
    const int arow = wm * 32 + (lane >> 2);
    const int brow = wn * 64 + (lane >> 2);

    for (int t = 0; t < T; t++) {
        if (t + 1 < T) {
            gemm_load_tile(A, B, M, N, K, row0, col0, sbase, tid, (t + 1) & 1, kbase + (t + 1) * 32);
            asm volatile("cp.async.commit_group;");
            asm volatile("cp.async.wait_group 1;");
        } else {
            asm volatile("cp.async.wait_group 0;");
        }
        __syncthreads();

        const float* as = sm + (t & 1) * GTILE;
        const float* bs = sm + 2 * GTILE + (t & 1) * GTILE;
        #pragma unroll
        for (int kk = 0; kk < 4; kk++) {
            const int kb = kk * 8 + t2k;
            uint32_t a[2][4];
            #pragma unroll
            for (int mi = 0; mi < 2; mi++) {
                const float* ap = as + (arow + mi * 16) * 36 + kb;
                float2 v0 = *(const float2*)ap;
                float2 v1 = *(const float2*)(ap + 8 * 36);
                a[mi][0] = __float_as_uint(v0.x);
                a[mi][2] = __float_as_uint(v0.y);
                a[mi][1] = __float_as_uint(v1.x);
                a[mi][3] = __float_as_uint(v1.y);
            }
            #pragma unroll
            for (int ni = 0; ni < 8; ni++) {
                const float* bp = bs + (brow + ni * 8) * 36 + kb;
                float2 bv = *(const float2*)bp;   // pre-rounded: raw bits valid
                uint32_t b0 = __float_as_uint(bv.x);
                uint32_t b1 = __float_as_uint(bv.y);
                #pragma unroll
                for (int mi = 0; mi < 2; mi++)
                    mma_tf32(acc[mi][ni], a[mi][0], a[mi][1], a[mi][2], a[mi][3], b0, b1);
            }
        }
        __syncthreads();
    }

    // epilogue
    if (gridDim.z == 1) {
        #pragma unroll
        for (int mi = 0; mi < 2; mi++) {
            int gr0 = row0 + wm * 32 + mi * 16 + (lane >> 2);
            #pragma unroll
            for (int ni = 0; ni < 8; ni++) {
                int gc = col0 + wn * 64 + ni * 8 + 2 * (lane & 3);
                if (gc >= N) continue;
                float bb0 = 0.f, bb1 = 0.f;
                if (bias) { bb0 = bias[gc]; bb1 = bias[gc + 1]; }
                #pragma unroll
                for (int half = 0; half < 2; half++) {
                    int gr = gr0 + half * 8;
                    if (gr >= M) continue;
                    float v0 = acc[mi][ni][half * 2]     + bb0;
                    float v1 = acc[mi][ni][half * 2 + 1] + bb1;
                    if (flags & 1) { v0 = fmaxf(v0, 0.f); v1 = fmaxf(v1, 0.f); }
                    if (flags & 2) { v0 = tfr(v0); v1 = tfr(v1); }
                    *(float2*)(C + (size_t)gr * N + gc) = make_float2(v0, v1);
                }
            }
        }
    } else {
        float* Pz = P + (size_t)blockIdx.z * M * 256;
        #pragma unroll
        for (int mi = 0; mi < 2; mi++) {
            int gr0 = row0 + wm * 32 + mi * 16 + (lane >> 2);
            #pragma unroll
            for (int ni = 0; ni < 8; ni++) {
                int gc = col0 + wn * 64 + ni * 8 + 2 * (lane & 3);
                if (gc >= N) continue;
                if (gr0 < M)
                    *(float2*)(Pz + (size_t)gr0 * 256 + gc) =
                        make_float2(acc[mi][ni][0], acc[mi][ni][1]);
                if (gr0 + 8 < M)
                    *(float2*)(Pz + (size_t)(gr0 + 8) * 256 + gc) =
                        make_float2(acc[mi][ni][2], acc[mi][ni][3]);
            }
        }
    }
}

// ---------------- split-K reduce: out[r][c] = sum_z P[z][r][c] + bias[c] ----------------
__global__ void reduce_splitk(const float* __restrict__ P, const float* __restrict__ bias,
                              float* __restrict__ out, int Z) {
    int r = blockIdx.x, c = threadIdx.x;    // 256 threads
    float s = 0.f;
    for (int z = 0; z < Z; z++) s += P[((size_t)z * ROWS + r) * 256 + c];
    out[(size_t)r * 256 + c] = s + bias[c];
}

// ---------------- IoU-relation attention mask ----------------
__global__ void mask_kernel(const float* __restrict__ bboxes,
                            const float* __restrict__ cur,
                            float* __restrict__ maskf) {
    int q = blockIdx.x, b = blockIdx.y, k = threadIdx.x;
    if (k >= NRr) return;
    float4 bq = *(const float4*)(bboxes + (size_t)(b*NRr + q)*4);
    float4 bk = *(const float4*)(bboxes + (size_t)(b*NRr + k)*4);
    float aq = (bq.z-bq.x)*(bq.w-bq.y);
    float ak = (bk.z-bk.x)*(bk.w-bk.y);
    float lx = fmaxf(bq.x, bk.x), ly = fmaxf(bq.y, bk.y);
    float rx = fminf(bq.z, bk.z), ry = fminf(bq.w, bk.w);
    float w  = fmaxf(rx-lx, 0.f), h = fmaxf(ry-ly, 0.f);
    float inter = w*h;
    float uni = fmaxf(aq + ak - inter, 1e-9f);
    float iou = inter/uni;
    float o   = (iou < 0.5f) ? 1.f : 0.f;
    float cq = cur[b*NRr + q], ck = cur[b*NRr + k];
    float val = o*cq*ck + ((q == k) ? (1.f - cq) : 0.f);
    maskf[((size_t)(b*NRr + q))*NRr + k] = (val > 0.f) ? 1.f : 0.f;
}

// ---------------- qk = round(pf+query); pfr = round(pf) ----------------
__global__ void add_round_kernel(const float* __restrict__ a, const float* __restrict__ b,
                                 float* __restrict__ qk, float* __restrict__ pfr, int n) {
    int i = blockIdx.x*blockDim.x + threadIdx.x;
    if (i < n) {
        float av = a[i];
        qk[i]  = tfr(av + b[i]);
        pfr[i] = tfr(av);
    }
}

// ---------------- masked multi-head attention (online softmax, q-chunked) ----------------
#define QCH 100
__global__ void attn_kernel(const float* __restrict__ qp, const float* __restrict__ kp,
                            const float* __restrict__ vp, const float* __restrict__ maskf,
                            float* __restrict__ ctx) {
    const int bh = blockIdx.x / 3;
    const int ch = blockIdx.x % 3;
    const int b = bh >> 3;
    const int h = bh & 7;
    __shared__ float Ks[150*32];
    __shared__ float Vs[150*32];
    const int tid = threadIdx.x;          // 128
    const int q = ch * QCH + tid;
    const bool act = (tid < QCH) && (q < NRr);
    float qv[32], acc[32];
    float m = -1e30f, ssum = 0.f;
    if (act) {
        const float* qr = qp + ((size_t)(b*NRr + q))*DD_ + h*HDIM;
        #pragma unroll
        for (int d = 0; d < 32; d++) { qv[d] = qr[d]; acc[d] = 0.f; }
    }
    const float* mrow = maskf + ((size_t)(b*NRr) + (act ? q : 0))*NRr;
    const float scale = 0.17677669529663687f;  // 1/sqrt(32)

    for (int c0 = 0; c0 < NRr; c0 += 150) {
        __syncthreads();
        for (int i = tid; i < 150*32; i += 128) {
            int k = i >> 5, d = i & 31;
            size_t gi = ((size_t)(b*NRr + c0 + k))*DD_ + h*HDIM + d;
            Ks[i] = kp[gi];
            Vs[i] = vp[gi];
        }
        __syncthreads();
        if (act) {
            for (int k = 0; k < 150; k++) {
                const float* kr = Ks + k*32;
                float x0 = 0.f, x1 = 0.f, x2 = 0.f, x3 = 0.f;
                #pragma unroll
                for (int d = 0; d < 32; d += 4) {
                    x0 += qv[d]*kr[d];   x1 += qv[d+1]*kr[d+1];
                    x2 += qv[d+2]*kr[d+2]; x3 += qv[d+3]*kr[d+3];
                }
                float x = ((x0+x1)+(x2+x3))*scale;
                if (mrow[c0+k] > 0.f) x = -1e9f;
                float nm = fmaxf(m, x);
                float sc = __expf(m - nm);
                float e  = __expf(x - nm);
                ssum = ssum*sc + e;
                const float* vr = Vs + k*32;
                #pragma unroll
                for (int d = 0; d < 32; d++) acc[d] = acc[d]*sc + e*vr[d];
                m = nm;
            }
        }
    }
    if (act) {
        float inv = 1.f/ssum;
        float* cr = ctx + ((size_t)(b*NRr + q))*DD_ + h*HDIM;
        #pragma unroll
        for (int d = 0; d < 32; d++) cr[d] = tfr(acc[d]*inv);
    }
}

// ---------------- ln(residual) * mask -> exact (optional) + rounded ----------------
__global__ void ln_res_mask_kernel(const float* __restrict__ a, const float* __restrict__ bq,
                                   const float* __restrict__ cur,
                                   float* __restrict__ out, float* __restrict__ out_r) {
    int r = blockIdx.x, t = threadIdx.x;
    float x = a[(size_t)r*DD_ + t] + bq[(size_t)r*DD_ + t];
    float mean = blockReduceSum256(x) * (1.f/256.f);
    float d = x - mean;
    float var = blockReduceSum256(d*d) * (1.f/256.f);
    float y = d * rsqrtf(var + 1e-5f) * cur[r];
    if (out) out[(size_t)r*DD_ + t] = y;
    out_r[(size_t)r*DD_ + t] = tfr(y);
}

// ---------------- relu(ln(x)) -> + pf1 -> ln (exact + rounded) ----------------
__global__ void post_dyn_kernel(const float* __restrict__ x, const float* __restrict__ pf1,
                                float* __restrict__ out, float* __restrict__ out_r) {
    int r = blockIdx.x, t = threadIdx.x;
    float v = x[(size_t)r*DD_ + t];
    float m1 = blockReduceSum256(v) * (1.f/256.f);
    float d1 = v - m1;
    float v1 = blockReduceSum256(d1*d1) * (1.f/256.f);
    float rl = fmaxf(d1 * rsqrtf(v1 + 1e-5f), 0.f);
    float y = pf1[(size_t)r*DD_ + t] + rl;
    float m2 = blockReduceSum256(y) * (1.f/256.f);
    float d2 = y - m2;
    float v2 = blockReduceSum256(d2*d2) * (1.f/256.f);
    float z = d2 * rsqrtf(v2 + 1e-5f);
    out[(size_t)r*DD_ + t] = z;
    out_r[(size_t)r*DD_ + t] = tfr(z);
}

// ---------------- relu(ln(x)) rounded ----------------
__global__ void ln_relu_kernel(const float* __restrict__ x, float* __restrict__ out) {
    int r = blockIdx.x, t = threadIdx.x;
    float v = x[(size_t)r*DD_ + t];
    float m = blockReduceSum256(v) * (1.f/256.f);
    float d = v - m;
    float var = blockReduceSum256(d*d) * (1.f/256.f);
    out[(size_t)r*DD_ + t] = tfr(fmaxf(d * rsqrtf(var + 1e-5f), 0.f));
}

// ---------------- DynamicConv (register-tiled) ----------------
#define SPAD 52
#define DYN_SMEM 210944

__global__ __launch_bounds__(256)
void dynconv_kernel(const float* __restrict__ roi, const float* __restrict__ params,
                    float* __restrict__ out) {
    int n = blockIdx.x;
    extern __shared__ float sm[];
    float* featsT = sm;                 // [d][s] 256 x 52
    float* p1     = sm + 13312;         // [d][e] 256 x 64
    float* p2     = p1 + 16384;         // [e][d] 64 x 256
    float* f1     = p2 + 16384;         // [s][e] 52 x 64
    float* f1T    = f1 + 3328;          // [e][s] 64 x 52
    int tid = threadIdx.x;

    for (int i = tid; i < 256*3; i += 256) {
        int d = i / 3, s = 49 + (i % 3);
        featsT[d*SPAD + s] = 0.f;
    }
    for (int i = tid; i < SS*DD_; i += 256) {
        int s = i >> 8, d = i & 255;
        featsT[d*SPAD + s] = roi[((size_t)s*ROWS + n)*DD_ + d];
    }
    const float4* pr = (const float4*)(params + (size_t)n * 32768);
    float4* p14 = (float4*)p1;
    float4* p24 = (float4*)p2;
    for (int i = tid; i < 4096; i += 256) p14[i] = pr[i];
    for (int i = tid; i < 4096; i += 256) p24[i] = pr[4096 + i];
    __syncthreads();

    {
        int te = tid & 15, tsg = tid >> 4;
        if (tsg < 13) {
            int e0 = te * 4, s0 = tsg * 4;
            float acc[4][4];
            #pragma unroll
            for (int i = 0; i < 4; i++)
                #pragma unroll
                for (int j = 0; j < 4; j++) acc[i][j] = 0.f;
            for (int d = 0; d < 256; d++) {
                float4 fv = *(const float4*)(featsT + d*SPAD + s0);
                float4 pv = *(const float4*)(p1 + d*64 + e0);
                acc[0][0] += fv.x*pv.x; acc[0][1] += fv.x*pv.y; acc[0][2] += fv.x*pv.z; acc[0][3] += fv.x*pv.w;
                acc[1][0] += fv.y*pv.x; acc[1][1] += fv.y*pv.y; acc[1][2] += fv.y*pv.z; acc[1][3] += fv.y*pv.w;
                acc[2][0] += fv.z*pv.x; acc[2][1] += fv.z*pv.y; acc[2][2] += fv.z*pv.z; acc[2][3] += fv.z*pv.w;
                acc[3][0] += fv.w*pv.x; acc[3][1] += fv.w*pv.y; acc[3][2] += fv.w*pv.z; acc[3][3] += fv.w*pv.w;
            }
            #pragma unroll
            for (int i = 0; i < 4; i++)
                #pragma unroll
                for (int j = 0; j < 4; j++)
                    f1[(s0+i)*64 + e0 + j] = acc[i][j];
        }
    }
    __syncthreads();

    int warp = tid >> 5, lane = tid & 31;
    for (int s = warp; s < SS; s += 8) {
        float x0 = f1[s*64 + lane], x1 = f1[s*64 + 32 + lane];
        float sum = x0 + x1;
        #pragma unroll
        for (int o = 16; o; o >>= 1) sum += __shfl_xor_sync(0xffffffffu, sum, o);
        float m = sum * (1.f/64.f);
        float d0 = x0 - m, d1 = x1 - m;
        float vs = d0*d0 + d1*d1;
        #pragma unroll
        for (int o = 16; o; o >>= 1) vs += __shfl_xor_sync(0xffffffffu, vs, o);
        float inv = rsqrtf(vs*(1.f/64.f) + 1e-5f);
        f1T[lane*SPAD + s]        = fmaxf(d0*inv, 0.f);
        f1T[(32+lane)*SPAD + s]   = fmaxf(d1*inv, 0.f);
    }
    __syncthreads();

    float* f2 = featsT;
    {
        int td = tid & 63, tsg2 = tid >> 6;
        int d0 = td * 4;
        for (int sg = tsg2; sg < 13; sg += 4) {
            int s0 = sg * 4;
            float acc[4][4];
            #pragma unroll
            for (int i = 0; i < 4; i++)
                #pragma unroll
                for (int j = 0; j < 4; j++) acc[i][j] = 0.f;
            for (int e = 0; e < 64; e++) {
                float4 fv = *(const float4*)(f1T + e*SPAD + s0);
                float4 pv = *(const float4*)(p2 + e*256 + d0);
                acc[0][0] += fv.x*pv.x; acc[0][1] += fv.x*pv.y; acc[0][2] += fv.x*pv.z; acc[0][3] += fv.x*pv.w;
                acc[1][0] += fv.y*pv.x; acc[1][1] += fv.y*pv.y; acc[1][2] += fv.y*pv.z; acc[1][3] += fv.y*pv.w;
                acc[2][0] += fv.z*pv.x; acc[2][1] += fv.z*pv.y; acc[2][2] += fv.z*pv.z; acc[2][3] += fv.z*pv.w;
                acc[3][0] += fv.w*pv.x; acc[3][1] += fv.w*pv.y; acc[3][2] += fv.w*pv.z; acc[3][3] += fv.w*pv.w;
            }
            #pragma unroll
            for (int i = 0; i < 4; i++)
                #pragma unroll
                for (int j = 0; j < 4; j++)
                    f2[(s0+i)*256 + d0 + j] = acc[i][j];
        }
    }
    __syncthreads();

    for (int s = warp; s < SS; s += 8) {
        float x[8]; float sum = 0.f;
        #pragma unroll
        for (int j = 0; j < 8; j++) { x[j] = f2[s*256 + j*32 + lane]; sum += x[j]; }
        #pragma unroll
        for (int o = 16; o; o >>= 1) sum += __shfl_xor_sync(0xffffffffu, sum, o);
        float m = sum * (1.f/256.f);
        float vs = 0.f;
        #pragma unroll
        for (int j = 0; j < 8; j++) { float dd = x[j]-m; vs += dd*dd; }
        #pragma unroll
        for (int o = 16; o; o >>= 1) vs += __shfl_xor_sync(0xffffffffu, vs, o);
        float inv = rsqrtf(vs*(1.f/256.f) + 1e-5f);
        #pragma unroll
        for (int j = 0; j < 8; j++)
            out[(size_t)n*12544 + s*256 + j*32 + lane] = tfr(fmaxf((x[j]-m)*inv, 0.f));
    }
}

// ---------------- host ----------------
extern "C" void kernel_launch(void* const* d_in, const int* in_sizes, int n_in,
                              void* d_out, int out_size) {
    const float* bboxes     = (const float*)d_in[0];
    const float* pf         = (const float*)d_in[1];
    const float* roi        = (const float*)d_in[2];
    const float* query      = (const float*)d_in[3];
    const float* cur        = (const float*)d_in[4];
    const float* w_qkv      = (const float*)d_in[5];
    const float* b_qkv      = (const float*)d_in[6];
    const float* w_attn_out = (const float*)d_in[7];
    const float* b_attn_out = (const float*)d_in[8];
    const float* w_dyn      = (const float*)d_in[9];
    const float* b_dyn      = (const float*)d_in[10];
    const float* w_dyn_out  = (const float*)d_in[11];
    const float* b_dyn_out  = (const float*)d_in[12];
    const float* w_ff1      = (const float*)d_in[13];
    const float* b_ff1      = (const float*)d_in[14];
    const float* w_ff2      = (const float*)d_in[15];
    const float* b_ff2      = (const float*)d_in[16];
    const float* w_cls      = (const float*)d_in[17];
    const float* w_logits   = (const float*)d_in[18];
    const float* b_logits   = (const float*)d_in[19];
    float* out = (float*)d_out;

    float *qk,*pfr,*qp,*kp,*vp,*maskb,*ctx,*tgt2,*pf1,*pf1r,*params,*f2,*x,*pf3,*pf3r,*ffn,*t2,*fc,*clsy,*clsf,*part;
    float *wqkv,*wattn,*wdyn,*wdynout,*wff1,*wff2,*wcls,*wlog;
    cudaGetSymbolAddress((void**)&qk,     g_qk);
    cudaGetSymbolAddress((void**)&pfr,    g_pfr);
    cudaGetSymbolAddress((void**)&qp,     g_qp);
    cudaGetSymbolAddress((void**)&kp,     g_kp);
    cudaGetSymbolAddress((void**)&vp,     g_vp);
    cudaGetSymbolAddress((void**)&maskb,  g_mask);
    cudaGetSymbolAddress((void**)&ctx,    g_ctx);
    cudaGetSymbolAddress((void**)&tgt2,   g_tgt2);
    cudaGetSymbolAddress((void**)&pf1,    g_pf1);
    cudaGetSymbolAddress((void**)&pf1r,   g_pf1r);
    cudaGetSymbolAddress((void**)&params, g_params);
    cudaGetSymbolAddress((void**)&f2,     g_f2);
    cudaGetSymbolAddress((void**)&x,      g_x);
    cudaGetSymbolAddress((void**)&pf3,    g_pf3);
    cudaGetSymbolAddress((void**)&pf3r,   g_pf3r);
    cudaGetSymbolAddress((void**)&ffn,    g_ffn);
    cudaGetSymbolAddress((void**)&t2,     g_t2);
    cudaGetSymbolAddress((void**)&fc,     g_fc);
    cudaGetSymbolAddress((void**)&clsy,   g_clsy);
    cudaGetSymbolAddress((void**)&clsf,   g_clsf);
    cudaGetSymbolAddress((void**)&part,   g_part);
    cudaGetSymbolAddress((void**)&wqkv,   g_wqkv_r);
    cudaGetSymbolAddress((void**)&wattn,  g_wattn_r);
    cudaGetSymbolAddress((void**)&wdyn,   g_wdyn_r);
    cudaGetSymbolAddress((void**)&wdynout,g_wdynout_r);
    cudaGetSymbolAddress((void**)&wff1,   g_wff1_r);
    cudaGetSymbolAddress((void**)&wff2,   g_wff2_r);
    cudaGetSymbolAddress((void**)&wcls,   g_wcls_r);
    cudaGetSymbolAddress((void**)&wlog,   g_wlog_r);

    const int GEMM_SMEM = 4 * GTILE * 4;   // 73728 B (2 stages, proven)
    cudaFuncSetAttribute(tf32_gemm, cudaFuncAttributeMaxDynamicSharedMemorySize, GEMM_SMEM);
    cudaFuncSetAttribute(dynconv_kernel, cudaFuncAttributeMaxDynamicSharedMemorySize, DYN_SMEM);

    auto grd = [](int M, int N) { return dim3((unsigned)((N+127)/128), (unsigned)((M+127)/128), 1); };

    // prep: mask, rounded activations, rounded weights
    mask_kernel<<<dim3(NRr, NB), 320>>>(bboxes, cur, maskb);
    add_round_kernel<<<(ROWS*DD_+255)/256, 256>>>(pf, query, qk, pfr, ROWS*DD_);
    round_weights<<<1280, 256>>>((const float4*)w_dyn,     (float4*)wdyn,
                                 (const float4*)w_dyn_out, (float4*)wdynout,
                                 (const float4*)w_ff1,     (float4*)wff1,
                                 (const float4*)w_ff2,     (float4*)wff2,
                                 (const float4*)w_qkv,     (float4*)wqkv,
                                 (const float4*)w_attn_out,(float4*)wattn,
                                 (const float4*)w_cls,     (float4*)wcls,
                                 (const float4*)w_logits,  (float4*)wlog);

    // QKV projections
    tf32_gemm<<<grd(ROWS,256), 256, GEMM_SMEM>>>(qk,  wqkv,           b_qkv,     qp, nullptr, ROWS, 256, 256, 0);
    tf32_gemm<<<grd(ROWS,256), 256, GEMM_SMEM>>>(qk,  wqkv + 256*256, b_qkv+256, kp, nullptr, ROWS, 256, 256, 0);
    tf32_gemm<<<grd(ROWS,256), 256, GEMM_SMEM>>>(pfr, wqkv + 512*256, b_qkv+512, vp, nullptr, ROWS, 256, 256, 0);
    // masked MHSA (ctx rounded in epilogue)
    attn_kernel<<<NB*HH*3, 128>>>(qp, kp, vp, maskb, ctx);
    // out proj + norm1*mask
    tf32_gemm<<<grd(ROWS,256), 256, GEMM_SMEM>>>(ctx, wattn, b_attn_out, tgt2, nullptr, ROWS, 256, 256, 0);
    ln_res_mask_kernel<<<ROWS, 256>>>(pf, tgt2, cur, pf1, pf1r);
    // DynamicConv params GEMM (dominant, chip-full)
    tf32_gemm<<<grd(ROWS,32768), 256, GEMM_SMEM>>>(pf1r, wdyn, b_dyn, params, nullptr, ROWS, 32768, 256, 0);
    // per-instance dynamic conv (rounded output)
    dynconv_kernel<<<ROWS, 256, DYN_SMEM>>>(roi, params, f2);
    // dyn out proj — split-K(8) + reduce; norm2
    tf32_gemm<<<dim3(2,19,8), 256, GEMM_SMEM>>>(f2, wdynout, nullptr, nullptr, part, ROWS, 256, 12544, 0);
    reduce_splitk<<<ROWS, 256>>>(part, b_dyn_out, x, 8);
    post_dyn_kernel<<<ROWS, 256>>>(x, pf1, pf3, pf3r);
    // FFN: ff1 (relu+round) + ff2 split-K(8); norm3
    tf32_gemm<<<grd(ROWS,2048), 256, GEMM_SMEM>>>(pf3r, wff1, b_ff1, ffn, nullptr, ROWS, 2048, 256, 3);
    tf32_gemm<<<dim3(2,19,8), 256, GEMM_SMEM>>>(ffn, wff2, nullptr, nullptr, part, ROWS, 256, 2048, 0);
    reduce_splitk<<<ROWS, 256>>>(part, b_ff2, t2, 8);
    ln_res_mask_kernel<<<ROWS, 256>>>(pf3, t2, cur, nullptr, fc);
    // cls tower + logits
    tf32_gemm<<<grd(ROWS,256), 256, GEMM_SMEM>>>(fc, wcls, nullptr, clsy, nullptr, ROWS, 256, 256, 0);
    ln_relu_kernel<<<ROWS, 256>>>(clsy, clsf);
    tf32_gemm<<<grd(ROWS,80), 256, GEMM_SMEM>>>(clsf, wlog, b_logits, out, nullptr, ROWS, 80, 256, 0);
}

// round 13
// speedup vs baseline: 1.5122x; 1.3585x over previous
#include <cuda_runtime.h>
#include <cuda_fp16.h>
#include <math.h>
#include <stdint.h>

// ---------------- constants ----------------
#define NB   8
#define NRr  300
#define DD_  256
#define HH   8
#define HDIM 32
#define SS   49
#define FFN  2048
#define NCL  80
#define ROWS (NB*NRr)    // 2400

// ---------------- scratch ----------------
__device__ __half g_qk   [ROWS*DD_];       // h(pf+query)
__device__ __half g_pfr  [ROWS*DD_];       // h(pf)
__device__ float  g_qp   [ROWS*DD_];
__device__ float  g_kp   [ROWS*DD_];
__device__ float  g_vp   [ROWS*DD_];
__device__ float  g_mask [NB*NRr*NRr];
__device__ __half g_ctx  [ROWS*DD_];
__device__ float  g_tgt2 [ROWS*DD_];
__device__ float  g_pf1  [ROWS*DD_];
__device__ __half g_pf1r [ROWS*DD_];
__device__ __half g_params[78643200];      // 2400*32768 fp16
__device__ __half g_f2   [30105600];       // 2400*12544 fp16
__device__ float  g_x    [ROWS*DD_];
__device__ float  g_pf3  [ROWS*DD_];
__device__ __half g_pf3r [ROWS*DD_];
__device__ __half g_ffn  [ROWS*FFN];       // fp16 (GEMM epilogue)
__device__ float  g_t2   [ROWS*DD_];
__device__ __half g_fc   [ROWS*DD_];
__device__ float  g_clsy [ROWS*DD_];
__device__ __half g_clsf [ROWS*DD_];
__device__ float  g_part [8*ROWS*256];     // split-K partials (fp32)
// fp16 weights
__device__ __half g_wqkv_h  [768*256];
__device__ __half g_wattn_h [256*256];
__device__ __half g_wdyn_h  [32768*256];
__device__ __half g_wdynout_h[256*12544];
__device__ __half g_wff1_h  [2048*256];
__device__ __half g_wff2_h  [256*2048];
__device__ __half g_wcls_h  [256*256];
__device__ __half g_wlog_h  [80*256];

// ---------------- helpers ----------------
__device__ __forceinline__ float blockReduceSum256(float v) {
    __shared__ float red[8];
    int lane = threadIdx.x & 31, w = threadIdx.x >> 5;
    #pragma unroll
    for (int o = 16; o; o >>= 1) v += __shfl_xor_sync(0xffffffffu, v, o);
    __syncthreads();
    if (lane == 0) red[w] = v;
    __syncthreads();
    float s = 0.f;
    #pragma unroll
    for (int i = 0; i < 8; i++) s += red[i];
    return s;
}

__device__ __forceinline__ void mma_fp16(float* c,
        uint32_t a0, uint32_t a1, uint32_t a2, uint32_t a3,
        uint32_t b0, uint32_t b1) {
    asm volatile(
        "mma.sync.aligned.m16n8k16.row.col.f32.f16.f16.f32 "
        "{%0,%1,%2,%3}, {%4,%5,%6,%7}, {%8,%9}, {%0,%1,%2,%3};"
        : "+f"(c[0]), "+f"(c[1]), "+f"(c[2]), "+f"(c[3])
        : "r"(a0), "r"(a1), "r"(a2), "r"(a3), "r"(b0), "r"(b1));
}

// ---------------- weight rounding fp32 -> fp16 (one streaming pass) ----------------
#define S_DYN    2097152
#define S_DYNOUT  802816
#define S_FF1     131072
#define S_FF2     131072
#define S_QKV      49152
#define S_ATTN     16384
#define S_CLS      16384
#define S_LOG       5120
#define S_TOT4   3249152

__global__ void round_weights(const float4* __restrict__ s_dyn,    __half* d_dyn,
                              const float4* __restrict__ s_dynout, __half* d_dynout,
                              const float4* __restrict__ s_ff1,    __half* d_ff1,
                              const float4* __restrict__ s_ff2,    __half* d_ff2,
                              const float4* __restrict__ s_qkv,    __half* d_qkv,
                              const float4* __restrict__ s_attn,   __half* d_attn,
                              const float4* __restrict__ s_cls,    __half* d_cls,
                              const float4* __restrict__ s_log,    __half* d_log) {
    for (long i = blockIdx.x*(long)blockDim.x + threadIdx.x; i < S_TOT4;
         i += (long)gridDim.x*blockDim.x) {
        long j = i;
        const float4* s; __half* d;
        if (j < S_DYN)                       { s = s_dyn;    d = d_dyn; }
        else if ((j -= S_DYN)    < S_DYNOUT) { s = s_dynout; d = d_dynout; }
        else if ((j -= S_DYNOUT) < S_FF1)    { s = s_ff1;    d = d_ff1; }
        else if ((j -= S_FF1)    < S_FF2)    { s = s_ff2;    d = d_ff2; }
        else if ((j -= S_FF2)    < S_QKV)    { s = s_qkv;    d = d_qkv; }
        else if ((j -= S_QKV)    < S_ATTN)   { s = s_attn;   d = d_attn; }
        else if ((j -= S_ATTN)   < S_CLS)    { s = s_cls;    d = d_cls; }
        else { j -= S_CLS;                     s = s_log;    d = d_log; }
        float4 v = s[j];
        __half2* dst = (__half2*)(d + j * 4);
        dst[0] = __floats2half2_rn(v.x, v.y);
        dst[1] = __floats2half2_rn(v.z, v.w);
    }
}

// ---------------- FP16 tensor GEMM: BM=128 BN=128 BK=64, 256 threads ----------------
// C[M,N] = A[M,K] @ B[N,K]^T + bias.  8 warps (4x2 of 32x64), 2-stage cp.async,
// 73728 B smem. A,B are __half. flags: 1=relu, 2=write half to Ch instead of C.
// Split-K: gridDim.z>1 -> raw fp32 partials to P[z][M][256] (requires N==256).
#define GT_H 9216   // 128 rows * 72 halfs per buffer

__device__ __forceinline__ void gemm_load_tile(
        const __half* __restrict__ A, const __half* __restrict__ B,
        int M, int N, int K, int row0, int col0,
        uint32_t sbase, int tid, int buf, int k0) {
    int r  = tid >> 3;              // 0..31
    int c8 = (tid & 7) * 8;         // half offset 0..56
    #pragma unroll
    for (int p = 0; p < 4; p++) {
        int rr = r + p * 32;
        int gr = row0 + rr;
        const __half* src = A + (size_t)(gr < M ? gr : (M - 1)) * K + k0 + c8;
        uint32_t dst = sbase + (uint32_t)((buf * GT_H + rr * 72 + c8) * 2);
        int sz = (gr < M) ? 16 : 0;
        asm volatile("cp.async.cg.shared.global [%0], [%1], 16, %2;\n"
                     :: "r"(dst), "l"(src), "r"(sz));
    }
    #pragma unroll
    for (int p = 0; p < 4; p++) {
        int rr = r + p * 32;
        int gn = col0 + rr;
        const __half* src = B + (size_t)(gn < N ? gn : (N - 1)) * K + k0 + c8;
        uint32_t dst = sbase + (uint32_t)(((2 * GT_H) + buf * GT_H + rr * 72 + c8) * 2);
        int sz = (gn < N) ? 16 : 0;
        asm volatile("cp.async.cg.shared.global [%0], [%1], 16, %2;\n"
                     :: "r"(dst), "l"(src), "r"(sz));
    }
}

__global__ __launch_bounds__(256)
void fp16_gemm(const __half* __restrict__ A, const __half* __restrict__ B,
               const float* __restrict__ bias, float* __restrict__ C,
               __half* __restrict__ Ch, float* __restrict__ P,
               int M, int N, int K, int flags) {
    extern __shared__ __half smh[];
    const int tid  = threadIdx.x;
    const int warp = tid >> 5, lane = tid & 31;
    const int wm = warp >> 1, wn = warp & 1;
    const int row0 = blockIdx.y * 128;
    const int col0 = blockIdx.x * 128;
    const int Kper  = K / gridDim.z;
    const int kbase = blockIdx.z * Kper;
    uint32_t sbase = (uint32_t)__cvta_generic_to_shared(smh);

    float acc[2][8][4];
    #pragma unroll
    for (int i = 0; i < 2; i++)
        #pragma unroll
        for (int j = 0; j < 8; j++)
            #pragma unroll
            for (int k = 0; k < 4; k++) acc[i][j][k] = 0.f;

    const int T = Kper >> 6;        // BK=64
    gemm_load_tile(A, B, M, N, K, row0, col0, sbase, tid, 0, kbase);
    asm volatile("cp.async.commit_group;");

    const int t4   = (lane & 3) * 4;   // logical-k offset within k16 sub-chunk
    const int arow = wm * 32 + (lane >> 2);
    const int brow = wn * 64 + (lane >> 2);

    for (int t = 0; t < T; t++) {
        if (t + 1 < T) {
            gemm_load_tile(A, B, M, N, K, row0, col0, sbase, tid, (t + 1) & 1, kbase + (t + 1) * 64);
            asm volatile("cp.async.commit_group;");
            asm volatile("cp.async.wait_group 1;");
        } else {
            asm volatile("cp.async.wait_group 0;");
        }
        __syncthreads();

        const __half* as = smh + (t & 1) * GT_H;
        const __half* bs = smh + 2 * GT_H + (t & 1) * GT_H;
        #pragma unroll
        for (int kk = 0; kk < 4; kk++) {            // 4 x k16
            const int kb = kk * 16 + t4;
            uint2 a0[2], a1[2];
            #pragma unroll
            for (int mi = 0; mi < 2; mi++) {
                a0[mi] = *(const uint2*)(as + (arow + mi * 16) * 72 + kb);
                a1[mi] = *(const uint2*)(as + (arow + mi * 16 + 8) * 72 + kb);
            }
            #pragma unroll
            for (int ni = 0; ni < 8; ni++) {
                uint2 bb = *(const uint2*)(bs + (brow + ni * 8) * 72 + kb);
                #pragma unroll
                for (int mi = 0; mi < 2; mi++)
                    mma_fp16(acc[mi][ni], a0[mi].x, a1[mi].x, a0[mi].y, a1[mi].y,
                             bb.x, bb.y);
            }
        }
        __syncthreads();
    }

    // epilogue
    if (gridDim.z == 1) {
        #pragma unroll
        for (int mi = 0; mi < 2; mi++) {
            int gr0 = row0 + wm * 32 + mi * 16 + (lane >> 2);
            #pragma unroll
            for (int ni = 0; ni < 8; ni++) {
                int gc = col0 + wn * 64 + ni * 8 + 2 * (lane & 3);
                if (gc >= N) continue;
                float bb0 = 0.f, bb1 = 0.f;
                if (bias) { bb0 = bias[gc]; bb1 = bias[gc + 1]; }
                #pragma unroll
                for (int half_ = 0; half_ < 2; half_++) {
                    int gr = gr0 + half_ * 8;
                    if (gr >= M) continue;
                    float v0 = acc[mi][ni][half_ * 2]     + bb0;
                    float v1 = acc[mi][ni][half_ * 2 + 1] + bb1;
                    if (flags & 1) { v0 = fmaxf(v0, 0.f); v1 = fmaxf(v1, 0.f); }
                    if (flags & 2) {
                        *(__half2*)(Ch + (size_t)gr * N + gc) = __floats2half2_rn(v0, v1);
                    } else {
                        *(float2*)(C + (size_t)gr * N + gc) = make_float2(v0, v1);
                    }
                }
            }
        }
    } else {
        float* Pz = P + (size_t)blockIdx.z * M * 256;
        #pragma unroll
        for (int mi = 0; mi < 2; mi++) {
            int gr0 = row0 + wm * 32 + mi * 16 + (lane >> 2);
            #pragma unroll
            for (int ni = 0; ni < 8; ni++) {
                int gc = col0 + wn * 64 + ni * 8 + 2 * (lane & 3);
                if (gc >= N) continue;
                if (gr0 < M)
                    *(float2*)(Pz + (size_t)gr0 * 256 + gc) =
                        make_float2(acc[mi][ni][0], acc[mi][ni][1]);
                if (gr0 + 8 < M)
                    *(float2*)(Pz + (size_t)(gr0 + 8) * 256 + gc) =
                        make_float2(acc[mi][ni][2], acc[mi][ni][3]);
            }
        }
    }
}

// ---------------- split-K reduce: out[r][c] = sum_z P[z][r][c] + bias[c] ----------------
__global__ void reduce_splitk(const float* __restrict__ P, const float* __restrict__ bias,
                              float* __restrict__ out, int Z) {
    int r = blockIdx.x, c = threadIdx.x;    // 256 threads
    float s = 0.f;
    for (int z = 0; z < Z; z++) s += P[((size_t)z * ROWS + r) * 256 + c];
    out[(size_t)r * 256 + c] = s + bias[c];
}

// ---------------- IoU-relation attention mask ----------------
__global__ void mask_kernel(const float* __restrict__ bboxes,
                            const float* __restrict__ cur,
                            float* __restrict__ maskf) {
    int q = blockIdx.x, b = blockIdx.y, k = threadIdx.x;
    if (k >= NRr) return;
    float4 bq = *(const float4*)(bboxes + (size_t)(b*NRr + q)*4);
    float4 bk = *(const float4*)(bboxes + (size_t)(b*NRr + k)*4);
    float aq = (bq.z-bq.x)*(bq.w-bq.y);
    float ak = (bk.z-bk.x)*(bk.w-bk.y);
    float lx = fmaxf(bq.x, bk.x), ly = fmaxf(bq.y, bk.y);
    float rx = fminf(bq.z, bk.z), ry = fminf(bq.w, bk.w);
    float w  = fmaxf(rx-lx, 0.f), h = fmaxf(ry-ly, 0.f);
    float inter = w*h;
    float uni = fmaxf(aq + ak - inter, 1e-9f);
    float iou = inter/uni;
    float o   = (iou < 0.5f) ? 1.f : 0.f;
    float cq = cur[b*NRr + q], ck = cur[b*NRr + k];
    float val = o*cq*ck + ((q == k) ? (1.f - cq) : 0.f);
    maskf[((size_t)(b*NRr + q))*NRr + k] = (val > 0.f) ? 1.f : 0.f;
}

// ---------------- qk = h(pf+query); pfr = h(pf) ----------------
__global__ void add_round_kernel(const float* __restrict__ a, const float* __restrict__ b,
                                 __half* __restrict__ qk, __half* __restrict__ pfr, int n) {
    int i = blockIdx.x*blockDim.x + threadIdx.x;
    if (i < n) {
        float av = a[i];
        qk[i]  = __float2half_rn(av + b[i]);
        pfr[i] = __float2half_rn(av);
    }
}

// ---------------- masked multi-head attention (online softmax, q-chunked) ----------------
#define QCH 100
__global__ void attn_kernel(const float* __restrict__ qp, const float* __restrict__ kp,
                            const float* __restrict__ vp, const float* __restrict__ maskf,
                            __half* __restrict__ ctx) {
    const int bh = blockIdx.x / 3;
    const int ch = blockIdx.x % 3;
    const int b = bh >> 3;
    const int h = bh & 7;
    __shared__ float Ks[150*32];
    __shared__ float Vs[150*32];
    const int tid = threadIdx.x;          // 128
    const int q = ch * QCH + tid;
    const bool act = (tid < QCH) && (q < NRr);
    float qv[32], acc[32];
    float m = -1e30f, ssum = 0.f;
    if (act) {
        const float* qr = qp + ((size_t)(b*NRr + q))*DD_ + h*HDIM;
        #pragma unroll
        for (int d = 0; d < 32; d++) { qv[d] = qr[d]; acc[d] = 0.f; }
    }
    const float* mrow = maskf + ((size_t)(b*NRr) + (act ? q : 0))*NRr;
    const float scale = 0.17677669529663687f;  // 1/sqrt(32)

    for (int c0 = 0; c0 < NRr; c0 += 150) {
        __syncthreads();
        for (int i = tid; i < 150*32; i += 128) {
            int k = i >> 5, d = i & 31;
            size_t gi = ((size_t)(b*NRr + c0 + k))*DD_ + h*HDIM + d;
            Ks[i] = kp[gi];
            Vs[i] = vp[gi];
        }
        __syncthreads();
        if (act) {
            for (int k = 0; k < 150; k++) {
                const float* kr = Ks + k*32;
                float x0 = 0.f, x1 = 0.f, x2 = 0.f, x3 = 0.f;
                #pragma unroll
                for (int d = 0; d < 32; d += 4) {
                    x0 += qv[d]*kr[d];   x1 += qv[d+1]*kr[d+1];
                    x2 += qv[d+2]*kr[d+2]; x3 += qv[d+3]*kr[d+3];
                }
                float x = ((x0+x1)+(x2+x3))*scale;
                if (mrow[c0+k] > 0.f) x = -1e9f;
                float nm = fmaxf(m, x);
                float sc = __expf(m - nm);
                float e  = __expf(x - nm);
                ssum = ssum*sc + e;
                const float* vr = Vs + k*32;
                #pragma unroll
                for (int d = 0; d < 32; d++) acc[d] = acc[d]*sc + e*vr[d];
                m = nm;
            }
        }
    }
    if (act) {
        float inv = 1.f/ssum;
        __half* cr = ctx + ((size_t)(b*NRr + q))*DD_ + h*HDIM;
        #pragma unroll
        for (int d = 0; d < 32; d++) cr[d] = __float2half_rn(acc[d]*inv);
    }
}

// ---------------- ln(residual) * mask -> exact (optional) + half ----------------
__global__ void ln_res_mask_kernel(const float* __restrict__ a, const float* __restrict__ bq,
                                   const float* __restrict__ cur,
                                   float* __restrict__ out, __half* __restrict__ out_r) {
    int r = blockIdx.x, t = threadIdx.x;
    float x = a[(size_t)r*DD_ + t] + bq[(size_t)r*DD_ + t];
    float mean = blockReduceSum256(x) * (1.f/256.f);
    float d = x - mean;
    float var = blockReduceSum256(d*d) * (1.f/256.f);
    float y = d * rsqrtf(var + 1e-5f) * cur[r];
    if (out) out[(size_t)r*DD_ + t] = y;
    out_r[(size_t)r*DD_ + t] = __float2half_rn(y);
}

// ---------------- relu(ln(x)) -> + pf1 -> ln (exact + half) ----------------
__global__ void post_dyn_kernel(const float* __restrict__ x, const float* __restrict__ pf1,
                                float* __restrict__ out, __half* __restrict__ out_r) {
    int r = blockIdx.x, t = threadIdx.x;
    float v = x[(size_t)r*DD_ + t];
    float m1 = blockReduceSum256(v) * (1.f/256.f);
    float d1 = v - m1;
    float v1 = blockReduceSum256(d1*d1) * (1.f/256.f);
    float rl = fmaxf(d1 * rsqrtf(v1 + 1e-5f), 0.f);
    float y = pf1[(size_t)r*DD_ + t] + rl;
    float m2 = blockReduceSum256(y) * (1.f/256.f);
    float d2 = y - m2;
    float v2 = blockReduceSum256(d2*d2) * (1.f/256.f);
    float z = d2 * rsqrtf(v2 + 1e-5f);
    out[(size_t)r*DD_ + t] = z;
    out_r[(size_t)r*DD_ + t] = __float2half_rn(z);
}

// ---------------- relu(ln(x)) -> half ----------------
__global__ void ln_relu_kernel(const float* __restrict__ x, __half* __restrict__ out) {
    int r = blockIdx.x, t = threadIdx.x;
    float v = x[(size_t)r*DD_ + t];
    float m = blockReduceSum256(v) * (1.f/256.f);
    float d = v - m;
    float var = blockReduceSum256(d*d) * (1.f/256.f);
    out[(size_t)r*DD_ + t] = __float2half_rn(fmaxf(d * rsqrtf(var + 1e-5f), 0.f));
}

// ---------------- DynamicConv (register-tiled; params fp16 in, f2 fp16 out) ----------------
#define SPAD 52
#define DYN_SMEM 210944

__global__ __launch_bounds__(256)
void dynconv_kernel(const float* __restrict__ roi, const __half* __restrict__ params,
                    __half* __restrict__ out) {
    int n = blockIdx.x;
    extern __shared__ float sm[];
    float* featsT = sm;                 // [d][s] 256 x 52
    float* p1     = sm + 13312;         // [d][e] 256 x 64
    float* p2     = p1 + 16384;         // [e][d] 64 x 256
    float* f1     = p2 + 16384;         // [s][e] 52 x 64
    float* f1T    = f1 + 3328;          // [e][s] 64 x 52
    int tid = threadIdx.x;

    for (int i = tid; i < 256*3; i += 256) {
        int d = i / 3, s = 49 + (i % 3);
        featsT[d*SPAD + s] = 0.f;
    }
    for (int i = tid; i < SS*DD_; i += 256) {
        int s = i >> 8, d = i & 255;
        featsT[d*SPAD + s] = roi[((size_t)s*ROWS + n)*DD_ + d];
    }
    const __half2* pr2 = (const __half2*)(params + (size_t)n * 32768);
    for (int i = tid; i < 8192; i += 256) {
        float2 f = __half22float2(pr2[i]);
        p1[2*i] = f.x; p1[2*i+1] = f.y;
    }
    for (int i = tid; i < 8192; i += 256) {
        float2 f = __half22float2(pr2[8192 + i]);
        p2[2*i] = f.x; p2[2*i+1] = f.y;
    }
    __syncthreads();

    {
        int te = tid & 15, tsg = tid >> 4;
        if (tsg < 13) {
            int e0 = te * 4, s0 = tsg * 4;
            float acc[4][4];
            #pragma unroll
            for (int i = 0; i < 4; i++)
                #pragma unroll
                for (int j = 0; j < 4; j++) acc[i][j] = 0.f;
            for (int d = 0; d < 256; d++) {
                float4 fv = *(const float4*)(featsT + d*SPAD + s0);
                float4 pv = *(const float4*)(p1 + d*64 + e0);
                acc[0][0] += fv.x*pv.x; acc[0][1] += fv.x*pv.y; acc[0][2] += fv.x*pv.z; acc[0][3] += fv.x*pv.w;
                acc[1][0] += fv.y*pv.x; acc[1][1] += fv.y*pv.y; acc[1][2] += fv.y*pv.z; acc[1][3] += fv.y*pv.w;
                acc[2][0] += fv.z*pv.x; acc[2][1] += fv.z*pv.y; acc[2][2] += fv.z*pv.z; acc[2][3] += fv.z*pv.w;
                acc[3][0] += fv.w*pv.x; acc[3][1] += fv.w*pv.y; acc[3][2] += fv.w*pv.z; acc[3][3] += fv.w*pv.w;
            }
            #pragma unroll
            for (int i = 0; i < 4; i++)
                #pragma unroll
                for (int j = 0; j < 4; j++)
                    f1[(s0+i)*64 + e0 + j] = acc[i][j];
        }
    }
    __syncthreads();

    int warp = tid >> 5, lane = tid & 31;
    for (int s = warp; s < SS; s += 8) {
        float x0 = f1[s*64 + lane], x1 = f1[s*64 + 32 + lane];
        float sum = x0 + x1;
        #pragma unroll
        for (int o = 16; o; o >>= 1) sum += __shfl_xor_sync(0xffffffffu, sum, o);
        float m = sum * (1.f/64.f);
        float d0 = x0 - m, d1 = x1 - m;
        float vs = d0*d0 + d1*d1;
        #pragma unroll
        for (int o = 16; o; o >>= 1) vs += __shfl_xor_sync(0xffffffffu, vs, o);
        float inv = rsqrtf(vs*(1.f/64.f) + 1e-5f);
        f1T[lane*SPAD + s]        = fmaxf(d0*inv, 0.f);
        f1T[(32+lane)*SPAD + s]   = fmaxf(d1*inv, 0.f);
    }
    __syncthreads();

    float* f2 = featsT;
    {
        int td = tid & 63, tsg2 = tid >> 6;
        int d0 = td * 4;
        for (int sg = tsg2; sg < 13; sg += 4) {
            int s0 = sg * 4;
            float acc[4][4];
            #pragma unroll
            for (int i = 0; i < 4; i++)
                #pragma unroll
                for (int j = 0; j < 4; j++) acc[i][j] = 0.f;
            for (int e = 0; e < 64; e++) {
                float4 fv = *(const float4*)(f1T + e*SPAD + s0);
                float4 pv = *(const float4*)(p2 + e*256 + d0);
                acc[0][0] += fv.x*pv.x; acc[0][1] += fv.x*pv.y; acc[0][2] += fv.x*pv.z; acc[0][3] += fv.x*pv.w;
                acc[1][0] += fv.y*pv.x; acc[1][1] += fv.y*pv.y; acc[1][2] += fv.y*pv.z; acc[1][3] += fv.y*pv.w;
                acc[2][0] += fv.z*pv.x; acc[2][1] += fv.z*pv.y; acc[2][2] += fv.z*pv.z; acc[2][3] += fv.z*pv.w;
                acc[3][0] += fv.w*pv.x; acc[3][1] += fv.w*pv.y; acc[3][2] += fv.w*pv.z; acc[3][3] += fv.w*pv.w;
            }
            #pragma unroll
            for (int i = 0; i < 4; i++)
                #pragma unroll
                for (int j = 0; j < 4; j++)
                    f2[(s0+i)*256 + d0 + j] = acc[i][j];
        }
    }
    __syncthreads();

    for (int s = warp; s < SS; s += 8) {
        float x[8]; float sum = 0.f;
        #pragma unroll
        for (int j = 0; j < 8; j++) { x[j] = f2[s*256 + j*32 + lane]; sum += x[j]; }
        #pragma unroll
        for (int o = 16; o; o >>= 1) sum += __shfl_xor_sync(0xffffffffu, sum, o);
        float m = sum * (1.f/256.f);
        float vs = 0.f;
        #pragma unroll
        for (int j = 0; j < 8; j++) { float dd = x[j]-m; vs += dd*dd; }
        #pragma unroll
        for (int o = 16; o; o >>= 1) vs += __shfl_xor_sync(0xffffffffu, vs, o);
        float inv = rsqrtf(vs*(1.f/256.f) + 1e-5f);
        #pragma unroll
        for (int j = 0; j < 8; j++)
            out[(size_t)n*12544 + s*256 + j*32 + lane] =
                __float2half_rn(fmaxf((x[j]-m)*inv, 0.f));
    }
}

// ---------------- host ----------------
extern "C" void kernel_launch(void* const* d_in, const int* in_sizes, int n_in,
                              void* d_out, int out_size) {
    const float* bboxes     = (const float*)d_in[0];
    const float* pf         = (const float*)d_in[1];
    const float* roi        = (const float*)d_in[2];
    const float* query      = (const float*)d_in[3];
    const float* cur        = (const float*)d_in[4];
    const float* w_qkv      = (const float*)d_in[5];
    const float* b_qkv      = (const float*)d_in[6];
    const float* w_attn_out = (const float*)d_in[7];
    const float* b_attn_out = (const float*)d_in[8];
    const float* w_dyn      = (const float*)d_in[9];
    const float* b_dyn      = (const float*)d_in[10];
    const float* w_dyn_out  = (const float*)d_in[11];
    const float* b_dyn_out  = (const float*)d_in[12];
    const float* w_ff1      = (const float*)d_in[13];
    const float* b_ff1      = (const float*)d_in[14];
    const float* w_ff2      = (const float*)d_in[15];
    const float* b_ff2      = (const float*)d_in[16];
    const float* w_cls      = (const float*)d_in[17];
    const float* w_logits   = (const float*)d_in[18];
    const float* b_logits   = (const float*)d_in[19];
    float* out = (float*)d_out;

    __half *qk,*pfr,*ctx,*pf1r,*params,*f2,*pf3r,*ffn,*fc,*clsf;
    __half *wqkv,*wattn,*wdyn,*wdynout,*wff1,*wff2,*wcls,*wlog;
    float *qp,*kp,*vp,*maskb,*tgt2,*pf1,*x,*pf3,*t2,*clsy,*part;
    cudaGetSymbolAddress((void**)&qk,     g_qk);
    cudaGetSymbolAddress((void**)&pfr,    g_pfr);
    cudaGetSymbolAddress((void**)&qp,     g_qp);
    cudaGetSymbolAddress((void**)&kp,     g_kp);
    cudaGetSymbolAddress((void**)&vp,     g_vp);
    cudaGetSymbolAddress((void**)&maskb,  g_mask);
    cudaGetSymbolAddress((void**)&ctx,    g_ctx);
    cudaGetSymbolAddress((void**)&tgt2,   g_tgt2);
    cudaGetSymbolAddress((void**)&pf1,    g_pf1);
    cudaGetSymbolAddress((void**)&pf1r,   g_pf1r);
    cudaGetSymbolAddress((void**)&params, g_params);
    cudaGetSymbolAddress((void**)&f2,     g_f2);
    cudaGetSymbolAddress((void**)&x,      g_x);
    cudaGetSymbolAddress((void**)&pf3,    g_pf3);
    cudaGetSymbolAddress((void**)&pf3r,   g_pf3r);
    cudaGetSymbolAddress((void**)&ffn,    g_ffn);
    cudaGetSymbolAddress((void**)&t2,     g_t2);
    cudaGetSymbolAddress((void**)&fc,     g_fc);
    cudaGetSymbolAddress((void**)&clsy,   g_clsy);
    cudaGetSymbolAddress((void**)&clsf,   g_clsf);
    cudaGetSymbolAddress((void**)&part,   g_part);
    cudaGetSymbolAddress((void**)&wqkv,   g_wqkv_h);
    cudaGetSymbolAddress((void**)&wattn,  g_wattn_h);
    cudaGetSymbolAddress((void**)&wdyn,   g_wdyn_h);
    cudaGetSymbolAddress((void**)&wdynout,g_wdynout_h);
    cudaGetSymbolAddress((void**)&wff1,   g_wff1_h);
    cudaGetSymbolAddress((void**)&wff2,   g_wff2_h);
    cudaGetSymbolAddress((void**)&wcls,   g_wcls_h);
    cudaGetSymbolAddress((void**)&wlog,   g_wlog_h);

    const int GEMM_SMEM = 4 * GT_H * 2;   // 73728 B
    cudaFuncSetAttribute(fp16_gemm, cudaFuncAttributeMaxDynamicSharedMemorySize, GEMM_SMEM);
    cudaFuncSetAttribute(dynconv_kernel, cudaFuncAttributeMaxDynamicSharedMemorySize, DYN_SMEM);

    auto grd = [](int M, int N) { return dim3((unsigned)((N+127)/128), (unsigned)((M+127)/128), 1); };

    // prep: mask, half activations, half weights
    mask_kernel<<<dim3(NRr, NB), 320>>>(bboxes, cur, maskb);
    add_round_kernel<<<(ROWS*DD_+255)/256, 256>>>(pf, query, qk, pfr, ROWS*DD_);
    round_weights<<<1280, 256>>>((const float4*)w_dyn,     wdyn,
                                 (const float4*)w_dyn_out, wdynout,
                                 (const float4*)w_ff1,     wff1,
                                 (const float4*)w_ff2,     wff2,
                                 (const float4*)w_qkv,     wqkv,
                                 (const float4*)w_attn_out,wattn,
                                 (const float4*)w_cls,     wcls,
                                 (const float4*)w_logits,  wlog);

    // QKV projections (fp32 out)
    fp16_gemm<<<grd(ROWS,256), 256, GEMM_SMEM>>>(qk,  wqkv,           b_qkv,     qp, nullptr, nullptr, ROWS, 256, 256, 0);
    fp16_gemm<<<grd(ROWS,256), 256, GEMM_SMEM>>>(qk,  wqkv + 256*256, b_qkv+256, kp, nullptr, nullptr, ROWS, 256, 256, 0);
    fp16_gemm<<<grd(ROWS,256), 256, GEMM_SMEM>>>(pfr, wqkv + 512*256, b_qkv+512, vp, nullptr, nullptr, ROWS, 256, 256, 0);
    // masked MHSA (ctx -> half)
    attn_kernel<<<NB*HH*3, 128>>>(qp, kp, vp, maskb, ctx);
    // out proj + norm1*mask
    fp16_gemm<<<grd(ROWS,256), 256, GEMM_SMEM>>>(ctx, wattn, b_attn_out, tgt2, nullptr, nullptr, ROWS, 256, 256, 0);
    ln_res_mask_kernel<<<ROWS, 256>>>(pf, tgt2, cur, pf1, pf1r);
    // DynamicConv params GEMM (dominant) -> fp16 params
    fp16_gemm<<<grd(ROWS,32768), 256, GEMM_SMEM>>>(pf1r, wdyn, b_dyn, nullptr, params, nullptr, ROWS, 32768, 256, 2);
    // per-instance dynamic conv -> fp16 f2
    dynconv_kernel<<<ROWS, 256, DYN_SMEM>>>(roi, params, f2);
    // dyn out proj — split-K(4): Kper=3136 (T=49); reduce; norm2
    fp16_gemm<<<dim3(2,19,4), 256, GEMM_SMEM>>>(f2, wdynout, nullptr, nullptr, nullptr, part, ROWS, 256, 12544, 0);
    reduce_splitk<<<ROWS, 256>>>(part, b_dyn_out, x, 4);
    post_dyn_kernel<<<ROWS, 256>>>(x, pf1, pf3, pf3r);
    // FFN: ff1 relu -> fp16 ffn; ff2 split-K(8); norm3
    fp16_gemm<<<grd(ROWS,2048), 256, GEMM_SMEM>>>(pf3r, wff1, b_ff1, nullptr, ffn, nullptr, ROWS, 2048, 256, 3);
    fp16_gemm<<<dim3(2,19,8), 256, GEMM_SMEM>>>(ffn, wff2, nullptr, nullptr, nullptr, part, ROWS, 256, 2048, 0);
    reduce_splitk<<<ROWS, 256>>>(part, b_ff2, t2, 8);
    ln_res_mask_kernel<<<ROWS, 256>>>(pf3, t2, cur, nullptr, fc);
    // cls tower + logits
    fp16_gemm<<<grd(ROWS,256), 256, GEMM_SMEM>>>(fc, wcls, nullptr, clsy, nullptr, nullptr, ROWS, 256, 256, 0);
    ln_relu_kernel<<<ROWS, 256>>>(clsy, clsf);
    fp16_gemm<<<grd(ROWS,80), 256, GEMM_SMEM>>>(clsf, wlog, b_logits, out, nullptr, nullptr, ROWS, 80, 256, 0);
}

// round 14
// speedup vs baseline: 1.5838x; 1.0473x over previous
#include <cuda_runtime.h>
#include <cuda_fp16.h>
#include <math.h>
#include <stdint.h>

// ---------------- constants ----------------
#define NB   8
#define NRr  300
#define DD_  256
#define HH   8
#define HDIM 32
#define SS   49
#define FFN  2048
#define NCL  80
#define ROWS (NB*NRr)    // 2400

// ---------------- scratch ----------------
__device__ __half g_qk   [ROWS*DD_];
__device__ __half g_pfr  [ROWS*DD_];
__device__ float  g_qp   [ROWS*DD_];
__device__ float  g_kp   [ROWS*DD_];
__device__ float  g_vp   [ROWS*DD_];
__device__ float  g_mask [NB*NRr*NRr];
__device__ __half g_ctx  [ROWS*DD_];
__device__ float  g_tgt2 [ROWS*DD_];
__device__ float  g_pf1  [ROWS*DD_];
__device__ __half g_pf1r [ROWS*DD_];
__device__ __half g_params[78643200];      // 2400*32768 fp16
__device__ __half g_f2   [30105600];       // 2400*12544 fp16
__device__ float  g_x    [ROWS*DD_];
__device__ float  g_pf3  [ROWS*DD_];
__device__ __half g_pf3r [ROWS*DD_];
__device__ __half g_ffn  [ROWS*FFN];
__device__ float  g_t2   [ROWS*DD_];
__device__ __half g_fc   [ROWS*DD_];
__device__ float  g_clsy [ROWS*DD_];
__device__ __half g_clsf [ROWS*DD_];
__device__ float  g_part [8*ROWS*256];     // split-K partials (fp32)
// fp16 weights
__device__ __half g_wqkv_h  [768*256];
__device__ __half g_wattn_h [256*256];
__device__ __half g_wdyn_h  [32768*256];
__device__ __half g_wdynout_h[256*12544];
__device__ __half g_wff1_h  [2048*256];
__device__ __half g_wff2_h  [256*2048];
__device__ __half g_wcls_h  [256*256];
__device__ __half g_wlog_h  [80*256];

// ---------------- helpers ----------------
__device__ __forceinline__ float blockReduceSum256(float v) {
    __shared__ float red[8];
    int lane = threadIdx.x & 31, w = threadIdx.x >> 5;
    #pragma unroll
    for (int o = 16; o; o >>= 1) v += __shfl_xor_sync(0xffffffffu, v, o);
    __syncthreads();
    if (lane == 0) red[w] = v;
    __syncthreads();
    float s = 0.f;
    #pragma unroll
    for (int i = 0; i < 8; i++) s += red[i];
    return s;
}

__device__ __forceinline__ void mma_fp16(float* c,
        uint32_t a0, uint32_t a1, uint32_t a2, uint32_t a3,
        uint32_t b0, uint32_t b1) {
    asm volatile(
        "mma.sync.aligned.m16n8k16.row.col.f32.f16.f16.f32 "
        "{%0,%1,%2,%3}, {%4,%5,%6,%7}, {%8,%9}, {%0,%1,%2,%3};"
        : "+f"(c[0]), "+f"(c[1]), "+f"(c[2]), "+f"(c[3])
        : "r"(a0), "r"(a1), "r"(a2), "r"(a3), "r"(b0), "r"(b1));
}

#define LDSM_X4(r, addr) \
    asm volatile("ldmatrix.sync.aligned.m8n8.x4.shared.b16 {%0,%1,%2,%3}, [%4];" \
        : "=r"((r)[0]), "=r"((r)[1]), "=r"((r)[2]), "=r"((r)[3]) : "r"(addr))

// ---------------- weight rounding fp32 -> fp16 ----------------
#define S_DYN    2097152
#define S_DYNOUT  802816
#define S_FF1     131072
#define S_FF2     131072
#define S_QKV      49152
#define S_ATTN     16384
#define S_CLS      16384
#define S_LOG       5120
#define S_TOT4   3249152

__global__ void round_weights(const float4* __restrict__ s_dyn,    __half* d_dyn,
                              const float4* __restrict__ s_dynout, __half* d_dynout,
                              const float4* __restrict__ s_ff1,    __half* d_ff1,
                              const float4* __restrict__ s_ff2,    __half* d_ff2,
                              const float4* __restrict__ s_qkv,    __half* d_qkv,
                              const float4* __restrict__ s_attn,   __half* d_attn,
                              const float4* __restrict__ s_cls,    __half* d_cls,
                              const float4* __restrict__ s_log,    __half* d_log) {
    for (long i = blockIdx.x*(long)blockDim.x + threadIdx.x; i < S_TOT4;
         i += (long)gridDim.x*blockDim.x) {
        long j = i;
        const float4* s; __half* d;
        if (j < S_DYN)                       { s = s_dyn;    d = d_dyn; }
        else if ((j -= S_DYN)    < S_DYNOUT) { s = s_dynout; d = d_dynout; }
        else if ((j -= S_DYNOUT) < S_FF1)    { s = s_ff1;    d = d_ff1; }
        else if ((j -= S_FF1)    < S_FF2)    { s = s_ff2;    d = d_ff2; }
        else if ((j -= S_FF2)    < S_QKV)    { s = s_qkv;    d = d_qkv; }
        else if ((j -= S_QKV)    < S_ATTN)   { s = s_attn;   d = d_attn; }
        else if ((j -= S_ATTN)   < S_CLS)    { s = s_cls;    d = d_cls; }
        else { j -= S_CLS;                     s = s_log;    d = d_log; }
        float4 v = s[j];
        __half2* dst = (__half2*)(d + j * 4);
        dst[0] = __floats2half2_rn(v.x, v.y);
        dst[1] = __floats2half2_rn(v.z, v.w);
    }
}

// ---------------- FP16 GEMM: BM=128 BN=128 BK=64, 256 threads, ldmatrix feed ----------------
#define GT_H 9216   // 128 rows * 72 halfs per buffer

__device__ __forceinline__ void gemm_load_tile(
        const __half* __restrict__ A, const __half* __restrict__ B,
        int M, int N, int K, int row0, int col0,
        uint32_t sbase, int tid, int buf, int k0) {
    int r  = tid >> 3;
    int c8 = (tid & 7) * 8;
    #pragma unroll
    for (int p = 0; p < 4; p++) {
        int rr = r + p * 32;
        int gr = row0 + rr;
        const __half* src = A + (size_t)(gr < M ? gr : (M - 1)) * K + k0 + c8;
        uint32_t dst = sbase + (uint32_t)((buf * GT_H + rr * 72 + c8) * 2);
        int sz = (gr < M) ? 16 : 0;
        asm volatile("cp.async.cg.shared.global [%0], [%1], 16, %2;\n"
                     :: "r"(dst), "l"(src), "r"(sz));
    }
    #pragma unroll
    for (int p = 0; p < 4; p++) {
        int rr = r + p * 32;
        int gn = col0 + rr;
        const __half* src = B + (size_t)(gn < N ? gn : (N - 1)) * K + k0 + c8;
        uint32_t dst = sbase + (uint32_t)(((2 * GT_H) + buf * GT_H + rr * 72 + c8) * 2);
        int sz = (gn < N) ? 16 : 0;
        asm volatile("cp.async.cg.shared.global [%0], [%1], 16, %2;\n"
                     :: "r"(dst), "l"(src), "r"(sz));
    }
}

__global__ __launch_bounds__(256)
void fp16_gemm(const __half* __restrict__ A, const __half* __restrict__ B,
               const float* __restrict__ bias, float* __restrict__ C,
               __half* __restrict__ Ch, float* __restrict__ P,
               int M, int N, int K, int flags) {
    extern __shared__ __half smh[];
    const int tid  = threadIdx.x;
    const int warp = tid >> 5, lane = tid & 31;
    const int wm = warp >> 1, wn = warp & 1;
    const int row0 = blockIdx.y * 128;
    const int col0 = blockIdx.x * 128;
    const int Kper  = K / gridDim.z;
    const int kbase = blockIdx.z * Kper;
    uint32_t sbase = (uint32_t)__cvta_generic_to_shared(smh);

    float acc[2][8][4];
    #pragma unroll
    for (int i = 0; i < 2; i++)
        #pragma unroll
        for (int j = 0; j < 8; j++)
            #pragma unroll
            for (int k = 0; k < 4; k++) acc[i][j][k] = 0.f;

    const int T = Kper >> 6;        // BK=64
    gemm_load_tile(A, B, M, N, K, row0, col0, sbase, tid, 0, kbase);
    asm volatile("cp.async.commit_group;");

    // ldmatrix per-lane addresses (canonical x4 layouts)
    // A: lanes 0-15 -> rows (wm*32 + (lane&15)), col 0; lanes 16-31 -> same rows, col 8
    const uint32_t aoff = (uint32_t)(((wm * 32 + (lane & 15)) * 72 + ((lane >> 4) * 8)) * 2);
    // B: mats (n0..n0+7,k0-7), (n0..n0+7,k8-15), (n0+8..+15,k0-7), (n0+8..+15,k8-15)
    const uint32_t boff = (uint32_t)(2 * GT_H * 2)
        + (uint32_t)(((wn * 64 + ((lane >> 4) & 1) * 8 + (lane & 7)) * 72
                      + (((lane >> 3) & 1) * 8)) * 2);

    for (int t = 0; t < T; t++) {
        if (t + 1 < T) {
            gemm_load_tile(A, B, M, N, K, row0, col0, sbase, tid, (t + 1) & 1, kbase + (t + 1) * 64);
            asm volatile("cp.async.commit_group;");
            asm volatile("cp.async.wait_group 1;");
        } else {
            asm volatile("cp.async.wait_group 0;");
        }
        __syncthreads();

        const uint32_t abase = sbase + (uint32_t)((t & 1) * GT_H * 2) + aoff;
        const uint32_t bbase = sbase + (uint32_t)((t & 1) * GT_H * 2) + boff;
        #pragma unroll
        for (int kk = 0; kk < 4; kk++) {            // 4 x k16
            const uint32_t kbyte = (uint32_t)(kk * 16 * 2);
            uint32_t a[2][4];
            #pragma unroll
            for (int mi = 0; mi < 2; mi++)
                LDSM_X4(a[mi], abase + (uint32_t)(mi * 16 * 72 * 2) + kbyte);
            #pragma unroll
            for (int pr = 0; pr < 4; pr++) {        // each pair covers ni = 2*pr, 2*pr+1
                uint32_t b[4];
                LDSM_X4(b, bbase + (uint32_t)(pr * 16 * 72 * 2) + kbyte);
                #pragma unroll
                for (int mi = 0; mi < 2; mi++) {
                    mma_fp16(acc[mi][2*pr],   a[mi][0], a[mi][1], a[mi][2], a[mi][3], b[0], b[1]);
                    mma_fp16(acc[mi][2*pr+1], a[mi][0], a[mi][1], a[mi][2], a[mi][3], b[2], b[3]);
                }
            }
        }
        __syncthreads();
    }

    // epilogue
    if (gridDim.z == 1) {
        #pragma unroll
        for (int mi = 0; mi < 2; mi++) {
            int gr0 = row0 + wm * 32 + mi * 16 + (lane >> 2);
            #pragma unroll
            for (int ni = 0; ni < 8; ni++) {
                int gc = col0 + wn * 64 + ni * 8 + 2 * (lane & 3);
                if (gc >= N) continue;
                float bb0 = 0.f, bb1 = 0.f;
                if (bias) { bb0 = bias[gc]; bb1 = bias[gc + 1]; }
                #pragma unroll
                for (int half_ = 0; half_ < 2; half_++) {
                    int gr = gr0 + half_ * 8;
                    if (gr >= M) continue;
                    float v0 = acc[mi][ni][half_ * 2]     + bb0;
                    float v1 = acc[mi][ni][half_ * 2 + 1] + bb1;
                    if (flags & 1) { v0 = fmaxf(v0, 0.f); v1 = fmaxf(v1, 0.f); }
                    if (flags & 2) {
                        *(__half2*)(Ch + (size_t)gr * N + gc) = __floats2half2_rn(v0, v1);
                    } else {
                        *(float2*)(C + (size_t)gr * N + gc) = make_float2(v0, v1);
                    }
                }
            }
        }
    } else {
        float* Pz = P + (size_t)blockIdx.z * M * 256;
        #pragma unroll
        for (int mi = 0; mi < 2; mi++) {
            int gr0 = row0 + wm * 32 + mi * 16 + (lane >> 2);
            #pragma unroll
            for (int ni = 0; ni < 8; ni++) {
                int gc = col0 + wn * 64 + ni * 8 + 2 * (lane & 3);
                if (gc >= N) continue;
                if (gr0 < M)
                    *(float2*)(Pz + (size_t)gr0 * 256 + gc) =
                        make_float2(acc[mi][ni][0], acc[mi][ni][1]);
                if (gr0 + 8 < M)
                    *(float2*)(Pz + (size_t)(gr0 + 8) * 256 + gc) =
                        make_float2(acc[mi][ni][2], acc[mi][ni][3]);
            }
        }
    }
}

// ---------------- split-K reduce ----------------
__global__ void reduce_splitk(const float* __restrict__ P, const float* __restrict__ bias,
                              float* __restrict__ out, int Z) {
    int r = blockIdx.x, c = threadIdx.x;    // 256 threads
    float s = 0.f;
    for (int z = 0; z < Z; z++) s += P[((size_t)z * ROWS + r) * 256 + c];
    out[(size_t)r * 256 + c] = s + bias[c];
}

// ---------------- IoU-relation attention mask ----------------
__global__ void mask_kernel(const float* __restrict__ bboxes,
                            const float* __restrict__ cur,
                            float* __restrict__ maskf) {
    int q = blockIdx.x, b = blockIdx.y, k = threadIdx.x;
    if (k >= NRr) return;
    float4 bq = *(const float4*)(bboxes + (size_t)(b*NRr + q)*4);
    float4 bk = *(const float4*)(bboxes + (size_t)(b*NRr + k)*4);
    float aq = (bq.z-bq.x)*(bq.w-bq.y);
    float ak = (bk.z-bk.x)*(bk.w-bk.y);
    float lx = fmaxf(bq.x, bk.x), ly = fmaxf(bq.y, bk.y);
    float rx = fminf(bq.z, bk.z), ry = fminf(bq.w, bk.w);
    float w  = fmaxf(rx-lx, 0.f), h = fmaxf(ry-ly, 0.f);
    float inter = w*h;
    float uni = fmaxf(aq + ak - inter, 1e-9f);
    float iou = inter/uni;
    float o   = (iou < 0.5f) ? 1.f : 0.f;
    float cq = cur[b*NRr + q], ck = cur[b*NRr + k];
    float val = o*cq*ck + ((q == k) ? (1.f - cq) : 0.f);
    maskf[((size_t)(b*NRr + q))*NRr + k] = (val > 0.f) ? 1.f : 0.f;
}

// ---------------- qk = h(pf+query); pfr = h(pf) ----------------
__global__ void add_round_kernel(const float* __restrict__ a, const float* __restrict__ b,
                                 __half* __restrict__ qk, __half* __restrict__ pfr, int n) {
    int i = blockIdx.x*blockDim.x + threadIdx.x;
    if (i < n) {
        float av = a[i];
        qk[i]  = __float2half_rn(av + b[i]);
        pfr[i] = __float2half_rn(av);
    }
}

// ---------------- masked multi-head attention ----------------
#define QCH 100
__global__ void attn_kernel(const float* __restrict__ qp, const float* __restrict__ kp,
                            const float* __restrict__ vp, const float* __restrict__ maskf,
                            __half* __restrict__ ctx) {
    const int bh = blockIdx.x / 3;
    const int ch = blockIdx.x % 3;
    const int b = bh >> 3;
    const int h = bh & 7;
    __shared__ float Ks[150*32];
    __shared__ float Vs[150*32];
    const int tid = threadIdx.x;          // 128
    const int q = ch * QCH + tid;
    const bool act = (tid < QCH) && (q < NRr);
    float qv[32], acc[32];
    float m = -1e30f, ssum = 0.f;
    if (act) {
        const float* qr = qp + ((size_t)(b*NRr + q))*DD_ + h*HDIM;
        #pragma unroll
        for (int d = 0; d < 32; d++) { qv[d] = qr[d]; acc[d] = 0.f; }
    }
    const float* mrow = maskf + ((size_t)(b*NRr) + (act ? q : 0))*NRr;
    const float scale = 0.17677669529663687f;

    for (int c0 = 0; c0 < NRr; c0 += 150) {
        __syncthreads();
        for (int i = tid; i < 150*32; i += 128) {
            int k = i >> 5, d = i & 31;
            size_t gi = ((size_t)(b*NRr + c0 + k))*DD_ + h*HDIM + d;
            Ks[i] = kp[gi];
            Vs[i] = vp[gi];
        }
        __syncthreads();
        if (act) {
            for (int k = 0; k < 150; k++) {
                const float* kr = Ks + k*32;
                float x0 = 0.f, x1 = 0.f, x2 = 0.f, x3 = 0.f;
                #pragma unroll
                for (int d = 0; d < 32; d += 4) {
                    x0 += qv[d]*kr[d];   x1 += qv[d+1]*kr[d+1];
                    x2 += qv[d+2]*kr[d+2]; x3 += qv[d+3]*kr[d+3];
                }
                float x = ((x0+x1)+(x2+x3))*scale;
                if (mrow[c0+k] > 0.f) x = -1e9f;
                float nm = fmaxf(m, x);
                float sc = __expf(m - nm);
                float e  = __expf(x - nm);
                ssum = ssum*sc + e;
                const float* vr = Vs + k*32;
                #pragma unroll
                for (int d = 0; d < 32; d++) acc[d] = acc[d]*sc + e*vr[d];
                m = nm;
            }
        }
    }
    if (act) {
        float inv = 1.f/ssum;
        __half* cr = ctx + ((size_t)(b*NRr + q))*DD_ + h*HDIM;
        #pragma unroll
        for (int d = 0; d < 32; d++) cr[d] = __float2half_rn(acc[d]*inv);
    }
}

// ---------------- ln(residual) * mask -> exact (optional) + half ----------------
__global__ void ln_res_mask_kernel(const float* __restrict__ a, const float* __restrict__ bq,
                                   const float* __restrict__ cur,
                                   float* __restrict__ out, __half* __restrict__ out_r) {
    int r = blockIdx.x, t = threadIdx.x;
    float x = a[(size_t)r*DD_ + t] + bq[(size_t)r*DD_ + t];
    float mean = blockReduceSum256(x) * (1.f/256.f);
    float d = x - mean;
    float var = blockReduceSum256(d*d) * (1.f/256.f);
    float y = d * rsqrtf(var + 1e-5f) * cur[r];
    if (out) out[(size_t)r*DD_ + t] = y;
    out_r[(size_t)r*DD_ + t] = __float2half_rn(y);
}

// ---------------- relu(ln(x)) -> + pf1 -> ln (exact + half) ----------------
__global__ void post_dyn_kernel(const float* __restrict__ x, const float* __restrict__ pf1,
                                float* __restrict__ out, __half* __restrict__ out_r) {
    int r = blockIdx.x, t = threadIdx.x;
    float v = x[(size_t)r*DD_ + t];
    float m1 = blockReduceSum256(v) * (1.f/256.f);
    float d1 = v - m1;
    float v1 = blockReduceSum256(d1*d1) * (1.f/256.f);
    float rl = fmaxf(d1 * rsqrtf(v1 + 1e-5f), 0.f);
    float y = pf1[(size_t)r*DD_ + t] + rl;
    float m2 = blockReduceSum256(y) * (1.f/256.f);
    float d2 = y - m2;
    float v2 = blockReduceSum256(d2*d2) * (1.f/256.f);
    float z = d2 * rsqrtf(v2 + 1e-5f);
    out[(size_t)r*DD_ + t] = z;
    out_r[(size_t)r*DD_ + t] = __float2half_rn(z);
}

// ---------------- relu(ln(x)) -> half ----------------
__global__ void ln_relu_kernel(const float* __restrict__ x, __half* __restrict__ out) {
    int r = blockIdx.x, t = threadIdx.x;
    float v = x[(size_t)r*DD_ + t];
    float m = blockReduceSum256(v) * (1.f/256.f);
    float d = v - m;
    float var = blockReduceSum256(d*d) * (1.f/256.f);
    out[(size_t)r*DD_ + t] = __float2half_rn(fmaxf(d * rsqrtf(var + 1e-5f), 0.f));
}

// ---------------- DynamicConv (register-tiled; params fp16 in, f2 fp16 out) ----------------
#define SPAD 52
#define DYN_SMEM 210944

__global__ __launch_bounds__(256)
void dynconv_kernel(const float* __restrict__ roi, const __half* __restrict__ params,
                    __half* __restrict__ out) {
    int n = blockIdx.x;
    extern __shared__ float sm[];
    float* featsT = sm;                 // [d][s] 256 x 52
    float* p1     = sm + 13312;         // [d][e] 256 x 64
    float* p2     = p1 + 16384;         // [e][d] 64 x 256
    float* f1     = p2 + 16384;         // [s][e] 52 x 64
    float* f1T    = f1 + 3328;          // [e][s] 64 x 52
    int tid = threadIdx.x;

    for (int i = tid; i < 256*3; i += 256) {
        int d = i / 3, s = 49 + (i % 3);
        featsT[d*SPAD + s] = 0.f;
    }
    for (int i = tid; i < SS*DD_; i += 256) {
        int s = i >> 8, d = i & 255;
        featsT[d*SPAD + s] = roi[((size_t)s*ROWS + n)*DD_ + d];
    }
    const __half2* pr2 = (const __half2*)(params + (size_t)n * 32768);
    for (int i = tid; i < 8192; i += 256) {
        float2 f = __half22float2(pr2[i]);
        p1[2*i] = f.x; p1[2*i+1] = f.y;
    }
    for (int i = tid; i < 8192; i += 256) {
        float2 f = __half22float2(pr2[8192 + i]);
        p2[2*i] = f.x; p2[2*i+1] = f.y;
    }
    __syncthreads();

    {
        int te = tid & 15, tsg = tid >> 4;
        if (tsg < 13) {
            int e0 = te * 4, s0 = tsg * 4;
            float acc[4][4];
            #pragma unroll
            for (int i = 0; i < 4; i++)
                #pragma unroll
                for (int j = 0; j < 4; j++) acc[i][j] = 0.f;
            for (int d = 0; d < 256; d++) {
                float4 fv = *(const float4*)(featsT + d*SPAD + s0);
                float4 pv = *(const float4*)(p1 + d*64 + e0);
                acc[0][0] += fv.x*pv.x; acc[0][1] += fv.x*pv.y; acc[0][2] += fv.x*pv.z; acc[0][3] += fv.x*pv.w;
                acc[1][0] += fv.y*pv.x; acc[1][1] += fv.y*pv.y; acc[1][2] += fv.y*pv.z; acc[1][3] += fv.y*pv.w;
                acc[2][0] += fv.z*pv.x; acc[2][1] += fv.z*pv.y; acc[2][2] += fv.z*pv.z; acc[2][3] += fv.z*pv.w;
                acc[3][0] += fv.w*pv.x; acc[3][1] += fv.w*pv.y; acc[3][2] += fv.w*pv.z; acc[3][3] += fv.w*pv.w;
            }
            #pragma unroll
            for (int i = 0; i < 4; i++)
                #pragma unroll
                for (int j = 0; j < 4; j++)
                    f1[(s0+i)*64 + e0 + j] = acc[i][j];
        }
    }
    __syncthreads();

    int warp = tid >> 5, lane = tid & 31;
    for (int s = warp; s < SS; s += 8) {
        float x0 = f1[s*64 + lane], x1 = f1[s*64 + 32 + lane];
        float sum = x0 + x1;
        #pragma unroll
        for (int o = 16; o; o >>= 1) sum += __shfl_xor_sync(0xffffffffu, sum, o);
        float m = sum * (1.f/64.f);
        float d0 = x0 - m, d1 = x1 - m;
        float vs = d0*d0 + d1*d1;
        #pragma unroll
        for (int o = 16; o; o >>= 1) vs += __shfl_xor_sync(0xffffffffu, vs, o);
        float inv = rsqrtf(vs*(1.f/64.f) + 1e-5f);
        f1T[lane*SPAD + s]        = fmaxf(d0*inv, 0.f);
        f1T[(32+lane)*SPAD + s]   = fmaxf(d1*inv, 0.f);
    }
    __syncthreads();

    float* f2 = featsT;
    {
        int td = tid & 63, tsg2 = tid >> 6;
        int d0 = td * 4;
        for (int sg = tsg2; sg < 13; sg += 4) {
            int s0 = sg * 4;
            float acc[4][4];
            #pragma unroll
            for (int i = 0; i < 4; i++)
                #pragma unroll
                for (int j = 0; j < 4; j++) acc[i][j] = 0.f;
            for (int e = 0; e < 64; e++) {
                float4 fv = *(const float4*)(f1T + e*SPAD + s0);
                float4 pv = *(const float4*)(p2 + e*256 + d0);
                acc[0][0] += fv.x*pv.x; acc[0][1] += fv.x*pv.y; acc[0][2] += fv.x*pv.z; acc[0][3] += fv.x*pv.w;
                acc[1][0] += fv.y*pv.x; acc[1][1] += fv.y*pv.y; acc[1][2] += fv.y*pv.z; acc[1][3] += fv.y*pv.w;
                acc[2][0] += fv.z*pv.x; acc[2][1] += fv.z*pv.y; acc[2][2] += fv.z*pv.z; acc[2][3] += fv.z*pv.w;
                acc[3][0] += fv.w*pv.x; acc[3][1] += fv.w*pv.y; acc[3][2] += fv.w*pv.z; acc[3][3] += fv.w*pv.w;
            }
            #pragma unroll
            for (int i = 0; i < 4; i++)
                #pragma unroll
                for (int j = 0; j < 4; j++)
                    f2[(s0+i)*256 + d0 + j] = acc[i][j];
        }
    }
    __syncthreads();

    for (int s = warp; s < SS; s += 8) {
        float x[8]; float sum = 0.f;
        #pragma unroll
        for (int j = 0; j < 8; j++) { x[j] = f2[s*256 + j*32 + lane]; sum += x[j]; }
        #pragma unroll
        for (int o = 16; o; o >>= 1) sum += __shfl_xor_sync(0xffffffffu, sum, o);
        float m = sum * (1.f/256.f);
        float vs = 0.f;
        #pragma unroll
        for (int j = 0; j < 8; j++) { float dd = x[j]-m; vs += dd*dd; }
        #pragma unroll
        for (int o = 16; o; o >>= 1) vs += __shfl_xor_sync(0xffffffffu, vs, o);
        float inv = rsqrtf(vs*(1.f/256.f) + 1e-5f);
        #pragma unroll
        for (int j = 0; j < 8; j++)
            out[(size_t)n*12544 + s*256 + j*32 + lane] =
                __float2half_rn(fmaxf((x[j]-m)*inv, 0.f));
    }
}

// ---------------- host ----------------
extern "C" void kernel_launch(void* const* d_in, const int* in_sizes, int n_in,
                              void* d_out, int out_size) {
    const float* bboxes     = (const float*)d_in[0];
    const float* pf         = (const float*)d_in[1];
    const float* roi        = (const float*)d_in[2];
    const float* query      = (const float*)d_in[3];
    const float* cur        = (const float*)d_in[4];
    const float* w_qkv      = (const float*)d_in[5];
    const float* b_qkv      = (const float*)d_in[6];
    const float* w_attn_out = (const float*)d_in[7];
    const float* b_attn_out = (const float*)d_in[8];
    const float* w_dyn      = (const float*)d_in[9];
    const float* b_dyn      = (const float*)d_in[10];
    const float* w_dyn_out  = (const float*)d_in[11];
    const float* b_dyn_out  = (const float*)d_in[12];
    const float* w_ff1      = (const float*)d_in[13];
    const float* b_ff1      = (const float*)d_in[14];
    const float* w_ff2      = (const float*)d_in[15];
    const float* b_ff2      = (const float*)d_in[16];
    const float* w_cls      = (const float*)d_in[17];
    const float* w_logits   = (const float*)d_in[18];
    const float* b_logits   = (const float*)d_in[19];
    float* out = (float*)d_out;

    __half *qk,*pfr,*ctx,*pf1r,*params,*f2,*pf3r,*ffn,*fc,*clsf;
    __half *wqkv,*wattn,*wdyn,*wdynout,*wff1,*wff2,*wcls,*wlog;
    float *qp,*kp,*vp,*maskb,*tgt2,*pf1,*x,*pf3,*t2,*clsy,*part;
    cudaGetSymbolAddress((void**)&qk,     g_qk);
    cudaGetSymbolAddress((void**)&pfr,    g_pfr);
    cudaGetSymbolAddress((void**)&qp,     g_qp);
    cudaGetSymbolAddress((void**)&kp,     g_kp);
    cudaGetSymbolAddress((void**)&vp,     g_vp);
    cudaGetSymbolAddress((void**)&maskb,  g_mask);
    cudaGetSymbolAddress((void**)&ctx,    g_ctx);
    cudaGetSymbolAddress((void**)&tgt2,   g_tgt2);
    cudaGetSymbolAddress((void**)&pf1,    g_pf1);
    cudaGetSymbolAddress((void**)&pf1r,   g_pf1r);
    cudaGetSymbolAddress((void**)&params, g_params);
    cudaGetSymbolAddress((void**)&f2,     g_f2);
    cudaGetSymbolAddress((void**)&x,      g_x);
    cudaGetSymbolAddress((void**)&pf3,    g_pf3);
    cudaGetSymbolAddress((void**)&pf3r,   g_pf3r);
    cudaGetSymbolAddress((void**)&ffn,    g_ffn);
    cudaGetSymbolAddress((void**)&t2,     g_t2);
    cudaGetSymbolAddress((void**)&fc,     g_fc);
    cudaGetSymbolAddress((void**)&clsy,   g_clsy);
    cudaGetSymbolAddress((void**)&clsf,   g_clsf);
    cudaGetSymbolAddress((void**)&part,   g_part);
    cudaGetSymbolAddress((void**)&wqkv,   g_wqkv_h);
    cudaGetSymbolAddress((void**)&wattn,  g_wattn_h);
    cudaGetSymbolAddress((void**)&wdyn,   g_wdyn_h);
    cudaGetSymbolAddress((void**)&wdynout,g_wdynout_h);
    cudaGetSymbolAddress((void**)&wff1,   g_wff1_h);
    cudaGetSymbolAddress((void**)&wff2,   g_wff2_h);
    cudaGetSymbolAddress((void**)&wcls,   g_wcls_h);
    cudaGetSymbolAddress((void**)&wlog,   g_wlog_h);

    const int GEMM_SMEM = 4 * GT_H * 2;   // 73728 B
    cudaFuncSetAttribute(fp16_gemm, cudaFuncAttributeMaxDynamicSharedMemorySize, GEMM_SMEM);
    cudaFuncSetAttribute(dynconv_kernel, cudaFuncAttributeMaxDynamicSharedMemorySize, DYN_SMEM);

    auto grd = [](int M, int N) { return dim3((unsigned)((N+127)/128), (unsigned)((M+127)/128), 1); };

    // prep: mask, half activations, half weights
    mask_kernel<<<dim3(NRr, NB), 320>>>(bboxes, cur, maskb);
    add_round_kernel<<<(ROWS*DD_+255)/256, 256>>>(pf, query, qk, pfr, ROWS*DD_);
    round_weights<<<1280, 256>>>((const float4*)w_dyn,     wdyn,
                                 (const float4*)w_dyn_out, wdynout,
                                 (const float4*)w_ff1,     wff1,
                                 (const float4*)w_ff2,     wff2,
                                 (const float4*)w_qkv,     wqkv,
                                 (const float4*)w_attn_out,wattn,
                                 (const float4*)w_cls,     wcls,
                                 (const float4*)w_logits,  wlog);

    // QKV projections (fp32 out)
    fp16_gemm<<<grd(ROWS,256), 256, GEMM_SMEM>>>(qk,  wqkv,           b_qkv,     qp, nullptr, nullptr, ROWS, 256, 256, 0);
    fp16_gemm<<<grd(ROWS,256), 256, GEMM_SMEM>>>(qk,  wqkv + 256*256, b_qkv+256, kp, nullptr, nullptr, ROWS, 256, 256, 0);
    fp16_gemm<<<grd(ROWS,256), 256, GEMM_SMEM>>>(pfr, wqkv + 512*256, b_qkv+512, vp, nullptr, nullptr, ROWS, 256, 256, 0);
    // masked MHSA (ctx -> half)
    attn_kernel<<<NB*HH*3, 128>>>(qp, kp, vp, maskb, ctx);
    // out proj + norm1*mask
    fp16_gemm<<<grd(ROWS,256), 256, GEMM_SMEM>>>(ctx, wattn, b_attn_out, tgt2, nullptr, nullptr, ROWS, 256, 256, 0);
    ln_res_mask_kernel<<<ROWS, 256>>>(pf, tgt2, cur, pf1, pf1r);
    // DynamicConv params GEMM (dominant) -> fp16 params
    fp16_gemm<<<grd(ROWS,32768), 256, GEMM_SMEM>>>(pf1r, wdyn, b_dyn, nullptr, params, nullptr, ROWS, 32768, 256, 2);
    // per-instance dynamic conv -> fp16 f2
    dynconv_kernel<<<ROWS, 256, DYN_SMEM>>>(roi, params, f2);
    // dyn out proj — split-K(4): Kper=3136 (T=49); reduce; norm2
    fp16_gemm<<<dim3(2,19,4), 256, GEMM_SMEM>>>(f2, wdynout, nullptr, nullptr, nullptr, part, ROWS, 256, 12544, 0);
    reduce_splitk<<<ROWS, 256>>>(part, b_dyn_out, x, 4);
    post_dyn_kernel<<<ROWS, 256>>>(x, pf1, pf3, pf3r);
    // FFN: ff1 relu -> fp16 ffn; ff2 split-K(8); norm3
    fp16_gemm<<<grd(ROWS,2048), 256, GEMM_SMEM>>>(pf3r, wff1, b_ff1, nullptr, ffn, nullptr, ROWS, 2048, 256, 3);
    fp16_gemm<<<dim3(2,19,8), 256, GEMM_SMEM>>>(ffn, wff2, nullptr, nullptr, nullptr, part, ROWS, 256, 2048, 0);
    reduce_splitk<<<ROWS, 256>>>(part, b_ff2, t2, 8);
    ln_res_mask_kernel<<<ROWS, 256>>>(pf3, t2, cur, nullptr, fc);
    // cls tower + logits
    fp16_gemm<<<grd(ROWS,256), 256, GEMM_SMEM>>>(fc, wcls, nullptr, clsy, nullptr, nullptr, ROWS, 256, 256, 0);
    ln_relu_kernel<<<ROWS, 256>>>(clsy, clsf);
    fp16_gemm<<<grd(ROWS,80), 256, GEMM_SMEM>>>(clsf, wlog, b_logits, out, nullptr, nullptr, ROWS, 80, 256, 0);
}

// round 16
// speedup vs baseline: 1.5987x; 1.0094x over previous
#include <cuda_runtime.h>
#include <cuda_fp16.h>
#include <math.h>
#include <stdint.h>

// ---------------- constants ----------------
#define NB   8
#define NRr  300
#define DD_  256
#define HH   8
#define HDIM 32
#define SS   49
#define FFN  2048
#define NCL  80
#define ROWS (NB*NRr)    // 2400

// ---------------- scratch ----------------
__device__ __half g_qk   [ROWS*DD_];
__device__ __half g_pfr  [ROWS*DD_];
__device__ float  g_qkp  [ROWS*512];       // merged q|k projections (fp32)
__device__ float  g_vp   [ROWS*DD_];
__device__ float  g_mask [NB*NRr*NRr];
__device__ __half g_ctx  [ROWS*DD_];
__device__ float  g_tgt2 [ROWS*DD_];
__device__ float  g_pf1  [ROWS*DD_];
__device__ __half g_pf1r [ROWS*DD_];
__device__ __half g_params[78643200];      // 2400*32768 fp16
__device__ __half g_f2   [30105600];       // 2400*12544 fp16
__device__ float  g_x    [ROWS*DD_];
__device__ float  g_pf3  [ROWS*DD_];
__device__ __half g_pf3r [ROWS*DD_];
__device__ __half g_ffn  [ROWS*FFN];
__device__ float  g_t2   [ROWS*DD_];
__device__ __half g_fc   [ROWS*DD_];
__device__ float  g_clsy [ROWS*DD_];
__device__ __half g_clsf [ROWS*DD_];
__device__ float  g_part [8*ROWS*256];     // split-K partials (fp32)
// fp16 weights
__device__ __half g_wqkv_h  [768*256];
__device__ __half g_wattn_h [256*256];
__device__ __half g_wdyn_h  [32768*256];
__device__ __half g_wdynout_h[256*12544];
__device__ __half g_wff1_h  [2048*256];
__device__ __half g_wff2_h  [256*2048];
__device__ __half g_wcls_h  [256*256];
__device__ __half g_wlog_h  [80*256];

// ---------------- helpers ----------------
__device__ __forceinline__ float blockReduceSum256(float v) {
    __shared__ float red[8];
    int lane = threadIdx.x & 31, w = threadIdx.x >> 5;
    #pragma unroll
    for (int o = 16; o; o >>= 1) v += __shfl_xor_sync(0xffffffffu, v, o);
    __syncthreads();
    if (lane == 0) red[w] = v;
    __syncthreads();
    float s = 0.f;
    #pragma unroll
    for (int i = 0; i < 8; i++) s += red[i];
    return s;
}

__device__ __forceinline__ void mma_fp16(float* c,
        uint32_t a0, uint32_t a1, uint32_t a2, uint32_t a3,
        uint32_t b0, uint32_t b1) {
    asm volatile(
        "mma.sync.aligned.m16n8k16.row.col.f32.f16.f16.f32 "
        "{%0,%1,%2,%3}, {%4,%5,%6,%7}, {%8,%9}, {%0,%1,%2,%3};"
        : "+f"(c[0]), "+f"(c[1]), "+f"(c[2]), "+f"(c[3])
        : "r"(a0), "r"(a1), "r"(a2), "r"(a3), "r"(b0), "r"(b1));
}

#define LDSM_X4(r, addr) \
    asm volatile("ldmatrix.sync.aligned.m8n8.x4.shared.b16 {%0,%1,%2,%3}, [%4];" \
        : "=r"((r)[0]), "=r"((r)[1]), "=r"((r)[2]), "=r"((r)[3]) : "r"(addr))

// ---------------- weight rounding fp32 -> fp16 ----------------
#define S_DYN    2097152
#define S_DYNOUT  802816
#define S_FF1     131072
#define S_FF2     131072
#define S_QKV      49152
#define S_ATTN     16384
#define S_CLS      16384
#define S_LOG       5120
#define S_TOT4   3249152

__global__ void round_weights(const float4* __restrict__ s_dyn,    __half* d_dyn,
                              const float4* __restrict__ s_dynout, __half* d_dynout,
                              const float4* __restrict__ s_ff1,    __half* d_ff1,
                              const float4* __restrict__ s_ff2,    __half* d_ff2,
                              const float4* __restrict__ s_qkv,    __half* d_qkv,
                              const float4* __restrict__ s_attn,   __half* d_attn,
                              const float4* __restrict__ s_cls,    __half* d_cls,
                              const float4* __restrict__ s_log,    __half* d_log) {
    for (long i = blockIdx.x*(long)blockDim.x + threadIdx.x; i < S_TOT4;
         i += (long)gridDim.x*blockDim.x) {
        long j = i;
        const float4* s; __half* d;
        if (j < S_DYN)                       { s = s_dyn;    d = d_dyn; }
        else if ((j -= S_DYN)    < S_DYNOUT) { s = s_dynout; d = d_dynout; }
        else if ((j -= S_DYNOUT) < S_FF1)    { s = s_ff1;    d = d_ff1; }
        else if ((j -= S_FF1)    < S_FF2)    { s = s_ff2;    d = d_ff2; }
        else if ((j -= S_FF2)    < S_QKV)    { s = s_qkv;    d = d_qkv; }
        else if ((j -= S_QKV)    < S_ATTN)   { s = s_attn;   d = d_attn; }
        else if ((j -= S_ATTN)   < S_CLS)    { s = s_cls;    d = d_cls; }
        else { j -= S_CLS;                     s = s_log;    d = d_log; }
        float4 v = s[j];
        __half2* dst = (__half2*)(d + j * 4);
        dst[0] = __floats2half2_rn(v.x, v.y);
        dst[1] = __floats2half2_rn(v.z, v.w);
    }
}

// ---------------- FP16 GEMM: BM=128 BN=128 BK=64, 3-stage, 1 barrier/chunk ----------------
#define GT_H 9216   // 128 rows * 72 halfs per buffer
#define NSTG 3

__device__ __forceinline__ void gemm_load_tile(
        const __half* __restrict__ A, const __half* __restrict__ B,
        int M, int N, int K, int row0, int col0,
        uint32_t sbase, int tid, int buf, int k0) {
    int r  = tid >> 3;
    int c8 = (tid & 7) * 8;
    #pragma unroll
    for (int p = 0; p < 4; p++) {
        int rr = r + p * 32;
        int gr = row0 + rr;
        const __half* src = A + (size_t)(gr < M ? gr : (M - 1)) * K + k0 + c8;
        uint32_t dst = sbase + (uint32_t)((buf * GT_H + rr * 72 + c8) * 2);
        int sz = (gr < M) ? 16 : 0;
        asm volatile("cp.async.cg.shared.global [%0], [%1], 16, %2;\n"
                     :: "r"(dst), "l"(src), "r"(sz));
    }
    #pragma unroll
    for (int p = 0; p < 4; p++) {
        int rr = r + p * 32;
        int gn = col0 + rr;
        const __half* src = B + (size_t)(gn < N ? gn : (N - 1)) * K + k0 + c8;
        uint32_t dst = sbase + (uint32_t)(((NSTG * GT_H) + buf * GT_H + rr * 72 + c8) * 2);
        int sz = (gn < N) ? 16 : 0;
        asm volatile("cp.async.cg.shared.global [%0], [%1], 16, %2;\n"
                     :: "r"(dst), "l"(src), "r"(sz));
    }
    asm volatile("cp.async.commit_group;");
}

__global__ __launch_bounds__(256)
void fp16_gemm(const __half* __restrict__ A, const __half* __restrict__ B,
               const float* __restrict__ bias, float* __restrict__ C,
               __half* __restrict__ Ch, float* __restrict__ P,
               int M, int N, int K, int flags) {
    extern __shared__ __half smh[];
    const int tid  = threadIdx.x;
    const int warp = tid >> 5, lane = tid & 31;
    const int wm = warp >> 1, wn = warp & 1;
    const int row0 = blockIdx.y * 128;
    const int col0 = blockIdx.x * 128;
    const int Kper  = K / gridDim.z;
    const int kbase = blockIdx.z * Kper;
    uint32_t sbase = (uint32_t)__cvta_generic_to_shared(smh);

    float acc[2][8][4];
    #pragma unroll
    for (int i = 0; i < 2; i++)
        #pragma unroll
        for (int j = 0; j < 8; j++)
            #pragma unroll
            for (int k = 0; k < 4; k++) acc[i][j][k] = 0.f;

    const int T = Kper >> 6;        // BK=64
    gemm_load_tile(A, B, M, N, K, row0, col0, sbase, tid, 0, kbase);
    if (T > 1)
        gemm_load_tile(A, B, M, N, K, row0, col0, sbase, tid, 1, kbase + 64);

    // ldmatrix per-lane addresses (canonical x4 layouts)
    const uint32_t aoff = (uint32_t)(((wm * 32 + (lane & 15)) * 72 + ((lane >> 4) * 8)) * 2);
    const uint32_t boff = (uint32_t)(NSTG * GT_H * 2)
        + (uint32_t)(((wn * 64 + ((lane >> 4) & 1) * 8 + (lane & 7)) * 72
                      + (((lane >> 3) & 1) * 8)) * 2);

    int cb = 0;   // current buffer = t % 3
    for (int t = 0; t < T; t++) {
        if (t + 1 < T) asm volatile("cp.async.wait_group 1;");
        else           asm volatile("cp.async.wait_group 0;");
        __syncthreads();
        if (t + 2 < T) {
            int lb = cb + 2; if (lb >= NSTG) lb -= NSTG;
            gemm_load_tile(A, B, M, N, K, row0, col0, sbase, tid, lb, kbase + (t + 2) * 64);
        }

        const uint32_t abase = sbase + (uint32_t)(cb * GT_H * 2) + aoff;
        const uint32_t bbase = sbase + (uint32_t)(cb * GT_H * 2) + boff;
        #pragma unroll
        for (int kk = 0; kk < 4; kk++) {            // 4 x k16
            const uint32_t kbyte = (uint32_t)(kk * 16 * 2);
            uint32_t a[2][4];
            #pragma unroll
            for (int mi = 0; mi < 2; mi++)
                LDSM_X4(a[mi], abase + (uint32_t)(mi * 16 * 72 * 2) + kbyte);
            #pragma unroll
            for (int pr = 0; pr < 4; pr++) {        // pair covers ni = 2*pr, 2*pr+1
                uint32_t b[4];
                LDSM_X4(b, bbase + (uint32_t)(pr * 16 * 72 * 2) + kbyte);
                #pragma unroll
                for (int mi = 0; mi < 2; mi++) {
                    mma_fp16(acc[mi][2*pr],   a[mi][0], a[mi][1], a[mi][2], a[mi][3], b[0], b[1]);
                    mma_fp16(acc[mi][2*pr+1], a[mi][0], a[mi][1], a[mi][2], a[mi][3], b[2], b[3]);
                }
            }
        }
        cb++; if (cb >= NSTG) cb = 0;
    }
    __syncthreads();

    // epilogue
    if (gridDim.z == 1) {
        #pragma unroll
        for (int mi = 0; mi < 2; mi++) {
            int gr0 = row0 + wm * 32 + mi * 16 + (lane >> 2);
            #pragma unroll
            for (int ni = 0; ni < 8; ni++) {
                int gc = col0 + wn * 64 + ni * 8 + 2 * (lane & 3);
                if (gc >= N) continue;
                float bb0 = 0.f, bb1 = 0.f;
                if (bias) { bb0 = bias[gc]; bb1 = bias[gc + 1]; }
                #pragma unroll
                for (int half_ = 0; half_ < 2; half_++) {
                    int gr = gr0 + half_ * 8;
                    if (gr >= M) continue;
                    float v0 = acc[mi][ni][half_ * 2]     + bb0;
                    float v1 = acc[mi][ni][half_ * 2 + 1] + bb1;
                    if (flags & 1) { v0 = fmaxf(v0, 0.f); v1 = fmaxf(v1, 0.f); }
                    if (flags & 2) {
                        *(__half2*)(Ch + (size_t)gr * N + gc) = __floats2half2_rn(v0, v1);
                    } else {
                        *(float2*)(C + (size_t)gr * N + gc) = make_float2(v0, v1);
                    }
                }
            }
        }
    } else {
        float* Pz = P + (size_t)blockIdx.z * M * 256;
        #pragma unroll
        for (int mi = 0; mi < 2; mi++) {
            int gr0 = row0 + wm * 32 + mi * 16 + (lane >> 2);
            #pragma unroll
            for (int ni = 0; ni < 8; ni++) {
                int gc = col0 + wn * 64 + ni * 8 + 2 * (lane & 3);
                if (gc >= N) continue;
                if (gr0 < M)
                    *(float2*)(Pz + (size_t)gr0 * 256 + gc) =
                        make_float2(acc[mi][ni][0], acc[mi][ni][1]);
                if (gr0 + 8 < M)
                    *(float2*)(Pz + (size_t)(gr0 + 8) * 256 + gc) =
                        make_float2(acc[mi][ni][2], acc[mi][ni][3]);
            }
        }
    }
}

// ---------------- split-K reduce ----------------
__global__ void reduce_splitk(const float* __restrict__ P, const float* __restrict__ bias,
                              float* __restrict__ out, int Z) {
    int r = blockIdx.x, c = threadIdx.x;    // 256 threads
    float s = 0.f;
    for (int z = 0; z < Z; z++) s += P[((size_t)z * ROWS + r) * 256 + c];
    out[(size_t)r * 256 + c] = s + bias[c];
}

// ---------------- IoU-relation attention mask ----------------
__global__ void mask_kernel(const float* __restrict__ bboxes,
                            const float* __restrict__ cur,
                            float* __restrict__ maskf) {
    int q = blockIdx.x, b = blockIdx.y, k = threadIdx.x;
    if (k >= NRr) return;
    float4 bq = *(const float4*)(bboxes + (size_t)(b*NRr + q)*4);
    float4 bk = *(const float4*)(bboxes + (size_t)(b*NRr + k)*4);
    float aq = (bq.z-bq.x)*(bq.w-bq.y);
    float ak = (bk.z-bk.x)*(bk.w-bk.y);
    float lx = fmaxf(bq.x, bk.x), ly = fmaxf(bq.y, bk.y);
    float rx = fminf(bq.z, bk.z), ry = fminf(bq.w, bk.w);
    float w  = fmaxf(rx-lx, 0.f), h = fmaxf(ry-ly, 0.f);
    float inter = w*h;
    float uni = fmaxf(aq + ak - inter, 1e-9f);
    float iou = inter/uni;
    float o   = (iou < 0.5f) ? 1.f : 0.f;
    float cq = cur[b*NRr + q], ck = cur[b*NRr + k];
    float val = o*cq*ck + ((q == k) ? (1.f - cq) : 0.f);
    maskf[((size_t)(b*NRr + q))*NRr + k] = (val > 0.f) ? 1.f : 0.f;
}

// ---------------- qk = h(pf+query); pfr = h(pf) ----------------
__global__ void add_round_kernel(const float* __restrict__ a, const float* __restrict__ b,
                                 __half* __restrict__ qk, __half* __restrict__ pfr, int n) {
    int i = blockIdx.x*blockDim.x + threadIdx.x;
    if (i < n) {
        float av = a[i];
        qk[i]  = __float2half_rn(av + b[i]);
        pfr[i] = __float2half_rn(av);
    }
}

// ---------------- masked multi-head attention (merged q|k input) ----------------
#define QCH 100
__global__ void attn_kernel(const float* __restrict__ qkp, const float* __restrict__ vp,
                            const float* __restrict__ maskf, __half* __restrict__ ctx) {
    const int bh = blockIdx.x / 3;
    const int ch = blockIdx.x % 3;
    const int b = bh >> 3;
    const int h = bh & 7;
    __shared__ float Ks[150*32];
    __shared__ float Vs[150*32];
    const int tid = threadIdx.x;          // 128
    const int q = ch * QCH + tid;
    const bool act = (tid < QCH) && (q < NRr);
    float qv[32], acc[32];
    float m = -1e30f, ssum = 0.f;
    if (act) {
        const float* qr = qkp + ((size_t)(b*NRr + q))*512 + h*HDIM;
        #pragma unroll
        for (int d = 0; d < 32; d++) { qv[d] = qr[d]; acc[d] = 0.f; }
    }
    const float* mrow = maskf + ((size_t)(b*NRr) + (act ? q : 0))*NRr;
    const float scale = 0.17677669529663687f;

    for (int c0 = 0; c0 < NRr; c0 += 150) {
        __syncthreads();
        for (int i = tid; i < 150*32; i += 128) {
            int k = i >> 5, d = i & 31;
            Ks[i] = qkp[((size_t)(b*NRr + c0 + k))*512 + 256 + h*HDIM + d];
            Vs[i] = vp[((size_t)(b*NRr + c0 + k))*DD_ + h*HDIM + d];
        }
        __syncthreads();
        if (act) {
            for (int k = 0; k < 150; k++) {
                const float* kr = Ks + k*32;
                float x0 = 0.f, x1 = 0.f, x2 = 0.f, x3 = 0.f;
                #pragma unroll
                for (int d = 0; d < 32; d += 4) {
                    x0 += qv[d]*kr[d];   x1 += qv[d+1]*kr[d+1];
                    x2 += qv[d+2]*kr[d+2]; x3 += qv[d+3]*kr[d+3];
                }
                float x = ((x0+x1)+(x2+x3))*scale;
                if (mrow[c0+k] > 0.f) x = -1e9f;
                float nm = fmaxf(m, x);
                float sc = __expf(m - nm);
                float e  = __expf(x - nm);
                ssum = ssum*sc + e;
                const float* vr = Vs + k*32;
                #pragma unroll
                for (int d = 0; d < 32; d++) acc[d] = acc[d]*sc + e*vr[d];
                m = nm;
            }
        }
    }
    if (act) {
        float inv = 1.f/ssum;
        __half* cr = ctx + ((size_t)(b*NRr + q))*DD_ + h*HDIM;
        #pragma unroll
        for (int d = 0; d < 32; d++) cr[d] = __float2half_rn(acc[d]*inv);
    }
}

// ---------------- ln(residual) * mask -> exact (optional) + half ----------------
__global__ void ln_res_mask_kernel(const float* __restrict__ a, const float* __restrict__ bq,
                                   const float* __restrict__ cur,
                                   float* __restrict__ out, __half* __restrict__ out_r) {
    int r = blockIdx.x, t = threadIdx.x;
    float x = a[(size_t)r*DD_ + t] + bq[(size_t)r*DD_ + t];
    float mean = blockReduceSum256(x) * (1.f/256.f);
    float d = x - mean;
    float var = blockReduceSum256(d*d) * (1.f/256.f);
    float y = d * rsqrtf(var + 1e-5f) * cur[r];
    if (out) out[(size_t)r*DD_ + t] = y;
    out_r[(size_t)r*DD_ + t] = __float2half_rn(y);
}

// ---------------- relu(ln(x)) -> + pf1 -> ln (exact + half) ----------------
__global__ void post_dyn_kernel(const float* __restrict__ x, const float* __restrict__ pf1,
                                float* __restrict__ out, __half* __restrict__ out_r) {
    int r = blockIdx.x, t = threadIdx.x;
    float v = x[(size_t)r*DD_ + t];
    float m1 = blockReduceSum256(v) * (1.f/256.f);
    float d1 = v - m1;
    float v1 = blockReduceSum256(d1*d1) * (1.f/256.f);
    float rl = fmaxf(d1 * rsqrtf(v1 + 1e-5f), 0.f);
    float y = pf1[(size_t)r*DD_ + t] + rl;
    float m2 = blockReduceSum256(y) * (1.f/256.f);
    float d2 = y - m2;
    float v2 = blockReduceSum256(d2*d2) * (1.f/256.f);
    float z = d2 * rsqrtf(v2 + 1e-5f);
    out[(size_t)r*DD_ + t] = z;
    out_r[(size_t)r*DD_ + t] = __float2half_rn(z);
}

// ---------------- relu(ln(x)) -> half ----------------
__global__ void ln_relu_kernel(const float* __restrict__ x, __half* __restrict__ out) {
    int r = blockIdx.x, t = threadIdx.x;
    float v = x[(size_t)r*DD_ + t];
    float m = blockReduceSum256(v) * (1.f/256.f);
    float d = v - m;
    float var = blockReduceSum256(d*d) * (1.f/256.f);
    out[(size_t)r*DD_ + t] = __float2half_rn(fmaxf(d * rsqrtf(var + 1e-5f), 0.f));
}

// ---------------- DynamicConv (register-tiled; params fp16 in, f2 fp16 out) ----------------
#define SPAD 52
#define DYN_SMEM 210944

__global__ __launch_bounds__(256)
void dynconv_kernel(const float* __restrict__ roi, const __half* __restrict__ params,
                    __half* __restrict__ out) {
    int n = blockIdx.x;
    extern __shared__ float sm[];
    float* featsT = sm;                 // [d][s] 256 x 52
    float* p1     = sm + 13312;         // [d][e] 256 x 64
    float* p2     = p1 + 16384;         // [e][d] 64 x 256
    float* f1     = p2 + 16384;         // [s][e] 52 x 64
    float* f1T    = f1 + 3328;          // [e][s] 64 x 52
    int tid = threadIdx.x;

    for (int i = tid; i < 256*3; i += 256) {
        int d = i / 3, s = 49 + (i % 3);
        featsT[d*SPAD + s] = 0.f;
    }
    for (int i = tid; i < SS*DD_; i += 256) {
        int s = i >> 8, d = i & 255;
        featsT[d*SPAD + s] = roi[((size_t)s*ROWS + n)*DD_ + d];
    }
    const __half2* pr2 = (const __half2*)(params + (size_t)n * 32768);
    for (int i = tid; i < 8192; i += 256) {
        float2 f = __half22float2(pr2[i]);
        p1[2*i] = f.x; p1[2*i+1] = f.y;
    }
    for (int i = tid; i < 8192; i += 256) {
        float2 f = __half22float2(pr2[8192 + i]);
        p2[2*i] = f.x; p2[2*i+1] = f.y;
    }
    __syncthreads();

    {
        int te = tid & 15, tsg = tid >> 4;
        if (tsg < 13) {
            int e0 = te * 4, s0 = tsg * 4;
            float acc[4][4];
            #pragma unroll
            for (int i = 0; i < 4; i++)
                #pragma unroll
                for (int j = 0; j < 4; j++) acc[i][j] = 0.f;
            for (int d = 0; d < 256; d++) {
                float4 fv = *(const float4*)(featsT + d*SPAD + s0);
                float4 pv = *(const float4*)(p1 + d*64 + e0);
                acc[0][0] += fv.x*pv.x; acc[0][1] += fv.x*pv.y; acc[0][2] += fv.x*pv.z; acc[0][3] += fv.x*pv.w;
                acc[1][0] += fv.y*pv.x; acc[1][1] += fv.y*pv.y; acc[1][2] += fv.y*pv.z; acc[1][3] += fv.y*pv.w;
                acc[2][0] += fv.z*pv.x; acc[2][1] += fv.z*pv.y; acc[2][2] += fv.z*pv.z; acc[2][3] += fv.z*pv.w;
                acc[3][0] += fv.w*pv.x; acc[3][1] += fv.w*pv.y; acc[3][2] += fv.w*pv.z; acc[3][3] += fv.w*pv.w;
            }
            #pragma unroll
            for (int i = 0; i < 4; i++)
                #pragma unroll
                for (int j = 0; j < 4; j++)
                    f1[(s0+i)*64 + e0 + j] = acc[i][j];
        }
    }
    __syncthreads();

    int warp = tid >> 5, lane = tid & 31;
    for (int s = warp; s < SS; s += 8) {
        float x0 = f1[s*64 + lane], x1 = f1[s*64 + 32 + lane];
        float sum = x0 + x1;
        #pragma unroll
        for (int o = 16; o; o >>= 1) sum += __shfl_xor_sync(0xffffffffu, sum, o);
        float m = sum * (1.f/64.f);
        float d0 = x0 - m, d1 = x1 - m;
        float vs = d0*d0 + d1*d1;
        #pragma unroll
        for (int o = 16; o; o >>= 1) vs += __shfl_xor_sync(0xffffffffu, vs, o);
        float inv = rsqrtf(vs*(1.f/64.f) + 1e-5f);
        f1T[lane*SPAD + s]        = fmaxf(d0*inv, 0.f);
        f1T[(32+lane)*SPAD + s]   = fmaxf(d1*inv, 0.f);
    }
    __syncthreads();

    float* f2 = featsT;
    {
        int td = tid & 63, tsg2 = tid >> 6;
        int d0 = td * 4;
        for (int sg = tsg2; sg < 13; sg += 4) {
            int s0 = sg * 4;
            float acc[4][4];
            #pragma unroll
            for (int i = 0; i < 4; i++)
                #pragma unroll
                for (int j = 0; j < 4; j++) acc[i][j] = 0.f;
            for (int e = 0; e < 64; e++) {
                float4 fv = *(const float4*)(f1T + e*SPAD + s0);
                float4 pv = *(const float4*)(p2 + e*256 + d0);
                acc[0][0] += fv.x*pv.x; acc[0][1] += fv.x*pv.y; acc[0][2] += fv.x*pv.z; acc[0][3] += fv.x*pv.w;
                acc[1][0] += fv.y*pv.x; acc[1][1] += fv.y*pv.y; acc[1][2] += fv.y*pv.z; acc[1][3] += fv.y*pv.w;
                acc[2][0] += fv.z*pv.x; acc[2][1] += fv.z*pv.y; acc[2][2] += fv.z*pv.z; acc[2][3] += fv.z*pv.w;
                acc[3][0] += fv.w*pv.x; acc[3][1] += fv.w*pv.y; acc[3][2] += fv.w*pv.z; acc[3][3] += fv.w*pv.w;
            }
            #pragma unroll
            for (int i = 0; i < 4; i++)
                #pragma unroll
                for (int j = 0; j < 4; j++)
                    f2[(s0+i)*256 + d0 + j] = acc[i][j];
        }
    }
    __syncthreads();

    for (int s = warp; s < SS; s += 8) {
        float x[8]; float sum = 0.f;
        #pragma unroll
        for (int j = 0; j < 8; j++) { x[j] = f2[s*256 + j*32 + lane]; sum += x[j]; }
        #pragma unroll
        for (int o = 16; o; o >>= 1) sum += __shfl_xor_sync(0xffffffffu, sum, o);
        float m = sum * (1.f/256.f);
        float vs = 0.f;
        #pragma unroll
        for (int j = 0; j < 8; j++) { float dd = x[j]-m; vs += dd*dd; }
        #pragma unroll
        for (int o = 16; o; o >>= 1) vs += __shfl_xor_sync(0xffffffffu, vs, o);
        float inv = rsqrtf(vs*(1.f/256.f) + 1e-5f);
        #pragma unroll
        for (int j = 0; j < 8; j++)
            out[(size_t)n*12544 + s*256 + j*32 + lane] =
                __float2half_rn(fmaxf((x[j]-m)*inv, 0.f));
    }
}

// ---------------- host ----------------
extern "C" void kernel_launch(void* const* d_in, const int* in_sizes, int n_in,
                              void* d_out, int out_size) {
    const float* bboxes     = (const float*)d_in[0];
    const float* pf         = (const float*)d_in[1];
    const float* roi        = (const float*)d_in[2];
    const float* query      = (const float*)d_in[3];
    const float* cur        = (const float*)d_in[4];
    const float* w_qkv      = (const float*)d_in[5];
    const float* b_qkv      = (const float*)d_in[6];
    const float* w_attn_out = (const float*)d_in[7];
    const float* b_attn_out = (const float*)d_in[8];
    const float* w_dyn      = (const float*)d_in[9];
    const float* b_dyn      = (const float*)d_in[10];
    const float* w_dyn_out  = (const float*)d_in[11];
    const float* b_dyn_out  = (const float*)d_in[12];
    const float* w_ff1      = (const float*)d_in[13];
    const float* b_ff1      = (const float*)d_in[14];
    const float* w_ff2      = (const float*)d_in[15];
    const float* b_ff2      = (const float*)d_in[16];
    const float* w_cls      = (const float*)d_in[17];
    const float* w_logits   = (const float*)d_in[18];
    const float* b_logits   = (const float*)d_in[19];
    float* out = (float*)d_out;

    __half *qk,*pfr,*ctx,*pf1r,*params,*f2,*pf3r,*ffn,*fc,*clsf;
    __half *wqkv,*wattn,*wdyn,*wdynout,*wff1,*wff2,*wcls,*wlog;
    float *qkp,*vp,*maskb,*tgt2,*pf1,*x,*pf3,*t2,*clsy,*part;
    cudaGetSymbolAddress((void**)&qk,     g_qk);
    cudaGetSymbolAddress((void**)&pfr,    g_pfr);
    cudaGetSymbolAddress((void**)&qkp,    g_qkp);
    cudaGetSymbolAddress((void**)&vp,     g_vp);
    cudaGetSymbolAddress((void**)&maskb,  g_mask);
    cudaGetSymbolAddress((void**)&ctx,    g_ctx);
    cudaGetSymbolAddress((void**)&tgt2,   g_tgt2);
    cudaGetSymbolAddress((void**)&pf1,    g_pf1);
    cudaGetSymbolAddress((void**)&pf1r,   g_pf1r);
    cudaGetSymbolAddress((void**)&params, g_params);
    cudaGetSymbolAddress((void**)&f2,     g_f2);
    cudaGetSymbolAddress((void**)&x,      g_x);
    cudaGetSymbolAddress((void**)&pf3,    g_pf3);
    cudaGetSymbolAddress((void**)&pf3r,   g_pf3r);
    cudaGetSymbolAddress((void**)&ffn,    g_ffn);
    cudaGetSymbolAddress((void**)&t2,     g_t2);
    cudaGetSymbolAddress((void**)&fc,     g_fc);
    cudaGetSymbolAddress((void**)&clsy,   g_clsy);
    cudaGetSymbolAddress((void**)&clsf,   g_clsf);
    cudaGetSymbolAddress((void**)&part,   g_part);
    cudaGetSymbolAddress((void**)&wqkv,   g_wqkv_h);
    cudaGetSymbolAddress((void**)&wattn,  g_wattn_h);
    cudaGetSymbolAddress((void**)&wdyn,   g_wdyn_h);
    cudaGetSymbolAddress((void**)&wdynout,g_wdynout_h);
    cudaGetSymbolAddress((void**)&wff1,   g_wff1_h);
    cudaGetSymbolAddress((void**)&wff2,   g_wff2_h);
    cudaGetSymbolAddress((void**)&wcls,   g_wcls_h);
    cudaGetSymbolAddress((void**)&wlog,   g_wlog_h);

    const int GEMM_SMEM = 2 * NSTG * GT_H * 2;   // 110592 B (3 stages)
    cudaFuncSetAttribute(fp16_gemm, cudaFuncAttributeMaxDynamicSharedMemorySize, GEMM_SMEM);
    cudaFuncSetAttribute(dynconv_kernel, cudaFuncAttributeMaxDynamicSharedMemorySize, DYN_SMEM);

    auto grd = [](int M, int N) { return dim3((unsigned)((N+127)/128), (unsigned)((M+127)/128), 1); };

    // prep: mask, half activations, half weights
    mask_kernel<<<dim3(NRr, NB), 320>>>(bboxes, cur, maskb);
    add_round_kernel<<<(ROWS*DD_+255)/256, 256>>>(pf, query, qk, pfr, ROWS*DD_);
    round_weights<<<1280, 256>>>((const float4*)w_dyn,     wdyn,
                                 (const float4*)w_dyn_out, wdynout,
                                 (const float4*)w_ff1,     wff1,
                                 (const float4*)w_ff2,     wff2,
                                 (const float4*)w_qkv,     wqkv,
                                 (const float4*)w_attn_out,wattn,
                                 (const float4*)w_cls,     wcls,
                                 (const float4*)w_logits,  wlog);

    // merged q|k projection (N=512) + v
    fp16_gemm<<<grd(ROWS,512), 256, GEMM_SMEM>>>(qk,  wqkv,           b_qkv,     qkp, nullptr, nullptr, ROWS, 512, 256, 0);
    fp16_gemm<<<grd(ROWS,256), 256, GEMM_SMEM>>>(pfr, wqkv + 512*256, b_qkv+512, vp,  nullptr, nullptr, ROWS, 256, 256, 0);
    // masked MHSA (ctx -> half)
    attn_kernel<<<NB*HH*3, 128>>>(qkp, vp, maskb, ctx);
    // out proj + norm1*mask
    fp16_gemm<<<grd(ROWS,256), 256, GEMM_SMEM>>>(ctx, wattn, b_attn_out, tgt2, nullptr, nullptr, ROWS, 256, 256, 0);
    ln_res_mask_kernel<<<ROWS, 256>>>(pf, tgt2, cur, pf1, pf1r);
    // DynamicConv params GEMM (dominant) -> fp16 params
    fp16_gemm<<<grd(ROWS,32768), 256, GEMM_SMEM>>>(pf1r, wdyn, b_dyn, nullptr, params, nullptr, ROWS, 32768, 256, 2);
    // per-instance dynamic conv -> fp16 f2
    dynconv_kernel<<<ROWS, 256, DYN_SMEM>>>(roi, params, f2);
    // dyn out proj — split-K(4): Kper=3136 (T=49); reduce; norm2
    fp16_gemm<<<dim3(2,19,4), 256, GEMM_SMEM>>>(f2, wdynout, nullptr, nullptr, nullptr, part, ROWS, 256, 12544, 0);
    reduce_splitk<<<ROWS, 256>>>(part, b_dyn_out, x, 4);
    post_dyn_kernel<<<ROWS, 256>>>(x, pf1, pf3, pf3r);
    // FFN: ff1 relu -> fp16 ffn; ff2 split-K(8); norm3
    fp16_gemm<<<grd(ROWS,2048), 256, GEMM_SMEM>>>(pf3r, wff1, b_ff1, nullptr, ffn, nullptr, ROWS, 2048, 256, 3);
    fp16_gemm<<<dim3(2,19,8), 256, GEMM_SMEM>>>(ffn, wff2, nullptr, nullptr, nullptr, part, ROWS, 256, 2048, 0);
    reduce_splitk<<<ROWS, 256>>>(part, b_ff2, t2, 8);
    ln_res_mask_kernel<<<ROWS, 256>>>(pf3, t2, cur, nullptr, fc);
    // cls tower + logits
    fp16_gemm<<<grd(ROWS,256), 256, GEMM_SMEM>>>(fc, wcls, nullptr, clsy, nullptr, nullptr, ROWS, 256, 256, 0);
    ln_relu_kernel<<<ROWS, 256>>>(clsy, clsf);
    fp16_gemm<<<grd(ROWS,80), 256, GEMM_SMEM>>>(clsf, wlog, b_logits, out, nullptr, nullptr, ROWS, 80, 256, 0);
}

// round 17
// speedup vs baseline: 1.6100x; 1.0071x over previous
#include <cuda_runtime.h>
#include <cuda_fp16.h>
#include <math.h>
#include <stdint.h>

// ---------------- constants ----------------
#define NB   8
#define NRr  300
#define DD_  256
#define HH   8
#define HDIM 32
#define SS   49
#define FFN  2048
#define NCL  80
#define ROWS (NB*NRr)    // 2400

// ---------------- scratch ----------------
__device__ __half g_qk   [ROWS*DD_];
__device__ __half g_pfr  [ROWS*DD_];
__device__ float  g_qkp  [ROWS*512];
__device__ float  g_vp   [ROWS*DD_];
__device__ float  g_mask [NB*NRr*NRr];
__device__ __half g_ctx  [ROWS*DD_];
__device__ float  g_tgt2 [ROWS*DD_];
__device__ float  g_pf1  [ROWS*DD_];
__device__ __half g_pf1r [ROWS*DD_];
__device__ __half g_params[78643200];      // 2400*32768 fp16
__device__ __half g_f2   [30105600];       // 2400*12544 fp16
__device__ float  g_x    [ROWS*DD_];
__device__ float  g_pf3  [ROWS*DD_];
__device__ __half g_pf3r [ROWS*DD_];
__device__ __half g_ffn  [ROWS*FFN];
__device__ float  g_t2   [ROWS*DD_];
__device__ __half g_fc   [ROWS*DD_];
__device__ float  g_clsy [ROWS*DD_];
__device__ __half g_clsf [ROWS*DD_];
__device__ float  g_part [8*ROWS*256];
// fp16 weights
__device__ __half g_wqkv_h  [768*256];
__device__ __half g_wattn_h [256*256];
__device__ __half g_wdyn_h  [32768*256];
__device__ __half g_wdynout_h[256*12544];
__device__ __half g_wff1_h  [2048*256];
__device__ __half g_wff2_h  [256*2048];
__device__ __half g_wcls_h  [256*256];
__device__ __half g_wlog_h  [80*256];

// ---------------- helpers ----------------
__device__ __forceinline__ float blockReduceSum256(float v) {
    __shared__ float red[8];
    int lane = threadIdx.x & 31, w = threadIdx.x >> 5;
    #pragma unroll
    for (int o = 16; o; o >>= 1) v += __shfl_xor_sync(0xffffffffu, v, o);
    __syncthreads();
    if (lane == 0) red[w] = v;
    __syncthreads();
    float s = 0.f;
    #pragma unroll
    for (int i = 0; i < 8; i++) s += red[i];
    return s;
}

__device__ __forceinline__ void mma_fp16(float* c,
        uint32_t a0, uint32_t a1, uint32_t a2, uint32_t a3,
        uint32_t b0, uint32_t b1) {
    asm volatile(
        "mma.sync.aligned.m16n8k16.row.col.f32.f16.f16.f32 "
        "{%0,%1,%2,%3}, {%4,%5,%6,%7}, {%8,%9}, {%0,%1,%2,%3};"
        : "+f"(c[0]), "+f"(c[1]), "+f"(c[2]), "+f"(c[3])
        : "r"(a0), "r"(a1), "r"(a2), "r"(a3), "r"(b0), "r"(b1));
}

#define LDSM_X4(r, addr) \
    asm volatile("ldmatrix.sync.aligned.m8n8.x4.shared.b16 {%0,%1,%2,%3}, [%4];" \
        : "=r"((r)[0]), "=r"((r)[1]), "=r"((r)[2]), "=r"((r)[3]) : "r"(addr))

// ---------------- weight rounding fp32 -> fp16 ----------------
#define S_DYN    2097152
#define S_DYNOUT  802816
#define S_FF1     131072
#define S_FF2     131072
#define S_QKV      49152
#define S_ATTN     16384
#define S_CLS      16384
#define S_LOG       5120
#define S_TOT4   3249152

__global__ void round_weights(const float4* __restrict__ s_dyn,    __half* d_dyn,
                              const float4* __restrict__ s_dynout, __half* d_dynout,
                              const float4* __restrict__ s_ff1,    __half* d_ff1,
                              const float4* __restrict__ s_ff2,    __half* d_ff2,
                              const float4* __restrict__ s_qkv,    __half* d_qkv,
                              const float4* __restrict__ s_attn,   __half* d_attn,
                              const float4* __restrict__ s_cls,    __half* d_cls,
                              const float4* __restrict__ s_log,    __half* d_log) {
    for (long i = blockIdx.x*(long)blockDim.x + threadIdx.x; i < S_TOT4;
         i += (long)gridDim.x*blockDim.x) {
        long j = i;
        const float4* s; __half* d;
        if (j < S_DYN)                       { s = s_dyn;    d = d_dyn; }
        else if ((j -= S_DYN)    < S_DYNOUT) { s = s_dynout; d = d_dynout; }
        else if ((j -= S_DYNOUT) < S_FF1)    { s = s_ff1;    d = d_ff1; }
        else if ((j -= S_FF1)    < S_FF2)    { s = s_ff2;    d = d_ff2; }
        else if ((j -= S_FF2)    < S_QKV)    { s = s_qkv;    d = d_qkv; }
        else if ((j -= S_QKV)    < S_ATTN)   { s = s_attn;   d = d_attn; }
        else if ((j -= S_ATTN)   < S_CLS)    { s = s_cls;    d = d_cls; }
        else { j -= S_CLS;                     s = s_log;    d = d_log; }
        float4 v = s[j];
        __half2* dst = (__half2*)(d + j * 4);
        dst[0] = __floats2half2_rn(v.x, v.y);
        dst[1] = __floats2half2_rn(v.z, v.w);
    }
}

// ---------------- FP16 GEMM: 3-stage cp.async + register fragment double-buffer ----------------
#define GT_H 9216   // 128 rows * 72 halfs per buffer
#define NSTG 3

__device__ __forceinline__ void gemm_load_tile(
        const __half* __restrict__ A, const __half* __restrict__ B,
        int M, int N, int K, int row0, int col0,
        uint32_t sbase, int tid, int buf, int k0) {
    int r  = tid >> 3;
    int c8 = (tid & 7) * 8;
    #pragma unroll
    for (int p = 0; p < 4; p++) {
        int rr = r + p * 32;
        int gr = row0 + rr;
        const __half* src = A + (size_t)(gr < M ? gr : (M - 1)) * K + k0 + c8;
        uint32_t dst = sbase + (uint32_t)((buf * GT_H + rr * 72 + c8) * 2);
        int sz = (gr < M) ? 16 : 0;
        asm volatile("cp.async.cg.shared.global [%0], [%1], 16, %2;\n"
                     :: "r"(dst), "l"(src), "r"(sz));
    }
    #pragma unroll
    for (int p = 0; p < 4; p++) {
        int rr = r + p * 32;
        int gn = col0 + rr;
        const __half* src = B + (size_t)(gn < N ? gn : (N - 1)) * K + k0 + c8;
        uint32_t dst = sbase + (uint32_t)(((NSTG * GT_H) + buf * GT_H + rr * 72 + c8) * 2);
        int sz = (gn < N) ? 16 : 0;
        asm volatile("cp.async.cg.shared.global [%0], [%1], 16, %2;\n"
                     :: "r"(dst), "l"(src), "r"(sz));
    }
    asm volatile("cp.async.commit_group;");
}

__global__ __launch_bounds__(256)
void fp16_gemm(const __half* __restrict__ A, const __half* __restrict__ B,
               const float* __restrict__ bias, float* __restrict__ C,
               __half* __restrict__ Ch, float* __restrict__ P,
               int M, int N, int K, int flags) {
    extern __shared__ __half smh[];
    const int tid  = threadIdx.x;
    const int warp = tid >> 5, lane = tid & 31;
    const int wm = warp >> 1, wn = warp & 1;
    const int row0 = blockIdx.y * 128;
    const int col0 = blockIdx.x * 128;
    const int Kper  = K / gridDim.z;
    const int kbase = blockIdx.z * Kper;
    uint32_t sbase = (uint32_t)__cvta_generic_to_shared(smh);

    float acc[2][8][4];
    #pragma unroll
    for (int i = 0; i < 2; i++)
        #pragma unroll
        for (int j = 0; j < 8; j++)
            #pragma unroll
            for (int k = 0; k < 4; k++) acc[i][j][k] = 0.f;

    const int T = Kper >> 6;        // BK=64
    gemm_load_tile(A, B, M, N, K, row0, col0, sbase, tid, 0, kbase);
    if (T > 1)
        gemm_load_tile(A, B, M, N, K, row0, col0, sbase, tid, 1, kbase + 64);

    const uint32_t aoff = (uint32_t)(((wm * 32 + (lane & 15)) * 72 + ((lane >> 4) * 8)) * 2);
    const uint32_t boff = (uint32_t)(NSTG * GT_H * 2)
        + (uint32_t)(((wn * 64 + ((lane >> 4) & 1) * 8 + (lane & 7)) * 72
                      + (((lane >> 3) & 1) * 8)) * 2);

    uint32_t aF[2][2][4], bF[2][4][4];   // [regbuf][mi/pr][4]

    int cb = 0;
    for (int t = 0; t < T; t++) {
        if (t + 1 < T) asm volatile("cp.async.wait_group 1;");
        else           asm volatile("cp.async.wait_group 0;");
        __syncthreads();
        if (t + 2 < T) {
            int lb = cb + 2; if (lb >= NSTG) lb -= NSTG;
            gemm_load_tile(A, B, M, N, K, row0, col0, sbase, tid, lb, kbase + (t + 2) * 64);
        }

        const uint32_t abase = sbase + (uint32_t)(cb * GT_H * 2) + aoff;
        const uint32_t bbase = sbase + (uint32_t)(cb * GT_H * 2) + boff;

        // preload fragments for kk = 0 into regbuf 0
        #pragma unroll
        for (int mi = 0; mi < 2; mi++)
            LDSM_X4(aF[0][mi], abase + (uint32_t)(mi * 16 * 72 * 2));
        #pragma unroll
        for (int pr = 0; pr < 4; pr++)
            LDSM_X4(bF[0][pr], bbase + (uint32_t)(pr * 16 * 72 * 2));

        #pragma unroll
        for (int kk = 0; kk < 4; kk++) {
            const int cur = kk & 1, nx = cur ^ 1;
            if (kk < 3) {
                const uint32_t kbyte = (uint32_t)((kk + 1) * 16 * 2);
                #pragma unroll
                for (int mi = 0; mi < 2; mi++)
                    LDSM_X4(aF[nx][mi], abase + (uint32_t)(mi * 16 * 72 * 2) + kbyte);
                #pragma unroll
                for (int pr = 0; pr < 4; pr++)
                    LDSM_X4(bF[nx][pr], bbase + (uint32_t)(pr * 16 * 72 * 2) + kbyte);
            }
            #pragma unroll
            for (int pr = 0; pr < 4; pr++) {
                #pragma unroll
                for (int mi = 0; mi < 2; mi++) {
                    mma_fp16(acc[mi][2*pr],   aF[cur][mi][0], aF[cur][mi][1],
                             aF[cur][mi][2], aF[cur][mi][3],
                             bF[cur][pr][0], bF[cur][pr][1]);
                    mma_fp16(acc[mi][2*pr+1], aF[cur][mi][0], aF[cur][mi][1],
                             aF[cur][mi][2], aF[cur][mi][3],
                             bF[cur][pr][2], bF[cur][pr][3]);
                }
            }
        }
        cb++; if (cb >= NSTG) cb = 0;
    }
    __syncthreads();

    // epilogue
    if (gridDim.z == 1) {
        #pragma unroll
        for (int mi = 0; mi < 2; mi++) {
            int gr0 = row0 + wm * 32 + mi * 16 + (lane >> 2);
            #pragma unroll
            for (int ni = 0; ni < 8; ni++) {
                int gc = col0 + wn * 64 + ni * 8 + 2 * (lane & 3);
                if (gc >= N) continue;
                float bb0 = 0.f, bb1 = 0.f;
                if (bias) { bb0 = bias[gc]; bb1 = bias[gc + 1]; }
                #pragma unroll
                for (int half_ = 0; half_ < 2; half_++) {
                    int gr = gr0 + half_ * 8;
                    if (gr >= M) continue;
                    float v0 = acc[mi][ni][half_ * 2]     + bb0;
                    float v1 = acc[mi][ni][half_ * 2 + 1] + bb1;
                    if (flags & 1) { v0 = fmaxf(v0, 0.f); v1 = fmaxf(v1, 0.f); }
                    if (flags & 2) {
                        *(__half2*)(Ch + (size_t)gr * N + gc) = __floats2half2_rn(v0, v1);
                    } else {
                        *(float2*)(C + (size_t)gr * N + gc) = make_float2(v0, v1);
                    }
                }
            }
        }
    } else {
        float* Pz = P + (size_t)blockIdx.z * M * 256;
        #pragma unroll
        for (int mi = 0; mi < 2; mi++) {
            int gr0 = row0 + wm * 32 + mi * 16 + (lane >> 2);
            #pragma unroll
            for (int ni = 0; ni < 8; ni++) {
                int gc = col0 + wn * 64 + ni * 8 + 2 * (lane & 3);
                if (gc >= N) continue;
                if (gr0 < M)
                    *(float2*)(Pz + (size_t)gr0 * 256 + gc) =
                        make_float2(acc[mi][ni][0], acc[mi][ni][1]);
                if (gr0 + 8 < M)
                    *(float2*)(Pz + (size_t)(gr0 + 8) * 256 + gc) =
                        make_float2(acc[mi][ni][2], acc[mi][ni][3]);
            }
        }
    }
}

// ---------------- split-K reduce ----------------
__global__ void reduce_splitk(const float* __restrict__ P, const float* __restrict__ bias,
                              float* __restrict__ out, int Z) {
    int r = blockIdx.x, c = threadIdx.x;
    float s = 0.f;
    for (int z = 0; z < Z; z++) s += P[((size_t)z * ROWS + r) * 256 + c];
    out[(size_t)r * 256 + c] = s + bias[c];
}

// ---------------- IoU-relation attention mask ----------------
__global__ void mask_kernel(const float* __restrict__ bboxes,
                            const float* __restrict__ cur,
                            float* __restrict__ maskf) {
    int q = blockIdx.x, b = blockIdx.y, k = threadIdx.x;
    if (k >= NRr) return;
    float4 bq = *(const float4*)(bboxes + (size_t)(b*NRr + q)*4);
    float4 bk = *(const float4*)(bboxes + (size_t)(b*NRr + k)*4);
    float aq = (bq.z-bq.x)*(bq.w-bq.y);
    float ak = (bk.z-bk.x)*(bk.w-bk.y);
    float lx = fmaxf(bq.x, bk.x), ly = fmaxf(bq.y, bk.y);
    float rx = fminf(bq.z, bk.z), ry = fminf(bq.w, bk.w);
    float w  = fmaxf(rx-lx, 0.f), h = fmaxf(ry-ly, 0.f);
    float inter = w*h;
    float uni = fmaxf(aq + ak - inter, 1e-9f);
    float iou = inter/uni;
    float o   = (iou < 0.5f) ? 1.f : 0.f;
    float cq = cur[b*NRr + q], ck = cur[b*NRr + k];
    float val = o*cq*ck + ((q == k) ? (1.f - cq) : 0.f);
    maskf[((size_t)(b*NRr + q))*NRr + k] = (val > 0.f) ? 1.f : 0.f;
}

// ---------------- qk = h(pf+query); pfr = h(pf) ----------------
__global__ void add_round_kernel(const float* __restrict__ a, const float* __restrict__ b,
                                 __half* __restrict__ qk, __half* __restrict__ pfr, int n) {
    int i = blockIdx.x*blockDim.x + threadIdx.x;
    if (i < n) {
        float av = a[i];
        qk[i]  = __float2half_rn(av + b[i]);
        pfr[i] = __float2half_rn(av);
    }
}

// ---------------- masked multi-head attention (merged q|k input) ----------------
#define QCH 100
__global__ void attn_kernel(const float* __restrict__ qkp, const float* __restrict__ vp,
                            const float* __restrict__ maskf, __half* __restrict__ ctx) {
    const int bh = blockIdx.x / 3;
    const int ch = blockIdx.x % 3;
    const int b = bh >> 3;
    const int h = bh & 7;
    __shared__ float Ks[150*32];
    __shared__ float Vs[150*32];
    const int tid = threadIdx.x;          // 128
    const int q = ch * QCH + tid;
    const bool act = (tid < QCH) && (q < NRr);
    float qv[32], acc[32];
    float m = -1e30f, ssum = 0.f;
    if (act) {
        const float* qr = qkp + ((size_t)(b*NRr + q))*512 + h*HDIM;
        #pragma unroll
        for (int d = 0; d < 32; d++) { qv[d] = qr[d]; acc[d] = 0.f; }
    }
    const float* mrow = maskf + ((size_t)(b*NRr) + (act ? q : 0))*NRr;
    const float scale = 0.17677669529663687f;

    for (int c0 = 0; c0 < NRr; c0 += 150) {
        __syncthreads();
        for (int i = tid; i < 150*32; i += 128) {
            int k = i >> 5, d = i & 31;
            Ks[i] = qkp[((size_t)(b*NRr + c0 + k))*512 + 256 + h*HDIM + d];
            Vs[i] = vp[((size_t)(b*NRr + c0 + k))*DD_ + h*HDIM + d];
        }
        __syncthreads();
        if (act) {
            for (int k = 0; k < 150; k++) {
                const float* kr = Ks + k*32;
                float x0 = 0.f, x1 = 0.f, x2 = 0.f, x3 = 0.f;
                #pragma unroll
                for (int d = 0; d < 32; d += 4) {
                    x0 += qv[d]*kr[d];   x1 += qv[d+1]*kr[d+1];
                    x2 += qv[d+2]*kr[d+2]; x3 += qv[d+3]*kr[d+3];
                }
                float x = ((x0+x1)+(x2+x3))*scale;
                if (mrow[c0+k] > 0.f) x = -1e9f;
                float nm = fmaxf(m, x);
                float sc = __expf(m - nm);
                float e  = __expf(x - nm);
                ssum = ssum*sc + e;
                const float* vr = Vs + k*32;
                #pragma unroll
                for (int d = 0; d < 32; d++) acc[d] = acc[d]*sc + e*vr[d];
                m = nm;
            }
        }
    }
    if (act) {
        float inv = 1.f/ssum;
        __half* cr = ctx + ((size_t)(b*NRr + q))*DD_ + h*HDIM;
        #pragma unroll
        for (int d = 0; d < 32; d++) cr[d] = __float2half_rn(acc[d]*inv);
    }
}

// ---------------- ln(residual) * mask -> exact (optional) + half ----------------
__global__ void ln_res_mask_kernel(const float* __restrict__ a, const float* __restrict__ bq,
                                   const float* __restrict__ cur,
                                   float* __restrict__ out, __half* __restrict__ out_r) {
    int r = blockIdx.x, t = threadIdx.x;
    float x = a[(size_t)r*DD_ + t] + bq[(size_t)r*DD_ + t];
    float mean = blockReduceSum256(x) * (1.f/256.f);
    float d = x - mean;
    float var = blockReduceSum256(d*d) * (1.f/256.f);
    float y = d * rsqrtf(var + 1e-5f) * cur[r];
    if (out) out[(size_t)r*DD_ + t] = y;
    out_r[(size_t)r*DD_ + t] = __float2half_rn(y);
}

// ---------------- relu(ln(x)) -> + pf1 -> ln (exact + half) ----------------
__global__ void post_dyn_kernel(const float* __restrict__ x, const float* __restrict__ pf1,
                                float* __restrict__ out, __half* __restrict__ out_r) {
    int r = blockIdx.x, t = threadIdx.x;
    float v = x[(size_t)r*DD_ + t];
    float m1 = blockReduceSum256(v) * (1.f/256.f);
    float d1 = v - m1;
    float v1 = blockReduceSum256(d1*d1) * (1.f/256.f);
    float rl = fmaxf(d1 * rsqrtf(v1 + 1e-5f), 0.f);
    float y = pf1[(size_t)r*DD_ + t] + rl;
    float m2 = blockReduceSum256(y) * (1.f/256.f);
    float d2 = y - m2;
    float v2 = blockReduceSum256(d2*d2) * (1.f/256.f);
    float z = d2 * rsqrtf(v2 + 1e-5f);
    out[(size_t)r*DD_ + t] = z;
    out_r[(size_t)r*DD_ + t] = __float2half_rn(z);
}

// ---------------- relu(ln(x)) -> half ----------------
__global__ void ln_relu_kernel(const float* __restrict__ x, __half* __restrict__ out) {
    int r = blockIdx.x, t = threadIdx.x;
    float v = x[(size_t)r*DD_ + t];
    float m = blockReduceSum256(v) * (1.f/256.f);
    float d = v - m;
    float var = blockReduceSum256(d*d) * (1.f/256.f);
    out[(size_t)r*DD_ + t] = __float2half_rn(fmaxf(d * rsqrtf(var + 1e-5f), 0.f));
}

// ---------------- DynamicConv (register-tiled; params fp16 in, f2 fp16 out) ----------------
#define SPAD 52
#define DYN_SMEM 210944

__global__ __launch_bounds__(256)
void dynconv_kernel(const float* __restrict__ roi, const __half* __restrict__ params,
                    __half* __restrict__ out) {
    int n = blockIdx.x;
    extern __shared__ float sm[];
    float* featsT = sm;                 // [d][s] 256 x 52
    float* p1     = sm + 13312;         // [d][e] 256 x 64
    float* p2     = p1 + 16384;         // [e][d] 64 x 256
    float* f1     = p2 + 16384;         // [s][e] 52 x 64
    float* f1T    = f1 + 3328;          // [e][s] 64 x 52
    int tid = threadIdx.x;

    for (int i = tid; i < 256*3; i += 256) {
        int d = i / 3, s = 49 + (i % 3);
        featsT[d*SPAD + s] = 0.f;
    }
    for (int i = tid; i < SS*DD_; i += 256) {
        int s = i >> 8, d = i & 255;
        featsT[d*SPAD + s] = roi[((size_t)s*ROWS + n)*DD_ + d];
    }
    const __half2* pr2 = (const __half2*)(params + (size_t)n * 32768);
    for (int i = tid; i < 8192; i += 256) {
        float2 f = __half22float2(pr2[i]);
        p1[2*i] = f.x; p1[2*i+1] = f.y;
    }
    for (int i = tid; i < 8192; i += 256) {
        float2 f = __half22float2(pr2[8192 + i]);
        p2[2*i] = f.x; p2[2*i+1] = f.y;
    }
    __syncthreads();

    {
        int te = tid & 15, tsg = tid >> 4;
        if (tsg < 13) {
            int e0 = te * 4, s0 = tsg * 4;
            float acc[4][4];
            #pragma unroll
            for (int i = 0; i < 4; i++)
                #pragma unroll
                for (int j = 0; j < 4; j++) acc[i][j] = 0.f;
            for (int d = 0; d < 256; d++) {
                float4 fv = *(const float4*)(featsT + d*SPAD + s0);
                float4 pv = *(const float4*)(p1 + d*64 + e0);
                acc[0][0] += fv.x*pv.x; acc[0][1] += fv.x*pv.y; acc[0][2] += fv.x*pv.z; acc[0][3] += fv.x*pv.w;
                acc[1][0] += fv.y*pv.x; acc[1][1] += fv.y*pv.y; acc[1][2] += fv.y*pv.z; acc[1][3] += fv.y*pv.w;
                acc[2][0] += fv.z*pv.x; acc[2][1] += fv.z*pv.y; acc[2][2] += fv.z*pv.z; acc[2][3] += fv.z*pv.w;
                acc[3][0] += fv.w*pv.x; acc[3][1] += fv.w*pv.y; acc[3][2] += fv.w*pv.z; acc[3][3] += fv.w*pv.w;
            }
            #pragma unroll
            for (int i = 0; i < 4; i++)
                #pragma unroll
                for (int j = 0; j < 4; j++)
                    f1[(s0+i)*64 + e0 + j] = acc[i][j];
        }
    }
    __syncthreads();

    int warp = tid >> 5, lane = tid & 31;
    for (int s = warp; s < SS; s += 8) {
        float x0 = f1[s*64 + lane], x1 = f1[s*64 + 32 + lane];
        float sum = x0 + x1;
        #pragma unroll
        for (int o = 16; o; o >>= 1) sum += __shfl_xor_sync(0xffffffffu, sum, o);
        float m = sum * (1.f/64.f);
        float d0 = x0 - m, d1 = x1 - m;
        float vs = d0*d0 + d1*d1;
        #pragma unroll
        for (int o = 16; o; o >>= 1) vs += __shfl_xor_sync(0xffffffffu, vs, o);
        float inv = rsqrtf(vs*(1.f/64.f) + 1e-5f);
        f1T[lane*SPAD + s]        = fmaxf(d0*inv, 0.f);
        f1T[(32+lane)*SPAD + s]   = fmaxf(d1*inv, 0.f);
    }
    __syncthreads();

    float* f2 = featsT;
    {
        int td = tid & 63, tsg2 = tid >> 6;
        int d0 = td * 4;
        for (int sg = tsg2; sg < 13; sg += 4) {
            int s0 = sg * 4;
            float acc[4][4];
            #pragma unroll
            for (int i = 0; i < 4; i++)
                #pragma unroll
                for (int j = 0; j < 4; j++) acc[i][j] = 0.f;
            for (int e = 0; e < 64; e++) {
                float4 fv = *(const float4*)(f1T + e*SPAD + s0);
                float4 pv = *(const float4*)(p2 + e*256 + d0);
                acc[0][0] += fv.x*pv.x; acc[0][1] += fv.x*pv.y; acc[0][2] += fv.x*pv.z; acc[0][3] += fv.x*pv.w;
                acc[1][0] += fv.y*pv.x; acc[1][1] += fv.y*pv.y; acc[1][2] += fv.y*pv.z; acc[1][3] += fv.y*pv.w;
                acc[2][0] += fv.z*pv.x; acc[2][1] += fv.z*pv.y; acc[2][2] += fv.z*pv.z; acc[2][3] += fv.z*pv.w;
                acc[3][0] += fv.w*pv.x; acc[3][1] += fv.w*pv.y; acc[3][2] += fv.w*pv.z; acc[3][3] += fv.w*pv.w;
            }
            #pragma unroll
            for (int i = 0; i < 4; i++)
                #pragma unroll
                for (int j = 0; j < 4; j++)
                    f2[(s0+i)*256 + d0 + j] = acc[i][j];
        }
    }
    __syncthreads();

    for (int s = warp; s < SS; s += 8) {
        float x[8]; float sum = 0.f;
        #pragma unroll
        for (int j = 0; j < 8; j++) { x[j] = f2[s*256 + j*32 + lane]; sum += x[j]; }
        #pragma unroll
        for (int o = 16; o; o >>= 1) sum += __shfl_xor_sync(0xffffffffu, sum, o);
        float m = sum * (1.f/256.f);
        float vs = 0.f;
        #pragma unroll
        for (int j = 0; j < 8; j++) { float dd = x[j]-m; vs += dd*dd; }
        #pragma unroll
        for (int o = 16; o; o >>= 1) vs += __shfl_xor_sync(0xffffffffu, vs, o);
        float inv = rsqrtf(vs*(1.f/256.f) + 1e-5f);
        #pragma unroll
        for (int j = 0; j < 8; j++)
            out[(size_t)n*12544 + s*256 + j*32 + lane] =
                __float2half_rn(fmaxf((x[j]-m)*inv, 0.f));
    }
}

// ---------------- host ----------------
extern "C" void kernel_launch(void* const* d_in, const int* in_sizes, int n_in,
                              void* d_out, int out_size) {
    const float* bboxes     = (const float*)d_in[0];
    const float* pf         = (const float*)d_in[1];
    const float* roi        = (const float*)d_in[2];
    const float* query      = (const float*)d_in[3];
    const float* cur        = (const float*)d_in[4];
    const float* w_qkv      = (const float*)d_in[5];
    const float* b_qkv      = (const float*)d_in[6];
    const float* w_attn_out = (const float*)d_in[7];
    const float* b_attn_out = (const float*)d_in[8];
    const float* w_dyn      = (const float*)d_in[9];
    const float* b_dyn      = (const float*)d_in[10];
    const float* w_dyn_out  = (const float*)d_in[11];
    const float* b_dyn_out  = (const float*)d_in[12];
    const float* w_ff1      = (const float*)d_in[13];
    const float* b_ff1      = (const float*)d_in[14];
    const float* w_ff2      = (const float*)d_in[15];
    const float* b_ff2      = (const float*)d_in[16];
    const float* w_cls      = (const float*)d_in[17];
    const float* w_logits   = (const float*)d_in[18];
    const float* b_logits   = (const float*)d_in[19];
    float* out = (float*)d_out;

    __half *qk,*pfr,*ctx,*pf1r,*params,*f2,*pf3r,*ffn,*fc,*clsf;
    __half *wqkv,*wattn,*wdyn,*wdynout,*wff1,*wff2,*wcls,*wlog;
    float *qkp,*vp,*maskb,*tgt2,*pf1,*x,*pf3,*t2,*clsy,*part;
    cudaGetSymbolAddress((void**)&qk,     g_qk);
    cudaGetSymbolAddress((void**)&pfr,    g_pfr);
    cudaGetSymbolAddress((void**)&qkp,    g_qkp);
    cudaGetSymbolAddress((void**)&vp,     g_vp);
    cudaGetSymbolAddress((void**)&maskb,  g_mask);
    cudaGetSymbolAddress((void**)&ctx,    g_ctx);
    cudaGetSymbolAddress((void**)&tgt2,   g_tgt2);
    cudaGetSymbolAddress((void**)&pf1,    g_pf1);
    cudaGetSymbolAddress((void**)&pf1r,   g_pf1r);
    cudaGetSymbolAddress((void**)&params, g_params);
    cudaGetSymbolAddress((void**)&f2,     g_f2);
    cudaGetSymbolAddress((void**)&x,      g_x);
    cudaGetSymbolAddress((void**)&pf3,    g_pf3);
    cudaGetSymbolAddress((void**)&pf3r,   g_pf3r);
    cudaGetSymbolAddress((void**)&ffn,    g_ffn);
    cudaGetSymbolAddress((void**)&t2,     g_t2);
    cudaGetSymbolAddress((void**)&fc,     g_fc);
    cudaGetSymbolAddress((void**)&clsy,   g_clsy);
    cudaGetSymbolAddress((void**)&clsf,   g_clsf);
    cudaGetSymbolAddress((void**)&part,   g_part);
    cudaGetSymbolAddress((void**)&wqkv,   g_wqkv_h);
    cudaGetSymbolAddress((void**)&wattn,  g_wattn_h);
    cudaGetSymbolAddress((void**)&wdyn,   g_wdyn_h);
    cudaGetSymbolAddress((void**)&wdynout,g_wdynout_h);
    cudaGetSymbolAddress((void**)&wff1,   g_wff1_h);
    cudaGetSymbolAddress((void**)&wff2,   g_wff2_h);
    cudaGetSymbolAddress((void**)&wcls,   g_wcls_h);
    cudaGetSymbolAddress((void**)&wlog,   g_wlog_h);

    const int GEMM_SMEM = 2 * NSTG * GT_H * 2;   // 110592 B (3 stages)
    cudaFuncSetAttribute(fp16_gemm, cudaFuncAttributeMaxDynamicSharedMemorySize, GEMM_SMEM);
    cudaFuncSetAttribute(dynconv_kernel, cudaFuncAttributeMaxDynamicSharedMemorySize, DYN_SMEM);

    auto grd = [](int M, int N) { return dim3((unsigned)((N+127)/128), (unsigned)((M+127)/128), 1); };

    // prep: mask, half activations, half weights
    mask_kernel<<<dim3(NRr, NB), 320>>>(bboxes, cur, maskb);
    add_round_kernel<<<(ROWS*DD_+255)/256, 256>>>(pf, query, qk, pfr, ROWS*DD_);
    round_weights<<<1280, 256>>>((const float4*)w_dyn,     wdyn,
                                 (const float4*)w_dyn_out, wdynout,
                                 (const float4*)w_ff1,     wff1,
                                 (const float4*)w_ff2,     wff2,
                                 (const float4*)w_qkv,     wqkv,
                                 (const float4*)w_attn_out,wattn,
                                 (const float4*)w_cls,     wcls,
                                 (const float4*)w_logits,  wlog);

    // merged q|k projection (N=512) + v
    fp16_gemm<<<grd(ROWS,512), 256, GEMM_SMEM>>>(qk,  wqkv,           b_qkv,     qkp, nullptr, nullptr, ROWS, 512, 256, 0);
    fp16_gemm<<<grd(ROWS,256), 256, GEMM_SMEM>>>(pfr, wqkv + 512*256, b_qkv+512, vp,  nullptr, nullptr, ROWS, 256, 256, 0);
    // masked MHSA (ctx -> half)
    attn_kernel<<<NB*HH*3, 128>>>(qkp, vp, maskb, ctx);
    // out proj + norm1*mask
    fp16_gemm<<<grd(ROWS,256), 256, GEMM_SMEM>>>(ctx, wattn, b_attn_out, tgt2, nullptr, nullptr, ROWS, 256, 256, 0);
    ln_res_mask_kernel<<<ROWS, 256>>>(pf, tgt2, cur, pf1, pf1r);
    // DynamicConv params GEMM (dominant) -> fp16 params
    fp16_gemm<<<grd(ROWS,32768), 256, GEMM_SMEM>>>(pf1r, wdyn, b_dyn, nullptr, params, nullptr, ROWS, 32768, 256, 2);
    // per-instance dynamic conv -> fp16 f2
    dynconv_kernel<<<ROWS, 256, DYN_SMEM>>>(roi, params, f2);
    // dyn out proj — split-K(4) + reduce; norm2
    fp16_gemm<<<dim3(2,19,4), 256, GEMM_SMEM>>>(f2, wdynout, nullptr, nullptr, nullptr, part, ROWS, 256, 12544, 0);
    reduce_splitk<<<ROWS, 256>>>(part, b_dyn_out, x, 4);
    post_dyn_kernel<<<ROWS, 256>>>(x, pf1, pf3, pf3r);
    // FFN: ff1 relu -> fp16 ffn; ff2 split-K(8); norm3
    fp16_gemm<<<grd(ROWS,2048), 256, GEMM_SMEM>>>(pf3r, wff1, b_ff1, nullptr, ffn, nullptr, ROWS, 2048, 256, 3);
    fp16_gemm<<<dim3(2,19,8), 256, GEMM_SMEM>>>(ffn, wff2, nullptr, nullptr, nullptr, part, ROWS, 256, 2048, 0);
    reduce_splitk<<<ROWS, 256>>>(part, b_ff2, t2, 8);
    ln_res_mask_kernel<<<ROWS, 256>>>(pf3, t2, cur, nullptr, fc);
    // cls tower + logits
    fp16_gemm<<<grd(ROWS,256), 256, GEMM_SMEM>>>(fc, wcls, nullptr, clsy, nullptr, nullptr, ROWS, 256, 256, 0);
    ln_relu_kernel<<<ROWS, 256>>>(clsy, clsf);
    fp16_gemm<<<grd(ROWS,80), 256, GEMM_SMEM>>>(clsf, wlog, b_logits, out, nullptr, nullptr, ROWS, 80, 256, 0);
}